// round 1
// baseline (speedup 1.0000x reference)
#include <cuda_runtime.h>
#include <math.h>

#define B_   2
#define S_   4096
#define D_   1024
#define H_   16
#define HD_  64
#define HD2_ 32
#define M_   512
#define L_   1024
#define HID_ 2816
#define NC_  8
#define EPS_ 1e-5f

// ---------------- scratch (no cudaMalloc allowed) ----------------
static __device__ float g_om  [B_*M_*D_];
static __device__ float g_om2 [B_*M_*D_];
static __device__ float g_tmp [B_*M_*D_];
static __device__ float g_h1  [B_*M_*HID_];
static __device__ float g_h3  [B_*M_*HID_];
static __device__ float g_q   [B_*L_*D_];
static __device__ float g_k   [B_*L_*D_];
static __device__ float g_v   [B_*L_*D_];
static __device__ float g_att [B_*L_*D_];
static __device__ float g_xo  [B_*S_*D_];
static __device__ float g_sc  [(size_t)B_*H_*L_*L_];   // 128 MB score buffer

// ---------------- generic batched NN GEMM: C = A@B (+C if acc) ----------------
// Tile 64(M) x 128(N) x 16(K), 256 threads, 4x8 micro-tile.
// Requires: rows%64==0 (grid.y), N%128==0 (grid.x), K%16==0. All true here.
__global__ void gemm_nn(const float* __restrict__ A, const float* __restrict__ B,
                        float* __restrict__ C, int K,
                        int lda, int ldb, int ldc,
                        long long sA, long long sB, long long sC, int acc)
{
    __shared__ float As[16][64];
    __shared__ float Bs[16][128];
    A += (long long)blockIdx.z * sA;
    B += (long long)blockIdx.z * sB;
    C += (long long)blockIdx.z * sC;
    const int m0 = blockIdx.y * 64;
    const int n0 = blockIdx.x * 128;
    const int t  = threadIdx.x;
    const int tx = t & 15, ty = t >> 4;
    const int am = t >> 2, ak = (t & 3) << 2;   // A tile load: 64 rows x 16 k
    const int bk = t >> 4, bn = (t & 15) << 3;  // B tile load: 16 k x 128 n

    float acc_r[4][8];
    #pragma unroll
    for (int i = 0; i < 4; i++)
        #pragma unroll
        for (int j = 0; j < 8; j++) acc_r[i][j] = 0.f;

    const float* Ap = A + (long long)(m0 + am) * lda + ak;
    const float* Bp = B + (long long)bk * ldb + n0 + bn;

    for (int k0 = 0; k0 < K; k0 += 16) {
        float4 a4 = *(const float4*)(Ap + k0);
        As[ak+0][am] = a4.x; As[ak+1][am] = a4.y;
        As[ak+2][am] = a4.z; As[ak+3][am] = a4.w;
        float4 b0 = *(const float4*)(Bp + (long long)k0 * ldb);
        float4 b1 = *(const float4*)(Bp + (long long)k0 * ldb + 4);
        *(float4*)&Bs[bk][bn]     = b0;
        *(float4*)&Bs[bk][bn + 4] = b1;
        __syncthreads();
        #pragma unroll
        for (int kk = 0; kk < 16; kk++) {
            float a[4], b[8];
            #pragma unroll
            for (int i = 0; i < 4; i++) a[i] = As[kk][ty*4 + i];
            #pragma unroll
            for (int j = 0; j < 8; j++) b[j] = Bs[kk][tx*8 + j];
            #pragma unroll
            for (int i = 0; i < 4; i++)
                #pragma unroll
                for (int j = 0; j < 8; j++)
                    acc_r[i][j] = fmaf(a[i], b[j], acc_r[i][j]);
        }
        __syncthreads();
    }
    #pragma unroll
    for (int i = 0; i < 4; i++) {
        float* Cp = C + (long long)(m0 + ty*4 + i) * ldc + n0 + tx*8;
        #pragma unroll
        for (int j = 0; j < 8; j++)
            Cp[j] = acc ? (Cp[j] + acc_r[i][j]) : acc_r[i][j];
    }
}

// ---------------- RMSNorm over last dim D_ ----------------
__global__ void rmsnorm_k(const float* __restrict__ X, const float* __restrict__ W,
                          float* __restrict__ Y)
{
    const long long row = blockIdx.x;
    const float* x = X + row * D_;
    float* y = Y + row * D_;
    float ss = 0.f;
    for (int i = threadIdx.x; i < D_; i += 256) { float v = x[i]; ss += v * v; }
    __shared__ float red[8];
    for (int o = 16; o; o >>= 1) ss += __shfl_xor_sync(~0u, ss, o);
    if ((threadIdx.x & 31) == 0) red[threadIdx.x >> 5] = ss;
    __syncthreads();
    float tot = 0.f;
    #pragma unroll
    for (int i = 0; i < 8; i++) tot += red[i];
    const float inv = rsqrtf(tot * (1.f / D_) + EPS_);
    for (int i = threadIdx.x; i < D_; i += 256) y[i] = x[i] * inv * W[i];
}

// ---------------- elementwise ----------------
__global__ void init_om_k(float* __restrict__ om, const float* __restrict__ om0)
{
    int i = blockIdx.x * 256 + threadIdx.x;
    if (i < B_*M_*D_) om[i] = om0[i % (M_*D_)];
}

__global__ void silu_mul_k(float* __restrict__ a, const float* __restrict__ b)
{
    int i = blockIdx.x * 256 + threadIdx.x;
    if (i < B_*M_*HID_) {
        float v = a[i];
        a[i] = (v / (1.f + expf(-v))) * b[i];
    }
}

__global__ void copy_mq_k(float* __restrict__ q, const float* __restrict__ k)
{
    int i = blockIdx.x * 256 + threadIdx.x;
    if (i < B_*M_*D_) {
        int b = i / (M_*D_), r = i % (M_*D_);
        q[(long long)b * L_ * D_ + r] = k[(long long)b * L_ * D_ + r];
    }
}

__global__ void rope_k(float* __restrict__ t, const float* __restrict__ cf,
                       const float* __restrict__ sf)
{
    int i = blockIdx.x * 256 + threadIdx.x;
    if (i >= B_*L_*H_*HD2_) return;
    int d2 = i & 31;
    int h  = (i >> 5) & 15;
    int l  = (i >> 9) & (L_ - 1);
    int b  = i >> 19;
    long long base = (long long)(b * L_ + l) * D_ + h * HD_ + 2 * d2;
    float c = cf[l * HD2_ + d2], s = sf[l * HD2_ + d2];
    float tr = t[base], ti = t[base + 1];
    t[base]     = tr * c - ti * s;
    t[base + 1] = tr * s + ti * c;
}

__global__ void extract_k(const float* __restrict__ att, float* __restrict__ om,
                          float* __restrict__ xo, int c)
{
    int i = blockIdx.x * 256 + threadIdx.x;
    if (i < B_*M_*D_) {
        int b = i / (M_*D_), r = i % (M_*D_);
        float v = att[(long long)b * L_ * D_ + (long long)M_ * D_ + r];
        om[i] = v;
        xo[(long long)b * S_ * D_ + (long long)c * M_ * D_ + r] = v;
    }
}

// ---------------- attention: S = Q K^T (NT, per-head) ----------------
// 64x64 tile, K=HD_=64. Skips fully-masked blocks (softmax zeros them).
__global__ void attn_scores_k(const float* __restrict__ Q, const float* __restrict__ K,
                              float* __restrict__ Ssc)
{
    const int z = blockIdx.z;
    const int b = z >> 4, h = z & 15;
    const int i0 = blockIdx.y * 64;
    const int j0 = blockIdx.x * 64;
    if (j0 > i0 + 63) return;
    const float* q  = Q + (long long)b * L_ * D_ + h * HD_;
    const float* kp = K + (long long)b * L_ * D_ + h * HD_;
    float* sc = Ssc + (long long)z * L_ * L_;
    __shared__ float Qs[16][64];
    __shared__ float Ks[16][64];
    const int t = threadIdx.x;
    const int tx = t & 15, ty = t >> 4;
    const int am = t >> 2, ak = (t & 3) << 2;
    float acc[4][4] = {};
    for (int k0 = 0; k0 < HD_; k0 += 16) {
        float4 qa = *(const float4*)(q  + (long long)(i0 + am) * D_ + k0 + ak);
        Qs[ak+0][am] = qa.x; Qs[ak+1][am] = qa.y; Qs[ak+2][am] = qa.z; Qs[ak+3][am] = qa.w;
        float4 ka = *(const float4*)(kp + (long long)(j0 + am) * D_ + k0 + ak);
        Ks[ak+0][am] = ka.x; Ks[ak+1][am] = ka.y; Ks[ak+2][am] = ka.z; Ks[ak+3][am] = ka.w;
        __syncthreads();
        #pragma unroll
        for (int kk = 0; kk < 16; kk++) {
            float a[4], c[4];
            #pragma unroll
            for (int i = 0; i < 4; i++) a[i] = Qs[kk][ty*4 + i];
            #pragma unroll
            for (int j = 0; j < 4; j++) c[j] = Ks[kk][tx*4 + j];
            #pragma unroll
            for (int i = 0; i < 4; i++)
                #pragma unroll
                for (int j = 0; j < 4; j++)
                    acc[i][j] = fmaf(a[i], c[j], acc[i][j]);
        }
        __syncthreads();
    }
    #pragma unroll
    for (int i = 0; i < 4; i++)
        #pragma unroll
        for (int j = 0; j < 4; j++)
            sc[(long long)(i0 + ty*4 + i) * L_ + j0 + tx*4 + j] = acc[i][j];
}

// ---------------- causal softmax (scale 1/sqrt(HD)=0.125), zeros masked ----------------
__global__ void softmax_causal_k(float* __restrict__ Ssc)
{
    const long long rowg = blockIdx.x;
    const int i = (int)(rowg & (L_ - 1));
    const long long z = rowg >> 10;
    float* s = Ssc + z * (long long)L_ * L_ + (long long)i * L_;
    const int n = i + 1;
    const float scale = 0.125f;
    __shared__ float red[4];
    float m = -3.4e38f;
    for (int j = threadIdx.x; j < n; j += 128) m = fmaxf(m, s[j]);
    for (int o = 16; o; o >>= 1) m = fmaxf(m, __shfl_xor_sync(~0u, m, o));
    if ((threadIdx.x & 31) == 0) red[threadIdx.x >> 5] = m;
    __syncthreads();
    m = fmaxf(fmaxf(red[0], red[1]), fmaxf(red[2], red[3]));
    const float ms = m * scale;
    float sum = 0.f;
    for (int j = threadIdx.x; j < n; j += 128) {
        float e = expf(s[j] * scale - ms);
        s[j] = e;
        sum += e;
    }
    for (int o = 16; o; o >>= 1) sum += __shfl_xor_sync(~0u, sum, o);
    __syncthreads();
    if ((threadIdx.x & 31) == 0) red[threadIdx.x >> 5] = sum;
    __syncthreads();
    sum = red[0] + red[1] + red[2] + red[3];
    const float inv = 1.f / sum;
    for (int j = threadIdx.x; j < n; j += 128) s[j] *= inv;
    for (int j = n + threadIdx.x; j < L_; j += 128) s[j] = 0.f;
}

// ---------------- attention: O = P @ V (per-head), K-loop truncated at diagonal ----------------
__global__ void attn_pv_k(const float* __restrict__ P, const float* __restrict__ V,
                          float* __restrict__ O)
{
    const int z = blockIdx.z;
    const int b = z >> 4, h = z & 15;
    const int i0 = blockIdx.x * 64;
    const float* p = P + (long long)z * L_ * L_;
    const float* v = V + (long long)b * L_ * D_ + h * HD_;
    float* o = O + (long long)b * L_ * D_ + h * HD_;
    __shared__ float Ps[16][64];
    __shared__ float Vs[16][64];
    const int t = threadIdx.x;
    const int tx = t & 15, ty = t >> 4;
    const int pm = t >> 2, pk = (t & 3) << 2;
    const int vk = t >> 4, vd = (t & 15) << 2;
    float acc[4][4] = {};
    const int kend = i0 + 64;   // columns beyond diagonal block are zero
    for (int j0 = 0; j0 < kend; j0 += 16) {
        float4 pa = *(const float4*)(p + (long long)(i0 + pm) * L_ + j0 + pk);
        Ps[pk+0][pm] = pa.x; Ps[pk+1][pm] = pa.y; Ps[pk+2][pm] = pa.z; Ps[pk+3][pm] = pa.w;
        float4 va = *(const float4*)(v + (long long)(j0 + vk) * D_ + vd);
        *(float4*)&Vs[vk][vd] = va;
        __syncthreads();
        #pragma unroll
        for (int kk = 0; kk < 16; kk++) {
            float a[4], c[4];
            #pragma unroll
            for (int i = 0; i < 4; i++) a[i] = Ps[kk][ty*4 + i];
            #pragma unroll
            for (int j = 0; j < 4; j++) c[j] = Vs[kk][tx*4 + j];
            #pragma unroll
            for (int i = 0; i < 4; i++)
                #pragma unroll
                for (int j = 0; j < 4; j++)
                    acc[i][j] = fmaf(a[i], c[j], acc[i][j]);
        }
        __syncthreads();
    }
    #pragma unroll
    for (int i = 0; i < 4; i++)
        #pragma unroll
        for (int j = 0; j < 4; j++)
            o[(long long)(i0 + ty*4 + i) * D_ + tx*4 + j] = acc[i][j];
}

// ---------------- host orchestration ----------------
extern "C" void kernel_launch(void* const* d_in, const int* in_sizes, int n_in,
                              void* d_out, int out_size)
{
    const float* x     = (const float*)d_in[0];
    const float* fcos  = (const float*)d_in[1];
    const float* fsin  = (const float*)d_in[2];
    const float* wq    = (const float*)d_in[3];
    const float* wk    = (const float*)d_in[4];
    const float* wv    = (const float*)d_in[5];
    const float* wo    = (const float*)d_in[6];
    const float* wm    = (const float*)d_in[7];
    const float* wkm   = (const float*)d_in[8];
    const float* wvm   = (const float*)d_in[9];
    const float* w1    = (const float*)d_in[10];
    const float* w3    = (const float*)d_in[11];
    const float* w2    = (const float*)d_in[12];
    const float* ffn_w = (const float*)d_in[13];
    const float* mem_w = (const float*)d_in[14];
    const float* om0   = (const float*)d_in[15];
    float* out = (float*)d_out;

    float *p_om, *p_om2, *p_tmp, *p_h1, *p_h3, *p_q, *p_k, *p_v, *p_att, *p_xo, *p_sc;
    cudaGetSymbolAddress((void**)&p_om,  g_om);
    cudaGetSymbolAddress((void**)&p_om2, g_om2);
    cudaGetSymbolAddress((void**)&p_tmp, g_tmp);
    cudaGetSymbolAddress((void**)&p_h1,  g_h1);
    cudaGetSymbolAddress((void**)&p_h3,  g_h3);
    cudaGetSymbolAddress((void**)&p_q,   g_q);
    cudaGetSymbolAddress((void**)&p_k,   g_k);
    cudaGetSymbolAddress((void**)&p_v,   g_v);
    cudaGetSymbolAddress((void**)&p_att, g_att);
    cudaGetSymbolAddress((void**)&p_xo,  g_xo);
    cudaGetSymbolAddress((void**)&p_sc,  g_sc);

    const long long MD = (long long)M_ * D_;
    const long long LD = (long long)L_ * D_;
    const long long MH = (long long)M_ * HID_;
    const long long SD = (long long)S_ * D_;

    init_om_k<<<(B_*M_*D_ + 255) / 256, 256>>>(p_om, om0);

    for (int c = 0; c < NC_; c++) {
        // om2 = om @ wm
        gemm_nn<<<dim3(D_/128, M_/64, B_), 256>>>(p_om, wm, p_om2, D_, D_, D_, D_, MD, 0, MD, 0);
        // tmp = rmsnorm(om2, ffn_norm_w)
        rmsnorm_k<<<B_*M_, 256>>>(p_om2, ffn_w, p_tmp);
        // h1 = tmp@w1, h3 = tmp@w3; h1 = silu(h1)*h3
        gemm_nn<<<dim3(HID_/128, M_/64, B_), 256>>>(p_tmp, w1, p_h1, D_, D_, HID_, HID_, MD, 0, MH, 0);
        gemm_nn<<<dim3(HID_/128, M_/64, B_), 256>>>(p_tmp, w3, p_h3, D_, D_, HID_, HID_, MD, 0, MH, 0);
        silu_mul_k<<<(B_*M_*HID_ + 255) / 256, 256>>>(p_h1, p_h3);
        // om2 += h1 @ w2
        gemm_nn<<<dim3(D_/128, M_/64, B_), 256>>>(p_h1, w2, p_om2, HID_, HID_, D_, D_, MH, 0, MD, 1);
        // tmp = rmsnorm(om2, mem_norm_w)
        rmsnorm_k<<<B_*M_, 256>>>(p_om2, mem_w, p_tmp);
        // mk -> k[:, :M], mv -> v[:, :M]
        gemm_nn<<<dim3(D_/128, M_/64, B_), 256>>>(p_tmp, wkm, p_k, D_, D_, D_, D_, MD, 0, LD, 0);
        gemm_nn<<<dim3(D_/128, M_/64, B_), 256>>>(p_tmp, wvm, p_v, D_, D_, D_, D_, MD, 0, LD, 0);
        // xq/xk/xv -> second halves
        const float* xs = x + (long long)c * M_ * D_;
        gemm_nn<<<dim3(D_/128, M_/64, B_), 256>>>(xs, wq, p_q + MD, D_, D_, D_, D_, SD, 0, LD, 0);
        gemm_nn<<<dim3(D_/128, M_/64, B_), 256>>>(xs, wk, p_k + MD, D_, D_, D_, D_, SD, 0, LD, 0);
        gemm_nn<<<dim3(D_/128, M_/64, B_), 256>>>(xs, wv, p_v + MD, D_, D_, D_, D_, SD, 0, LD, 0);
        // mq = mk (pre-rope; rope is position-wise so equivalent)
        copy_mq_k<<<(B_*M_*D_ + 255) / 256, 256>>>(p_q, p_k);
        // rope q, k
        rope_k<<<(B_*L_*H_*HD2_ + 255) / 256, 256>>>(p_q, fcos, fsin);
        rope_k<<<(B_*L_*H_*HD2_ + 255) / 256, 256>>>(p_k, fcos, fsin);
        // attention
        attn_scores_k<<<dim3(L_/64, L_/64, B_*H_), 256>>>(p_q, p_k, p_sc);
        softmax_causal_k<<<B_*H_*L_, 128>>>(p_sc);
        attn_pv_k<<<dim3(L_/64, 1, B_*H_), 256>>>(p_sc, p_v, p_att);
        // om = out[:, M:]; stash into xo[:, c*M:(c+1)*M]
        extract_k<<<(B_*M_*D_ + 255) / 256, 256>>>(p_att, p_om, p_xo, c);
    }
    // final: out = xo @ wo  (8192 x 1024 x 1024)
    gemm_nn<<<dim3(D_/128, (B_*S_)/64, 1), 256>>>(p_xo, wo, out, D_, D_, D_, D_, 0, 0, 0, 0);
}

// round 2
// speedup vs baseline: 1.8464x; 1.8464x over previous
#include <cuda_runtime.h>
#include <math.h>

#define B_   2
#define S_   4096
#define D_   1024
#define H_   16
#define HD_  64
#define HD2_ 32
#define M_   512
#define L_   1024
#define HID_ 2816
#define NC_  8
#define EPS_ 1e-5f

// ---------------- scratch (no cudaMalloc allowed) ----------------
static __device__ float g_om  [B_*M_*D_];
static __device__ float g_om2 [B_*M_*D_];
static __device__ float g_tmp [B_*M_*D_];
static __device__ float g_h1  [B_*M_*HID_];
static __device__ float g_h3  [B_*M_*HID_];
static __device__ float g_q   [B_*L_*D_];
static __device__ float g_k   [B_*L_*D_];
static __device__ float g_v   [B_*L_*D_];
static __device__ float g_att [B_*L_*D_];
static __device__ float g_xo  [B_*S_*D_];
static __device__ float g_sc  [(size_t)B_*H_*L_*L_];   // 128 MB score buffer

// ---------------- generic batched NN GEMM: C = A@B (+C if acc) ----------------
// Tile 64(M) x 128(N) x 16(K), 256 threads, 4x8 micro-tile.
// Double-buffered smem: one bar.sync per K-slab, global loads overlap compute.
__global__ void gemm_nn(const float* __restrict__ A, const float* __restrict__ B,
                        float* __restrict__ C, int K,
                        int lda, int ldb, int ldc,
                        long long sA, long long sB, long long sC, int acc)
{
    __shared__ float As[2][16][64];
    __shared__ float Bs[2][16][128];
    A += (long long)blockIdx.z * sA;
    B += (long long)blockIdx.z * sB;
    C += (long long)blockIdx.z * sC;
    const int m0 = blockIdx.y * 64;
    const int n0 = blockIdx.x * 128;
    const int t  = threadIdx.x;
    const int tx = t & 15, ty = t >> 4;
    const int am = t >> 2, ak = (t & 3) << 2;   // A tile load: 64 rows x 16 k
    const int bk = t >> 4, bn = (t & 15) << 3;  // B tile load: 16 k x 128 n

    float acc_r[4][8];
    #pragma unroll
    for (int i = 0; i < 4; i++)
        #pragma unroll
        for (int j = 0; j < 8; j++) acc_r[i][j] = 0.f;

    const float* Ap = A + (long long)(m0 + am) * lda + ak;
    const float* Bp = B + (long long)bk * ldb + n0 + bn;

    const int nk = K >> 4;

    // prologue: load slab 0 into buffer 0
    {
        float4 a4 = *(const float4*)(Ap);
        As[0][ak+0][am] = a4.x; As[0][ak+1][am] = a4.y;
        As[0][ak+2][am] = a4.z; As[0][ak+3][am] = a4.w;
        float4 b0 = *(const float4*)(Bp);
        float4 b1 = *(const float4*)(Bp + 4);
        *(float4*)&Bs[0][bk][bn]     = b0;
        *(float4*)&Bs[0][bk][bn + 4] = b1;
    }
    __syncthreads();

    for (int kb = 0; kb < nk; kb++) {
        const int cur = kb & 1;
        float4 na, nb0, nb1;
        const bool has_next = (kb + 1 < nk);
        if (has_next) {
            na  = *(const float4*)(Ap + (kb + 1) * 16);
            nb0 = *(const float4*)(Bp + (long long)(kb + 1) * 16 * ldb);
            nb1 = *(const float4*)(Bp + (long long)(kb + 1) * 16 * ldb + 4);
        }
        #pragma unroll
        for (int kk = 0; kk < 16; kk++) {
            float4 av  = *(const float4*)&As[cur][kk][ty * 4];
            float4 bv0 = *(const float4*)&Bs[cur][kk][tx * 8];
            float4 bv1 = *(const float4*)&Bs[cur][kk][tx * 8 + 4];
            float a[4] = {av.x, av.y, av.z, av.w};
            float b[8] = {bv0.x, bv0.y, bv0.z, bv0.w, bv1.x, bv1.y, bv1.z, bv1.w};
            #pragma unroll
            for (int i = 0; i < 4; i++)
                #pragma unroll
                for (int j = 0; j < 8; j++)
                    acc_r[i][j] = fmaf(a[i], b[j], acc_r[i][j]);
        }
        if (has_next) {
            const int nxt = cur ^ 1;
            As[nxt][ak+0][am] = na.x; As[nxt][ak+1][am] = na.y;
            As[nxt][ak+2][am] = na.z; As[nxt][ak+3][am] = na.w;
            *(float4*)&Bs[nxt][bk][bn]     = nb0;
            *(float4*)&Bs[nxt][bk][bn + 4] = nb1;
        }
        __syncthreads();
    }

    #pragma unroll
    for (int i = 0; i < 4; i++) {
        float* Cp = C + (long long)(m0 + ty*4 + i) * ldc + n0 + tx*8;
        if (acc) {
            float4 c0 = *(float4*)Cp;
            float4 c1 = *(float4*)(Cp + 4);
            c0.x += acc_r[i][0]; c0.y += acc_r[i][1]; c0.z += acc_r[i][2]; c0.w += acc_r[i][3];
            c1.x += acc_r[i][4]; c1.y += acc_r[i][5]; c1.z += acc_r[i][6]; c1.w += acc_r[i][7];
            *(float4*)Cp       = c0;
            *(float4*)(Cp + 4) = c1;
        } else {
            float4 c0 = {acc_r[i][0], acc_r[i][1], acc_r[i][2], acc_r[i][3]};
            float4 c1 = {acc_r[i][4], acc_r[i][5], acc_r[i][6], acc_r[i][7]};
            *(float4*)Cp       = c0;
            *(float4*)(Cp + 4) = c1;
        }
    }
}

// ---------------- RMSNorm over last dim D_ ----------------
__global__ void rmsnorm_k(const float* __restrict__ X, const float* __restrict__ W,
                          float* __restrict__ Y)
{
    const long long row = blockIdx.x;
    const float* x = X + row * D_;
    float* y = Y + row * D_;
    float ss = 0.f;
    for (int i = threadIdx.x; i < D_; i += 256) { float v = x[i]; ss += v * v; }
    __shared__ float red[8];
    for (int o = 16; o; o >>= 1) ss += __shfl_xor_sync(~0u, ss, o);
    if ((threadIdx.x & 31) == 0) red[threadIdx.x >> 5] = ss;
    __syncthreads();
    float tot = 0.f;
    #pragma unroll
    for (int i = 0; i < 8; i++) tot += red[i];
    const float inv = rsqrtf(tot * (1.f / D_) + EPS_);
    for (int i = threadIdx.x; i < D_; i += 256) y[i] = x[i] * inv * W[i];
}

// ---------------- elementwise ----------------
__global__ void init_om_k(float* __restrict__ om, const float* __restrict__ om0)
{
    int i = blockIdx.x * 256 + threadIdx.x;
    if (i < B_*M_*D_) om[i] = om0[i % (M_*D_)];
}

__global__ void silu_mul_k(float* __restrict__ a, const float* __restrict__ b)
{
    int i = blockIdx.x * 256 + threadIdx.x;
    if (i < B_*M_*HID_) {
        float v = a[i];
        a[i] = (v / (1.f + expf(-v))) * b[i];
    }
}

__global__ void copy_mq_k(float* __restrict__ q, const float* __restrict__ k)
{
    int i = blockIdx.x * 256 + threadIdx.x;
    if (i < B_*M_*D_) {
        int b = i / (M_*D_), r = i % (M_*D_);
        q[(long long)b * L_ * D_ + r] = k[(long long)b * L_ * D_ + r];
    }
}

__global__ void rope_k(float* __restrict__ t, const float* __restrict__ cf,
                       const float* __restrict__ sf)
{
    int i = blockIdx.x * 256 + threadIdx.x;
    if (i >= B_*L_*H_*HD2_) return;
    int d2 = i & 31;
    int h  = (i >> 5) & 15;
    int l  = (i >> 9) & (L_ - 1);
    int b  = i >> 19;
    long long base = (long long)(b * L_ + l) * D_ + h * HD_ + 2 * d2;
    float c = cf[l * HD2_ + d2], s = sf[l * HD2_ + d2];
    float tr = t[base], ti = t[base + 1];
    t[base]     = tr * c - ti * s;
    t[base + 1] = tr * s + ti * c;
}

__global__ void extract_k(const float* __restrict__ att, float* __restrict__ om,
                          float* __restrict__ xo, int c)
{
    int i = blockIdx.x * 256 + threadIdx.x;
    if (i < B_*M_*D_) {
        int b = i / (M_*D_), r = i % (M_*D_);
        float v = att[(long long)b * L_ * D_ + (long long)M_ * D_ + r];
        om[i] = v;
        xo[(long long)b * S_ * D_ + (long long)c * M_ * D_ + r] = v;
    }
}

// ---------------- attention: S = Q K^T (NT, per-head) ----------------
// 64x64 tile, full K=HD_=64 staged in smem once (no mainloop syncs).
__global__ void attn_scores_k(const float* __restrict__ Q, const float* __restrict__ K,
                              float* __restrict__ Ssc)
{
    const int z = blockIdx.z;
    const int b = z >> 4, h = z & 15;
    const int i0 = blockIdx.y * 64;
    const int j0 = blockIdx.x * 64;
    if (j0 > i0 + 63) return;
    const float* q  = Q + (long long)b * L_ * D_ + h * HD_;
    const float* kp = K + (long long)b * L_ * D_ + h * HD_;
    float* sc = Ssc + (long long)z * L_ * L_;
    __shared__ float Qs[64][64];   // [k][row]
    __shared__ float Ks[64][64];   // [k][col]
    const int t = threadIdx.x;
    const int tx = t & 15, ty = t >> 4;
    const int r = t >> 2, c0 = (t & 3) << 4;

    #pragma unroll
    for (int w = 0; w < 4; w++) {
        float4 qa = *(const float4*)(q  + (long long)(i0 + r) * D_ + c0 + 4*w);
        Qs[c0+4*w+0][r] = qa.x; Qs[c0+4*w+1][r] = qa.y;
        Qs[c0+4*w+2][r] = qa.z; Qs[c0+4*w+3][r] = qa.w;
        float4 ka = *(const float4*)(kp + (long long)(j0 + r) * D_ + c0 + 4*w);
        Ks[c0+4*w+0][r] = ka.x; Ks[c0+4*w+1][r] = ka.y;
        Ks[c0+4*w+2][r] = ka.z; Ks[c0+4*w+3][r] = ka.w;
    }
    __syncthreads();

    float acc[4][4] = {};
    #pragma unroll 8
    for (int kk = 0; kk < 64; kk++) {
        float4 av = *(const float4*)&Qs[kk][ty * 4];
        float4 cv = *(const float4*)&Ks[kk][tx * 4];
        float a[4] = {av.x, av.y, av.z, av.w};
        float c[4] = {cv.x, cv.y, cv.z, cv.w};
        #pragma unroll
        for (int i = 0; i < 4; i++)
            #pragma unroll
            for (int j = 0; j < 4; j++)
                acc[i][j] = fmaf(a[i], c[j], acc[i][j]);
    }
    #pragma unroll
    for (int i = 0; i < 4; i++) {
        float4 o = {acc[i][0], acc[i][1], acc[i][2], acc[i][3]};
        *(float4*)&sc[(long long)(i0 + ty*4 + i) * L_ + j0 + tx*4] = o;
    }
}

// ---------------- causal softmax (scale 1/sqrt(HD)=0.125), zeros masked ----------------
__global__ void softmax_causal_k(float* __restrict__ Ssc)
{
    const long long rowg = blockIdx.x;
    const int i = (int)(rowg & (L_ - 1));
    const long long z = rowg >> 10;
    float* s = Ssc + z * (long long)L_ * L_ + (long long)i * L_;
    const int n = i + 1;
    const float scale = 0.125f;
    __shared__ float red[4];
    float m = -3.4e38f;
    for (int j = threadIdx.x; j < n; j += 128) m = fmaxf(m, s[j]);
    for (int o = 16; o; o >>= 1) m = fmaxf(m, __shfl_xor_sync(~0u, m, o));
    if ((threadIdx.x & 31) == 0) red[threadIdx.x >> 5] = m;
    __syncthreads();
    m = fmaxf(fmaxf(red[0], red[1]), fmaxf(red[2], red[3]));
    const float ms = m * scale;
    float sum = 0.f;
    for (int j = threadIdx.x; j < n; j += 128) {
        float e = expf(s[j] * scale - ms);
        s[j] = e;
        sum += e;
    }
    for (int o = 16; o; o >>= 1) sum += __shfl_xor_sync(~0u, sum, o);
    __syncthreads();
    if ((threadIdx.x & 31) == 0) red[threadIdx.x >> 5] = sum;
    __syncthreads();
    sum = red[0] + red[1] + red[2] + red[3];
    const float inv = 1.f / sum;
    for (int j = threadIdx.x; j < n; j += 128) s[j] *= inv;
    for (int j = n + threadIdx.x; j < L_; j += 128) s[j] = 0.f;
}

// ---------------- attention: O = P @ V (per-head), K-loop truncated at diagonal ----------------
// Double-buffered smem, vectorized fragments.
__global__ void attn_pv_k(const float* __restrict__ P, const float* __restrict__ V,
                          float* __restrict__ O)
{
    const int z = blockIdx.z;
    const int b = z >> 4, h = z & 15;
    const int i0 = blockIdx.x * 64;
    const float* p = P + (long long)z * L_ * L_;
    const float* v = V + (long long)b * L_ * D_ + h * HD_;
    float* o = O + (long long)b * L_ * D_ + h * HD_;
    __shared__ float Ps[2][16][64];
    __shared__ float Vs[2][16][64];
    const int t = threadIdx.x;
    const int tx = t & 15, ty = t >> 4;
    const int pm = t >> 2, pk = (t & 3) << 2;
    const int vk = t >> 4, vd = (t & 15) << 2;
    float acc[4][4] = {};
    const int nk = (i0 + 64) >> 4;   // columns beyond diagonal block are zero

    {
        float4 pa = *(const float4*)(p + (long long)(i0 + pm) * L_ + pk);
        Ps[0][pk+0][pm] = pa.x; Ps[0][pk+1][pm] = pa.y;
        Ps[0][pk+2][pm] = pa.z; Ps[0][pk+3][pm] = pa.w;
        float4 va = *(const float4*)(v + (long long)vk * D_ + vd);
        *(float4*)&Vs[0][vk][vd] = va;
    }
    __syncthreads();

    for (int kb = 0; kb < nk; kb++) {
        const int cur = kb & 1;
        float4 npa, nva;
        const bool has_next = (kb + 1 < nk);
        if (has_next) {
            npa = *(const float4*)(p + (long long)(i0 + pm) * L_ + (kb+1)*16 + pk);
            nva = *(const float4*)(v + (long long)((kb+1)*16 + vk) * D_ + vd);
        }
        #pragma unroll
        for (int kk = 0; kk < 16; kk++) {
            float4 av = *(const float4*)&Ps[cur][kk][ty * 4];
            float4 cv = *(const float4*)&Vs[cur][kk][tx * 4];
            float a[4] = {av.x, av.y, av.z, av.w};
            float c[4] = {cv.x, cv.y, cv.z, cv.w};
            #pragma unroll
            for (int i = 0; i < 4; i++)
                #pragma unroll
                for (int j = 0; j < 4; j++)
                    acc[i][j] = fmaf(a[i], c[j], acc[i][j]);
        }
        if (has_next) {
            const int nxt = cur ^ 1;
            Ps[nxt][pk+0][pm] = npa.x; Ps[nxt][pk+1][pm] = npa.y;
            Ps[nxt][pk+2][pm] = npa.z; Ps[nxt][pk+3][pm] = npa.w;
            *(float4*)&Vs[nxt][vk][vd] = nva;
        }
        __syncthreads();
    }
    #pragma unroll
    for (int i = 0; i < 4; i++) {
        float4 ov = {acc[i][0], acc[i][1], acc[i][2], acc[i][3]};
        *(float4*)&o[(long long)(i0 + ty*4 + i) * D_ + tx*4] = ov;
    }
}

// ---------------- host orchestration ----------------
extern "C" void kernel_launch(void* const* d_in, const int* in_sizes, int n_in,
                              void* d_out, int out_size)
{
    const float* x     = (const float*)d_in[0];
    const float* fcos  = (const float*)d_in[1];
    const float* fsin  = (const float*)d_in[2];
    const float* wq    = (const float*)d_in[3];
    const float* wk    = (const float*)d_in[4];
    const float* wv    = (const float*)d_in[5];
    const float* wo    = (const float*)d_in[6];
    const float* wm    = (const float*)d_in[7];
    const float* wkm   = (const float*)d_in[8];
    const float* wvm   = (const float*)d_in[9];
    const float* w1    = (const float*)d_in[10];
    const float* w3    = (const float*)d_in[11];
    const float* w2    = (const float*)d_in[12];
    const float* ffn_w = (const float*)d_in[13];
    const float* mem_w = (const float*)d_in[14];
    const float* om0   = (const float*)d_in[15];
    float* out = (float*)d_out;

    float *p_om, *p_om2, *p_tmp, *p_h1, *p_h3, *p_q, *p_k, *p_v, *p_att, *p_xo, *p_sc;
    cudaGetSymbolAddress((void**)&p_om,  g_om);
    cudaGetSymbolAddress((void**)&p_om2, g_om2);
    cudaGetSymbolAddress((void**)&p_tmp, g_tmp);
    cudaGetSymbolAddress((void**)&p_h1,  g_h1);
    cudaGetSymbolAddress((void**)&p_h3,  g_h3);
    cudaGetSymbolAddress((void**)&p_q,   g_q);
    cudaGetSymbolAddress((void**)&p_k,   g_k);
    cudaGetSymbolAddress((void**)&p_v,   g_v);
    cudaGetSymbolAddress((void**)&p_att, g_att);
    cudaGetSymbolAddress((void**)&p_xo,  g_xo);
    cudaGetSymbolAddress((void**)&p_sc,  g_sc);

    const long long MD = (long long)M_ * D_;
    const long long LD = (long long)L_ * D_;
    const long long MH = (long long)M_ * HID_;
    const long long SD = (long long)S_ * D_;

    init_om_k<<<(B_*M_*D_ + 255) / 256, 256>>>(p_om, om0);

    for (int c = 0; c < NC_; c++) {
        // om2 = om @ wm
        gemm_nn<<<dim3(D_/128, M_/64, B_), 256>>>(p_om, wm, p_om2, D_, D_, D_, D_, MD, 0, MD, 0);
        // tmp = rmsnorm(om2, ffn_norm_w)
        rmsnorm_k<<<B_*M_, 256>>>(p_om2, ffn_w, p_tmp);
        // h1 = tmp@w1, h3 = tmp@w3; h1 = silu(h1)*h3
        gemm_nn<<<dim3(HID_/128, M_/64, B_), 256>>>(p_tmp, w1, p_h1, D_, D_, HID_, HID_, MD, 0, MH, 0);
        gemm_nn<<<dim3(HID_/128, M_/64, B_), 256>>>(p_tmp, w3, p_h3, D_, D_, HID_, HID_, MD, 0, MH, 0);
        silu_mul_k<<<(B_*M_*HID_ + 255) / 256, 256>>>(p_h1, p_h3);
        // om2 += h1 @ w2
        gemm_nn<<<dim3(D_/128, M_/64, B_), 256>>>(p_h1, w2, p_om2, HID_, HID_, D_, D_, MH, 0, MD, 1);
        // tmp = rmsnorm(om2, mem_norm_w)
        rmsnorm_k<<<B_*M_, 256>>>(p_om2, mem_w, p_tmp);
        // mk -> k[:, :M], mv -> v[:, :M]
        gemm_nn<<<dim3(D_/128, M_/64, B_), 256>>>(p_tmp, wkm, p_k, D_, D_, D_, D_, MD, 0, LD, 0);
        gemm_nn<<<dim3(D_/128, M_/64, B_), 256>>>(p_tmp, wvm, p_v, D_, D_, D_, D_, MD, 0, LD, 0);
        // xq/xk/xv -> second halves
        const float* xs = x + (long long)c * M_ * D_;
        gemm_nn<<<dim3(D_/128, M_/64, B_), 256>>>(xs, wq, p_q + MD, D_, D_, D_, D_, SD, 0, LD, 0);
        gemm_nn<<<dim3(D_/128, M_/64, B_), 256>>>(xs, wk, p_k + MD, D_, D_, D_, D_, SD, 0, LD, 0);
        gemm_nn<<<dim3(D_/128, M_/64, B_), 256>>>(xs, wv, p_v + MD, D_, D_, D_, D_, SD, 0, LD, 0);
        // mq = mk (pre-rope; rope is position-wise so equivalent)
        copy_mq_k<<<(B_*M_*D_ + 255) / 256, 256>>>(p_q, p_k);
        // rope q, k
        rope_k<<<(B_*L_*H_*HD2_ + 255) / 256, 256>>>(p_q, fcos, fsin);
        rope_k<<<(B_*L_*H_*HD2_ + 255) / 256, 256>>>(p_k, fcos, fsin);
        // attention
        attn_scores_k<<<dim3(L_/64, L_/64, B_*H_), 256>>>(p_q, p_k, p_sc);
        softmax_causal_k<<<B_*H_*L_, 128>>>(p_sc);
        attn_pv_k<<<dim3(L_/64, 1, B_*H_), 256>>>(p_sc, p_v, p_att);
        // om = out[:, M:]; stash into xo[:, c*M:(c+1)*M]
        extract_k<<<(B_*M_*D_ + 255) / 256, 256>>>(p_att, p_om, p_xo, c);
    }
    // final: out = xo @ wo  (8192 x 1024 x 1024)
    gemm_nn<<<dim3(D_/128, (B_*S_)/64, 1), 256>>>(p_xo, wo, out, D_, D_, D_, D_, 0, 0, 0, 0);
}

// round 4
// speedup vs baseline: 3.7015x; 2.0047x over previous
#include <cuda_runtime.h>
#include <cuda_bf16.h>
#include <math.h>
#include <stdint.h>

#define B_   2
#define S_   4096
#define D_   1024
#define H_   16
#define HD_  64
#define HD2_ 32
#define M_   512
#define L_   1024
#define HID_ 2816
#define NC_  8
#define EPS_ 1e-5f

// ---------------- scratch (no cudaMalloc allowed) ----------------
static __device__ float g_om  [B_*M_*D_];
static __device__ float g_om2 [B_*M_*D_];
static __device__ float g_tmp [B_*M_*D_];
static __device__ float g_h1  [B_*M_*HID_];
static __device__ float g_h3  [B_*M_*HID_];
static __device__ float g_q   [B_*L_*D_];
static __device__ float g_k   [B_*L_*D_];
static __device__ float g_v   [B_*L_*D_];
static __device__ float g_att [B_*L_*D_];
static __device__ float g_xo  [B_*S_*D_];
static __device__ float g_sc  [(size_t)B_*H_*L_*L_];   // 128 MB score buffer

// bf16 hi/lo transposed weights [N, K]
static __device__ __nv_bfloat16 g_wq_h[D_*D_],  g_wq_l[D_*D_];
static __device__ __nv_bfloat16 g_wk_h[D_*D_],  g_wk_l[D_*D_];
static __device__ __nv_bfloat16 g_wv_h[D_*D_],  g_wv_l[D_*D_];
static __device__ __nv_bfloat16 g_wo_h[D_*D_],  g_wo_l[D_*D_];
static __device__ __nv_bfloat16 g_wm_h[D_*D_],  g_wm_l[D_*D_];
static __device__ __nv_bfloat16 g_wkm_h[D_*D_], g_wkm_l[D_*D_];
static __device__ __nv_bfloat16 g_wvm_h[D_*D_], g_wvm_l[D_*D_];
static __device__ __nv_bfloat16 g_w1_h[HID_*D_], g_w1_l[HID_*D_];
static __device__ __nv_bfloat16 g_w3_h[HID_*D_], g_w3_l[HID_*D_];
static __device__ __nv_bfloat16 g_w2_h[D_*HID_], g_w2_l[D_*HID_];

// ---------------- PTX helpers (baseline PTX only: works on plain sm_103) ----------------
__device__ __forceinline__ uint32_t smem_u32(const void* p){
    uint32_t a;
    asm("{ .reg .u64 t; cvta.to.shared.u64 t, %1; cvt.u32.u64 %0, t; }":"=r"(a):"l"(p));
    return a;
}

#define LDM4(r, addr) \
    asm volatile("ldmatrix.sync.aligned.m8n8.x4.shared.b16 {%0,%1,%2,%3}, [%4];" \
        : "=r"((r)[0]), "=r"((r)[1]), "=r"((r)[2]), "=r"((r)[3]) : "r"(addr))

#define LDM2(r, addr) \
    asm volatile("ldmatrix.sync.aligned.m8n8.x2.shared.b16 {%0,%1}, [%2];" \
        : "=r"((r)[0]), "=r"((r)[1]) : "r"(addr))

#define MMA_BF16(c, a, b) \
    asm volatile("mma.sync.aligned.m16n8k16.row.col.f32.bf16.bf16.f32 " \
        "{%0,%1,%2,%3}, {%4,%5,%6,%7}, {%8,%9}, {%0,%1,%2,%3};" \
        : "+f"((c)[0]), "+f"((c)[1]), "+f"((c)[2]), "+f"((c)[3]) \
        : "r"((a)[0]), "r"((a)[1]), "r"((a)[2]), "r"((a)[3]), \
          "r"((b)[0]), "r"((b)[1]))

// smem tile layout per stage: Ah(0) Al(10240) Bh(20480) Bl(30720); stage stride 40960
#define STG_   40960
#define AHOFF_ 0
#define ALOFF_ 10240
#define BHOFF_ 20480
#define BLOFF_ 30720
#define LDS_   40        // padded row stride in bf16 elements (80B: ldmatrix conflict-free)

// ---------------- weight prep: W[K,N] -> Thi/Tlo[N,K] bf16 ----------------
__global__ void wprep_k(const float* __restrict__ W,
                        __nv_bfloat16* __restrict__ Thi, __nv_bfloat16* __restrict__ Tlo,
                        int K, int N)
{
    __shared__ float s[32][33];
    const int n0 = blockIdx.x * 32, k0 = blockIdx.y * 32;
    const int tx = threadIdx.x & 31, ty = threadIdx.x >> 5;
    #pragma unroll
    for (int i = 0; i < 4; i++)
        s[ty + 8*i][tx] = W[(long long)(k0 + ty + 8*i) * N + n0 + tx];
    __syncthreads();
    #pragma unroll
    for (int i = 0; i < 4; i++) {
        float x = s[tx][ty + 8*i];
        __nv_bfloat16 h = __float2bfloat16(x);
        __nv_bfloat16 l = __float2bfloat16(x - __bfloat162float(h));
        long long o = (long long)(n0 + ty + 8*i) * K + k0 + tx;
        Thi[o] = h; Tlo[o] = l;
    }
}

// ---------------- HMMA GEMM: C[M,N] (+)= A[M,K] @ Bt[N,K]^T, bf16 hi/lo x3 ----------------
// CTA 128x128, 8 warps (2x4), warp tile 64x32, K-slab 32, double-buffered smem.
__global__ void __launch_bounds__(256, 1) gemm_mma(
    const float* __restrict__ A, const __nv_bfloat16* __restrict__ Bhi,
    const __nv_bfloat16* __restrict__ Blo, float* __restrict__ C,
    int K, int lda, int ldc, long long sA, long long sC, int acc)
{
    extern __shared__ char sm[];
    const uint32_t sb = smem_u32(sm);
    const int t = threadIdx.x, lane = t & 31, wid = t >> 5;
    const int wm = (wid >> 2) * 64, wn = (wid & 3) * 32;

    A += (long long)blockIdx.z * sA;
    C += (long long)blockIdx.z * sC;
    const int m0 = blockIdx.y * 128, n0 = blockIdx.x * 128;

    float accr[4][4][4];
    #pragma unroll
    for (int i = 0; i < 4; i++)
        #pragma unroll
        for (int j = 0; j < 4; j++)
            #pragma unroll
            for (int r = 0; r < 4; r++) accr[i][j][r] = 0.f;

    // loader index maps
    const int ar  = t >> 3, akq = t & 7;        // A: 4 iters, row = i*32+ar? no: g=i*256+t
    const int br  = t >> 2, bkq = t & 3;        // B: 2 iters
    // actually recompute per-iter below with g = i*256 + t

    const int nk = K >> 5;   // 32-wide slabs

    // ---- store helpers (functionally inlined) ----
    // A float4 -> hi/lo bf16 at [row][k..k+3]
    // B uint4 (8 bf16) at [row][k..k+7]

    // prologue: slab 0 -> stage 0
    {
        #pragma unroll
        for (int i = 0; i < 4; i++) {
            int g = i * 256 + t, row = g >> 3, kq = g & 7;
            float4 v = *(const float4*)(A + (long long)(m0 + row) * lda + kq * 4);
            __nv_bfloat16 h0=__float2bfloat16(v.x), h1=__float2bfloat16(v.y),
                          h2=__float2bfloat16(v.z), h3=__float2bfloat16(v.w);
            __nv_bfloat16 l0=__float2bfloat16(v.x-__bfloat162float(h0)),
                          l1=__float2bfloat16(v.y-__bfloat162float(h1)),
                          l2=__float2bfloat16(v.z-__bfloat162float(h2)),
                          l3=__float2bfloat16(v.w-__bfloat162float(h3));
            uint2 hw, lw;
            hw.x = (uint32_t)__bfloat16_as_ushort(h0) | ((uint32_t)__bfloat16_as_ushort(h1) << 16);
            hw.y = (uint32_t)__bfloat16_as_ushort(h2) | ((uint32_t)__bfloat16_as_ushort(h3) << 16);
            lw.x = (uint32_t)__bfloat16_as_ushort(l0) | ((uint32_t)__bfloat16_as_ushort(l1) << 16);
            lw.y = (uint32_t)__bfloat16_as_ushort(l2) | ((uint32_t)__bfloat16_as_ushort(l3) << 16);
            int eo = (row * LDS_ + kq * 4) * 2;
            *(uint2*)(sm + AHOFF_ + eo) = hw;
            *(uint2*)(sm + ALOFF_ + eo) = lw;
        }
        #pragma unroll
        for (int i = 0; i < 2; i++) {
            int g = i * 256 + t, row = g >> 2, kq = g & 3;
            uint4 vh = *(const uint4*)(Bhi + (long long)(n0 + row) * K + kq * 8);
            uint4 vl = *(const uint4*)(Blo + (long long)(n0 + row) * K + kq * 8);
            int eo = (row * LDS_ + kq * 8) * 2;
            *(uint4*)(sm + BHOFF_ + eo) = vh;
            *(uint4*)(sm + BLOFF_ + eo) = vl;
        }
    }
    __syncthreads();

    for (int kb = 0; kb < nk; kb++) {
        const int cur = kb & 1;
        const bool hn = (kb + 1 < nk);
        float4 av[4]; uint4 gbh[2], gbl[2];
        if (hn) {
            const float* Ak = A + (kb + 1) * 32;
            const __nv_bfloat16* Bhk = Bhi + (kb + 1) * 32;
            const __nv_bfloat16* Blk = Blo + (kb + 1) * 32;
            #pragma unroll
            for (int i = 0; i < 4; i++) {
                int g = i * 256 + t, row = g >> 3, kq = g & 7;
                av[i] = *(const float4*)(Ak + (long long)(m0 + row) * lda + kq * 4);
            }
            #pragma unroll
            for (int i = 0; i < 2; i++) {
                int g = i * 256 + t, row = g >> 2, kq = g & 3;
                gbh[i] = *(const uint4*)(Bhk + (long long)(n0 + row) * K + kq * 8);
                gbl[i] = *(const uint4*)(Blk + (long long)(n0 + row) * K + kq * 8);
            }
        }

        const uint32_t stg = sb + cur * STG_;
        #pragma unroll
        for (int ks = 0; ks < 2; ks++) {
            const int k0 = ks * 16;
            uint32_t ah[4][4], al[4][4];
            const int arow = lane & 15, acol = k0 + ((lane >> 4) << 3);
            #pragma unroll
            for (int mi = 0; mi < 4; mi++) {
                uint32_t ad = stg + AHOFF_ + ((wm + mi*16 + arow) * LDS_ + acol) * 2;
                LDM4(ah[mi], ad);
                LDM4(al[mi], ad + (ALOFF_ - AHOFF_));
            }
            const int brow = lane & 7, bcol = k0 + (((lane >> 3) & 1) << 3);
            #pragma unroll
            for (int ni = 0; ni < 4; ni++) {
                uint32_t bfh[2], bfl[2];
                uint32_t bd = stg + BHOFF_ + ((wn + ni*8 + brow) * LDS_ + bcol) * 2;
                LDM2(bfh, bd);
                LDM2(bfl, bd + (BLOFF_ - BHOFF_));
                #pragma unroll
                for (int mi = 0; mi < 4; mi++) {
                    MMA_BF16(accr[mi][ni], ah[mi], bfh);
                    MMA_BF16(accr[mi][ni], ah[mi], bfl);
                    MMA_BF16(accr[mi][ni], al[mi], bfh);
                }
            }
        }

        if (hn) {
            char* stp = sm + (cur ^ 1) * STG_;
            #pragma unroll
            for (int i = 0; i < 4; i++) {
                int g = i * 256 + t, row = g >> 3, kq = g & 7;
                float4 v = av[i];
                __nv_bfloat16 h0=__float2bfloat16(v.x), h1=__float2bfloat16(v.y),
                              h2=__float2bfloat16(v.z), h3=__float2bfloat16(v.w);
                __nv_bfloat16 l0=__float2bfloat16(v.x-__bfloat162float(h0)),
                              l1=__float2bfloat16(v.y-__bfloat162float(h1)),
                              l2=__float2bfloat16(v.z-__bfloat162float(h2)),
                              l3=__float2bfloat16(v.w-__bfloat162float(h3));
                uint2 hw, lw;
                hw.x = (uint32_t)__bfloat16_as_ushort(h0) | ((uint32_t)__bfloat16_as_ushort(h1) << 16);
                hw.y = (uint32_t)__bfloat16_as_ushort(h2) | ((uint32_t)__bfloat16_as_ushort(h3) << 16);
                lw.x = (uint32_t)__bfloat16_as_ushort(l0) | ((uint32_t)__bfloat16_as_ushort(l1) << 16);
                lw.y = (uint32_t)__bfloat16_as_ushort(l2) | ((uint32_t)__bfloat16_as_ushort(l3) << 16);
                int eo = (row * LDS_ + kq * 4) * 2;
                *(uint2*)(stp + AHOFF_ + eo) = hw;
                *(uint2*)(stp + ALOFF_ + eo) = lw;
            }
            #pragma unroll
            for (int i = 0; i < 2; i++) {
                int g = i * 256 + t, row = g >> 2, kq = g & 3;
                int eo = (row * LDS_ + kq * 8) * 2;
                *(uint4*)(stp + BHOFF_ + eo) = gbh[i];
                *(uint4*)(stp + BLOFF_ + eo) = gbl[i];
            }
        }
        __syncthreads();
    }

    // epilogue
    #pragma unroll
    for (int mi = 0; mi < 4; mi++) {
        #pragma unroll
        for (int ni = 0; ni < 4; ni++) {
            long long r0 = m0 + wm + mi*16 + (lane >> 2);
            int cc = n0 + wn + ni*8 + (lane & 3) * 2;
            float* cp0 = C + r0 * ldc + cc;
            float* cp1 = cp0 + 8LL * ldc;
            if (acc) {
                float2 o0 = *(float2*)cp0, o1 = *(float2*)cp1;
                o0.x += accr[mi][ni][0]; o0.y += accr[mi][ni][1];
                o1.x += accr[mi][ni][2]; o1.y += accr[mi][ni][3];
                *(float2*)cp0 = o0; *(float2*)cp1 = o1;
            } else {
                float2 o0 = {accr[mi][ni][0], accr[mi][ni][1]};
                float2 o1 = {accr[mi][ni][2], accr[mi][ni][3]};
                *(float2*)cp0 = o0; *(float2*)cp1 = o1;
            }
        }
    }
}

// ---------------- RMSNorm over last dim D_ ----------------
__global__ void rmsnorm_k(const float* __restrict__ X, const float* __restrict__ W,
                          float* __restrict__ Y)
{
    const long long row = blockIdx.x;
    const float* x = X + row * D_;
    float* y = Y + row * D_;
    float ss = 0.f;
    for (int i = threadIdx.x; i < D_; i += 256) { float v = x[i]; ss += v * v; }
    __shared__ float red[8];
    for (int o = 16; o; o >>= 1) ss += __shfl_xor_sync(~0u, ss, o);
    if ((threadIdx.x & 31) == 0) red[threadIdx.x >> 5] = ss;
    __syncthreads();
    float tot = 0.f;
    #pragma unroll
    for (int i = 0; i < 8; i++) tot += red[i];
    const float inv = rsqrtf(tot * (1.f / D_) + EPS_);
    for (int i = threadIdx.x; i < D_; i += 256) y[i] = x[i] * inv * W[i];
}

// ---------------- elementwise ----------------
__global__ void init_om_k(float* __restrict__ om, const float* __restrict__ om0)
{
    int i = blockIdx.x * 256 + threadIdx.x;
    if (i < B_*M_*D_) om[i] = om0[i % (M_*D_)];
}

__global__ void silu_mul_k(float* __restrict__ a, const float* __restrict__ b)
{
    int i = blockIdx.x * 256 + threadIdx.x;
    if (i < B_*M_*HID_) {
        float v = a[i];
        a[i] = (v / (1.f + expf(-v))) * b[i];
    }
}

__global__ void copy_mq_k(float* __restrict__ q, const float* __restrict__ k)
{
    int i = blockIdx.x * 256 + threadIdx.x;
    if (i < B_*M_*D_) {
        int b = i / (M_*D_), r = i % (M_*D_);
        q[(long long)b * L_ * D_ + r] = k[(long long)b * L_ * D_ + r];
    }
}

__global__ void rope_k(float* __restrict__ t, const float* __restrict__ cf,
                       const float* __restrict__ sf)
{
    int i = blockIdx.x * 256 + threadIdx.x;
    if (i >= B_*L_*H_*HD2_) return;
    int d2 = i & 31;
    int h  = (i >> 5) & 15;
    int l  = (i >> 9) & (L_ - 1);
    int b  = i >> 19;
    long long base = (long long)(b * L_ + l) * D_ + h * HD_ + 2 * d2;
    float c = cf[l * HD2_ + d2], s = sf[l * HD2_ + d2];
    float tr = t[base], ti = t[base + 1];
    t[base]     = tr * c - ti * s;
    t[base + 1] = tr * s + ti * c;
}

__global__ void extract_k(const float* __restrict__ att, float* __restrict__ om,
                          float* __restrict__ xo, int c)
{
    int i = blockIdx.x * 256 + threadIdx.x;
    if (i < B_*M_*D_) {
        int b = i / (M_*D_), r = i % (M_*D_);
        float v = att[(long long)b * L_ * D_ + (long long)M_ * D_ + r];
        om[i] = v;
        xo[(long long)b * S_ * D_ + (long long)c * M_ * D_ + r] = v;
    }
}

// ---------------- attention: S = Q K^T (NT, per-head) ----------------
__global__ void attn_scores_k(const float* __restrict__ Q, const float* __restrict__ K,
                              float* __restrict__ Ssc)
{
    const int z = blockIdx.z;
    const int b = z >> 4, h = z & 15;
    const int i0 = blockIdx.y * 64;
    const int j0 = blockIdx.x * 64;
    if (j0 > i0 + 63) return;
    const float* q  = Q + (long long)b * L_ * D_ + h * HD_;
    const float* kp = K + (long long)b * L_ * D_ + h * HD_;
    float* sc = Ssc + (long long)z * L_ * L_;
    __shared__ float Qs[64][64];
    __shared__ float Ks[64][64];
    const int t = threadIdx.x;
    const int tx = t & 15, ty = t >> 4;
    const int r = t >> 2, c0 = (t & 3) << 4;

    #pragma unroll
    for (int w = 0; w < 4; w++) {
        float4 qa = *(const float4*)(q  + (long long)(i0 + r) * D_ + c0 + 4*w);
        Qs[c0+4*w+0][r] = qa.x; Qs[c0+4*w+1][r] = qa.y;
        Qs[c0+4*w+2][r] = qa.z; Qs[c0+4*w+3][r] = qa.w;
        float4 ka = *(const float4*)(kp + (long long)(j0 + r) * D_ + c0 + 4*w);
        Ks[c0+4*w+0][r] = ka.x; Ks[c0+4*w+1][r] = ka.y;
        Ks[c0+4*w+2][r] = ka.z; Ks[c0+4*w+3][r] = ka.w;
    }
    __syncthreads();

    float acc[4][4] = {};
    #pragma unroll 8
    for (int kk = 0; kk < 64; kk++) {
        float4 av = *(const float4*)&Qs[kk][ty * 4];
        float4 cv = *(const float4*)&Ks[kk][tx * 4];
        float a[4] = {av.x, av.y, av.z, av.w};
        float c[4] = {cv.x, cv.y, cv.z, cv.w};
        #pragma unroll
        for (int i = 0; i < 4; i++)
            #pragma unroll
            for (int j = 0; j < 4; j++)
                acc[i][j] = fmaf(a[i], c[j], acc[i][j]);
    }
    #pragma unroll
    for (int i = 0; i < 4; i++) {
        float4 o = {acc[i][0], acc[i][1], acc[i][2], acc[i][3]};
        *(float4*)&sc[(long long)(i0 + ty*4 + i) * L_ + j0 + tx*4] = o;
    }
}

// ---------------- causal softmax ----------------
__global__ void softmax_causal_k(float* __restrict__ Ssc)
{
    const long long rowg = blockIdx.x;
    const int i = (int)(rowg & (L_ - 1));
    const long long z = rowg >> 10;
    float* s = Ssc + z * (long long)L_ * L_ + (long long)i * L_;
    const int n = i + 1;
    const float scale = 0.125f;
    __shared__ float red[4];
    float m = -3.4e38f;
    for (int j = threadIdx.x; j < n; j += 128) m = fmaxf(m, s[j]);
    for (int o = 16; o; o >>= 1) m = fmaxf(m, __shfl_xor_sync(~0u, m, o));
    if ((threadIdx.x & 31) == 0) red[threadIdx.x >> 5] = m;
    __syncthreads();
    m = fmaxf(fmaxf(red[0], red[1]), fmaxf(red[2], red[3]));
    const float ms = m * scale;
    float sum = 0.f;
    for (int j = threadIdx.x; j < n; j += 128) {
        float e = expf(s[j] * scale - ms);
        s[j] = e;
        sum += e;
    }
    for (int o = 16; o; o >>= 1) sum += __shfl_xor_sync(~0u, sum, o);
    __syncthreads();
    if ((threadIdx.x & 31) == 0) red[threadIdx.x >> 5] = sum;
    __syncthreads();
    sum = red[0] + red[1] + red[2] + red[3];
    const float inv = 1.f / sum;
    for (int j = threadIdx.x; j < n; j += 128) s[j] *= inv;
    for (int j = n + threadIdx.x; j < L_; j += 128) s[j] = 0.f;
}

// ---------------- attention: O = P @ V ----------------
__global__ void attn_pv_k(const float* __restrict__ P, const float* __restrict__ V,
                          float* __restrict__ O)
{
    const int z = blockIdx.z;
    const int b = z >> 4, h = z & 15;
    const int i0 = blockIdx.x * 64;
    const float* p = P + (long long)z * L_ * L_;
    const float* v = V + (long long)b * L_ * D_ + h * HD_;
    float* o = O + (long long)b * L_ * D_ + h * HD_;
    __shared__ float Ps[2][16][64];
    __shared__ float Vs[2][16][64];
    const int t = threadIdx.x;
    const int tx = t & 15, ty = t >> 4;
    const int pm = t >> 2, pk = (t & 3) << 2;
    const int vk = t >> 4, vd = (t & 15) << 2;
    float acc[4][4] = {};
    const int nk = (i0 + 64) >> 4;

    {
        float4 pa = *(const float4*)(p + (long long)(i0 + pm) * L_ + pk);
        Ps[0][pk+0][pm] = pa.x; Ps[0][pk+1][pm] = pa.y;
        Ps[0][pk+2][pm] = pa.z; Ps[0][pk+3][pm] = pa.w;
        float4 va = *(const float4*)(v + (long long)vk * D_ + vd);
        *(float4*)&Vs[0][vk][vd] = va;
    }
    __syncthreads();

    for (int kb = 0; kb < nk; kb++) {
        const int cur = kb & 1;
        float4 npa, nva;
        const bool has_next = (kb + 1 < nk);
        if (has_next) {
            npa = *(const float4*)(p + (long long)(i0 + pm) * L_ + (kb+1)*16 + pk);
            nva = *(const float4*)(v + (long long)((kb+1)*16 + vk) * D_ + vd);
        }
        #pragma unroll
        for (int kk = 0; kk < 16; kk++) {
            float4 av = *(const float4*)&Ps[cur][kk][ty * 4];
            float4 cv = *(const float4*)&Vs[cur][kk][tx * 4];
            float a[4] = {av.x, av.y, av.z, av.w};
            float c[4] = {cv.x, cv.y, cv.z, cv.w};
            #pragma unroll
            for (int i = 0; i < 4; i++)
                #pragma unroll
                for (int j = 0; j < 4; j++)
                    acc[i][j] = fmaf(a[i], c[j], acc[i][j]);
        }
        if (has_next) {
            const int nxt = cur ^ 1;
            Ps[nxt][pk+0][pm] = npa.x; Ps[nxt][pk+1][pm] = npa.y;
            Ps[nxt][pk+2][pm] = npa.z; Ps[nxt][pk+3][pm] = npa.w;
            *(float4*)&Vs[nxt][vk][vd] = nva;
        }
        __syncthreads();
    }
    #pragma unroll
    for (int i = 0; i < 4; i++) {
        float4 ov = {acc[i][0], acc[i][1], acc[i][2], acc[i][3]};
        *(float4*)&o[(long long)(i0 + ty*4 + i) * D_ + tx*4] = ov;
    }
}

// ---------------- host orchestration ----------------
extern "C" void kernel_launch(void* const* d_in, const int* in_sizes, int n_in,
                              void* d_out, int out_size)
{
    const float* x     = (const float*)d_in[0];
    const float* fcos  = (const float*)d_in[1];
    const float* fsin  = (const float*)d_in[2];
    const float* wq    = (const float*)d_in[3];
    const float* wk    = (const float*)d_in[4];
    const float* wv    = (const float*)d_in[5];
    const float* wo    = (const float*)d_in[6];
    const float* wm    = (const float*)d_in[7];
    const float* wkm   = (const float*)d_in[8];
    const float* wvm   = (const float*)d_in[9];
    const float* w1    = (const float*)d_in[10];
    const float* w3    = (const float*)d_in[11];
    const float* w2    = (const float*)d_in[12];
    const float* ffn_w = (const float*)d_in[13];
    const float* mem_w = (const float*)d_in[14];
    const float* om0   = (const float*)d_in[15];
    float* out = (float*)d_out;

    float *p_om, *p_om2, *p_tmp, *p_h1, *p_h3, *p_q, *p_k, *p_v, *p_att, *p_xo, *p_sc;
    cudaGetSymbolAddress((void**)&p_om,  g_om);
    cudaGetSymbolAddress((void**)&p_om2, g_om2);
    cudaGetSymbolAddress((void**)&p_tmp, g_tmp);
    cudaGetSymbolAddress((void**)&p_h1,  g_h1);
    cudaGetSymbolAddress((void**)&p_h3,  g_h3);
    cudaGetSymbolAddress((void**)&p_q,   g_q);
    cudaGetSymbolAddress((void**)&p_k,   g_k);
    cudaGetSymbolAddress((void**)&p_v,   g_v);
    cudaGetSymbolAddress((void**)&p_att, g_att);
    cudaGetSymbolAddress((void**)&p_xo,  g_xo);
    cudaGetSymbolAddress((void**)&p_sc,  g_sc);

    __nv_bfloat16 *wqh,*wql,*wkh,*wkl,*wvh,*wvl,*woh,*wol,*wmh,*wml,*wkmh,*wkml,*wvmh,*wvml;
    __nv_bfloat16 *w1h,*w1l,*w3h,*w3l,*w2h,*w2l;
    cudaGetSymbolAddress((void**)&wqh,  g_wq_h);  cudaGetSymbolAddress((void**)&wql,  g_wq_l);
    cudaGetSymbolAddress((void**)&wkh,  g_wk_h);  cudaGetSymbolAddress((void**)&wkl,  g_wk_l);
    cudaGetSymbolAddress((void**)&wvh,  g_wv_h);  cudaGetSymbolAddress((void**)&wvl,  g_wv_l);
    cudaGetSymbolAddress((void**)&woh,  g_wo_h);  cudaGetSymbolAddress((void**)&wol,  g_wo_l);
    cudaGetSymbolAddress((void**)&wmh,  g_wm_h);  cudaGetSymbolAddress((void**)&wml,  g_wm_l);
    cudaGetSymbolAddress((void**)&wkmh, g_wkm_h); cudaGetSymbolAddress((void**)&wkml, g_wkm_l);
    cudaGetSymbolAddress((void**)&wvmh, g_wvm_h); cudaGetSymbolAddress((void**)&wvml, g_wvm_l);
    cudaGetSymbolAddress((void**)&w1h,  g_w1_h);  cudaGetSymbolAddress((void**)&w1l,  g_w1_l);
    cudaGetSymbolAddress((void**)&w3h,  g_w3_h);  cudaGetSymbolAddress((void**)&w3l,  g_w3_l);
    cudaGetSymbolAddress((void**)&w2h,  g_w2_h);  cudaGetSymbolAddress((void**)&w2l,  g_w2_l);

    cudaFuncSetAttribute(gemm_mma, cudaFuncAttributeMaxDynamicSharedMemorySize, 2 * STG_);
    const int GSM = 2 * STG_;

    const long long MD = (long long)M_ * D_;
    const long long LD = (long long)L_ * D_;
    const long long SD = (long long)S_ * D_;

    // weight prep (transpose + bf16 hi/lo split)
    wprep_k<<<dim3(D_/32,   D_/32),   256>>>(wq,  wqh,  wql,  D_,   D_);
    wprep_k<<<dim3(D_/32,   D_/32),   256>>>(wk,  wkh,  wkl,  D_,   D_);
    wprep_k<<<dim3(D_/32,   D_/32),   256>>>(wv,  wvh,  wvl,  D_,   D_);
    wprep_k<<<dim3(D_/32,   D_/32),   256>>>(wo,  woh,  wol,  D_,   D_);
    wprep_k<<<dim3(D_/32,   D_/32),   256>>>(wm,  wmh,  wml,  D_,   D_);
    wprep_k<<<dim3(D_/32,   D_/32),   256>>>(wkm, wkmh, wkml, D_,   D_);
    wprep_k<<<dim3(D_/32,   D_/32),   256>>>(wvm, wvmh, wvml, D_,   D_);
    wprep_k<<<dim3(HID_/32, D_/32),   256>>>(w1,  w1h,  w1l,  D_,   HID_);
    wprep_k<<<dim3(HID_/32, D_/32),   256>>>(w3,  w3h,  w3l,  D_,   HID_);
    wprep_k<<<dim3(D_/32,   HID_/32), 256>>>(w2,  w2h,  w2l,  HID_, D_);

    init_om_k<<<(B_*M_*D_ + 255) / 256, 256>>>(p_om, om0);

    for (int c = 0; c < NC_; c++) {
        // om2 = om @ wm   (B*M = 1024 contiguous rows)
        gemm_mma<<<dim3(D_/128, 8, 1), 256, GSM>>>(p_om, wmh, wml, p_om2, D_, D_, D_, 0, 0, 0);
        rmsnorm_k<<<B_*M_, 256>>>(p_om2, ffn_w, p_tmp);
        // h1 = tmp@w1, h3 = tmp@w3
        gemm_mma<<<dim3(HID_/128, 8, 1), 256, GSM>>>(p_tmp, w1h, w1l, p_h1, D_, D_, HID_, 0, 0, 0);
        gemm_mma<<<dim3(HID_/128, 8, 1), 256, GSM>>>(p_tmp, w3h, w3l, p_h3, D_, D_, HID_, 0, 0, 0);
        silu_mul_k<<<(B_*M_*HID_ + 255) / 256, 256>>>(p_h1, p_h3);
        // om2 += h1 @ w2
        gemm_mma<<<dim3(D_/128, 8, 1), 256, GSM>>>(p_h1, w2h, w2l, p_om2, HID_, HID_, D_, 0, 0, 1);
        rmsnorm_k<<<B_*M_, 256>>>(p_om2, mem_w, p_tmp);
        // mk/mv -> k/v[:, :M]   (batched: A stride MD, C stride LD)
        gemm_mma<<<dim3(D_/128, 4, B_), 256, GSM>>>(p_tmp, wkmh, wkml, p_k, D_, D_, D_, MD, LD, 0);
        gemm_mma<<<dim3(D_/128, 4, B_), 256, GSM>>>(p_tmp, wvmh, wvml, p_v, D_, D_, D_, MD, LD, 0);
        // xq/xk/xv -> second halves
        const float* xs = x + (long long)c * M_ * D_;
        gemm_mma<<<dim3(D_/128, 4, B_), 256, GSM>>>(xs, wqh, wql, p_q + MD, D_, D_, D_, SD, LD, 0);
        gemm_mma<<<dim3(D_/128, 4, B_), 256, GSM>>>(xs, wkh, wkl, p_k + MD, D_, D_, D_, SD, LD, 0);
        gemm_mma<<<dim3(D_/128, 4, B_), 256, GSM>>>(xs, wvh, wvl, p_v + MD, D_, D_, D_, SD, LD, 0);
        // mq = mk (pre-rope; rope is position-wise so equivalent)
        copy_mq_k<<<(B_*M_*D_ + 255) / 256, 256>>>(p_q, p_k);
        rope_k<<<(B_*L_*H_*HD2_ + 255) / 256, 256>>>(p_q, fcos, fsin);
        rope_k<<<(B_*L_*H_*HD2_ + 255) / 256, 256>>>(p_k, fcos, fsin);
        // attention
        attn_scores_k<<<dim3(L_/64, L_/64, B_*H_), 256>>>(p_q, p_k, p_sc);
        softmax_causal_k<<<B_*H_*L_, 128>>>(p_sc);
        attn_pv_k<<<dim3(L_/64, 1, B_*H_), 256>>>(p_sc, p_v, p_att);
        extract_k<<<(B_*M_*D_ + 255) / 256, 256>>>(p_att, p_om, p_xo, c);
    }
    // final: out = xo @ wo
    gemm_mma<<<dim3(D_/128, (B_*S_)/128, 1), 256, GSM>>>(p_xo, woh, wol, out, D_, D_, D_, 0, 0, 0);
}

// round 7
// speedup vs baseline: 5.0613x; 1.3674x over previous
#include <cuda_runtime.h>
#include <cuda_bf16.h>
#include <math.h>
#include <stdint.h>

#define B_   2
#define S_   4096
#define D_   1024
#define H_   16
#define HD_  64
#define HD2_ 32
#define M_   512
#define L_   1024
#define HID_ 2816
#define NC_  8
#define EPS_ 1e-5f

// ---------------- scratch (no cudaMalloc allowed) ----------------
static __device__ float g_om  [B_*M_*D_];
static __device__ float g_om2 [B_*M_*D_];
static __device__ float g_tmp [B_*M_*D_];
static __device__ float g_h1  [B_*M_*HID_];
static __device__ float g_h3  [B_*M_*HID_];
static __device__ float g_k   [B_*L_*D_];   // mem-K (= mem-Q), first M rows per batch
static __device__ float g_v   [B_*L_*D_];   // mem-V, first M rows per batch
static __device__ float g_att [B_*L_*D_];
static __device__ float g_xo  [B_*S_*D_];
static __device__ float g_xq  [B_*S_*D_];   // precomputed rope'd x-part Q
static __device__ float g_xk  [B_*S_*D_];
static __device__ float g_xv  [B_*S_*D_];

// bf16 hi/lo transposed weights [N, K]
static __device__ __nv_bfloat16 g_wq_h[D_*D_],  g_wq_l[D_*D_];
static __device__ __nv_bfloat16 g_wk_h[D_*D_],  g_wk_l[D_*D_];
static __device__ __nv_bfloat16 g_wv_h[D_*D_],  g_wv_l[D_*D_];
static __device__ __nv_bfloat16 g_wo_h[D_*D_],  g_wo_l[D_*D_];
static __device__ __nv_bfloat16 g_wm_h[D_*D_],  g_wm_l[D_*D_];
static __device__ __nv_bfloat16 g_wkm_h[D_*D_], g_wkm_l[D_*D_];
static __device__ __nv_bfloat16 g_wvm_h[D_*D_], g_wvm_l[D_*D_];
static __device__ __nv_bfloat16 g_w1_h[HID_*D_], g_w1_l[HID_*D_];
static __device__ __nv_bfloat16 g_w3_h[HID_*D_], g_w3_l[HID_*D_];
static __device__ __nv_bfloat16 g_w2_h[D_*HID_], g_w2_l[D_*HID_];

// ---------------- PTX helpers (baseline PTX only: works on plain sm_103) ----------------
__device__ __forceinline__ uint32_t smem_u32(const void* p){
    uint32_t a;
    asm("{ .reg .u64 t; cvta.to.shared.u64 t, %1; cvt.u32.u64 %0, t; }":"=r"(a):"l"(p));
    return a;
}

#define LDM4(r, addr) \
    asm volatile("ldmatrix.sync.aligned.m8n8.x4.shared.b16 {%0,%1,%2,%3}, [%4];" \
        : "=r"((r)[0]), "=r"((r)[1]), "=r"((r)[2]), "=r"((r)[3]) : "r"(addr))

#define LDM2(r, addr) \
    asm volatile("ldmatrix.sync.aligned.m8n8.x2.shared.b16 {%0,%1}, [%2];" \
        : "=r"((r)[0]), "=r"((r)[1]) : "r"(addr))

#define MMA_BF16(c, a, b) \
    asm volatile("mma.sync.aligned.m16n8k16.row.col.f32.bf16.bf16.f32 " \
        "{%0,%1,%2,%3}, {%4,%5,%6,%7}, {%8,%9}, {%0,%1,%2,%3};" \
        : "+f"((c)[0]), "+f"((c)[1]), "+f"((c)[2]), "+f"((c)[3]) \
        : "r"((a)[0]), "r"((a)[1]), "r"((a)[2]), "r"((a)[3]), \
          "r"((b)[0]), "r"((b)[1]))

__device__ __forceinline__ uint32_t pack_hi(float a, float b){
    return (uint32_t)__bfloat16_as_ushort(__float2bfloat16(a))
         | ((uint32_t)__bfloat16_as_ushort(__float2bfloat16(b)) << 16);
}
__device__ __forceinline__ uint32_t pack_lo(float a, float b){
    float ah = __bfloat162float(__float2bfloat16(a));
    float bh = __bfloat162float(__float2bfloat16(b));
    return (uint32_t)__bfloat16_as_ushort(__float2bfloat16(a - ah))
         | ((uint32_t)__bfloat16_as_ushort(__float2bfloat16(b - bh)) << 16);
}

#define LDS_   40        // GEMM smem row stride in bf16 (80B: conflict-free + 16B aligned)

// ---------------- weight prep: W[K,N] -> Thi/Tlo[N,K] bf16 ----------------
__global__ void wprep_k(const float* __restrict__ W,
                        __nv_bfloat16* __restrict__ Thi, __nv_bfloat16* __restrict__ Tlo,
                        int K, int N)
{
    __shared__ float s[32][33];
    const int n0 = blockIdx.x * 32, k0 = blockIdx.y * 32;
    const int tx = threadIdx.x & 31, ty = threadIdx.x >> 5;
    #pragma unroll
    for (int i = 0; i < 4; i++)
        s[ty + 8*i][tx] = W[(long long)(k0 + ty + 8*i) * N + n0 + tx];
    __syncthreads();
    #pragma unroll
    for (int i = 0; i < 4; i++) {
        float x = s[tx][ty + 8*i];
        __nv_bfloat16 h = __float2bfloat16(x);
        __nv_bfloat16 l = __float2bfloat16(x - __bfloat162float(h));
        long long o = (long long)(n0 + ty + 8*i) * K + k0 + tx;
        Thi[o] = h; Tlo[o] = l;
    }
}

// ---------------- HMMA GEMM: C[M,N] (+)= A[M,K] @ Bt[N,K]^T, bf16 hi/lo x3 ----------------
// CTA 128 x BN, 8 warps (2 x 4), warp tile 64 x BN/4, K-slab 32, double-buffered smem.
template<int BN>
__global__ void __launch_bounds__(256, 1) gemm_mma(
    const float* __restrict__ A, const __nv_bfloat16* __restrict__ Bhi,
    const __nv_bfloat16* __restrict__ Blo, float* __restrict__ C,
    int K, int lda, int ldc, long long sA, long long sC, int acc)
{
    constexpr int NI    = BN / 32;
    constexpr int ALOFF = 10240;
    constexpr int BHOFF = 20480;
    constexpr int BLOFF = 20480 + BN * 80;
    constexpr int STG   = 20480 + 2 * BN * 80;

    extern __shared__ char sm[];
    const uint32_t sb = smem_u32(sm);
    const int t = threadIdx.x, lane = t & 31, wid = t >> 5;
    const int wm = (wid >> 2) * 64, wn = (wid & 3) * (BN / 4);

    A += (long long)blockIdx.z * sA;
    C += (long long)blockIdx.z * sC;
    const int m0 = blockIdx.y * 128, n0 = blockIdx.x * BN;

    float accr[4][NI][4];
    #pragma unroll
    for (int i = 0; i < 4; i++)
        #pragma unroll
        for (int j = 0; j < NI; j++)
            #pragma unroll
            for (int r = 0; r < 4; r++) accr[i][j][r] = 0.f;

    const int nk = K >> 5;

    // prologue: slab 0 -> stage 0
    {
        #pragma unroll
        for (int i = 0; i < 4; i++) {
            int g = i * 256 + t, row = g >> 3, kq = g & 7;
            float4 v = *(const float4*)(A + (long long)(m0 + row) * lda + kq * 4);
            uint2 hw, lw;
            hw.x = pack_hi(v.x, v.y); hw.y = pack_hi(v.z, v.w);
            lw.x = pack_lo(v.x, v.y); lw.y = pack_lo(v.z, v.w);
            int eo = (row * LDS_ + kq * 4) * 2;
            *(uint2*)(sm + eo)         = hw;
            *(uint2*)(sm + ALOFF + eo) = lw;
        }
        #pragma unroll
        for (int i = 0; i < BN/64; i++) {
            int g = i * 256 + t, row = g >> 2, kq = g & 3;
            uint4 vh = *(const uint4*)(Bhi + (long long)(n0 + row) * K + kq * 8);
            uint4 vl = *(const uint4*)(Blo + (long long)(n0 + row) * K + kq * 8);
            int eo = (row * LDS_ + kq * 8) * 2;
            *(uint4*)(sm + BHOFF + eo) = vh;
            *(uint4*)(sm + BLOFF + eo) = vl;
        }
    }
    __syncthreads();

    for (int kb = 0; kb < nk; kb++) {
        const int cur = kb & 1;
        const bool hn = (kb + 1 < nk);
        float4 av[4]; uint4 gbh[BN/64], gbl[BN/64];
        if (hn) {
            const float* Ak = A + (kb + 1) * 32;
            const __nv_bfloat16* Bhk = Bhi + (kb + 1) * 32;
            const __nv_bfloat16* Blk = Blo + (kb + 1) * 32;
            #pragma unroll
            for (int i = 0; i < 4; i++) {
                int g = i * 256 + t, row = g >> 3, kq = g & 7;
                av[i] = *(const float4*)(Ak + (long long)(m0 + row) * lda + kq * 4);
            }
            #pragma unroll
            for (int i = 0; i < BN/64; i++) {
                int g = i * 256 + t, row = g >> 2, kq = g & 3;
                gbh[i] = *(const uint4*)(Bhk + (long long)(n0 + row) * K + kq * 8);
                gbl[i] = *(const uint4*)(Blk + (long long)(n0 + row) * K + kq * 8);
            }
        }

        const uint32_t stg = sb + cur * STG;
        #pragma unroll
        for (int ks = 0; ks < 2; ks++) {
            const int k0 = ks * 16;
            uint32_t ah[4][4], al[4][4];
            const int arow = lane & 15, acol = k0 + ((lane >> 4) << 3);
            #pragma unroll
            for (int mi = 0; mi < 4; mi++) {
                uint32_t ad = stg + ((wm + mi*16 + arow) * LDS_ + acol) * 2;
                LDM4(ah[mi], ad);
                LDM4(al[mi], ad + ALOFF);
            }
            const int brow = lane & 7, bcol = k0 + (((lane >> 3) & 1) << 3);
            #pragma unroll
            for (int ni = 0; ni < NI; ni++) {
                uint32_t bfh[2], bfl[2];
                uint32_t bd = stg + BHOFF + ((wn + ni*8 + brow) * LDS_ + bcol) * 2;
                LDM2(bfh, bd);
                LDM2(bfl, bd + (BLOFF - BHOFF));
                #pragma unroll
                for (int mi = 0; mi < 4; mi++) {
                    MMA_BF16(accr[mi][ni], ah[mi], bfh);
                    MMA_BF16(accr[mi][ni], ah[mi], bfl);
                    MMA_BF16(accr[mi][ni], al[mi], bfh);
                }
            }
        }

        if (hn) {
            char* stp = sm + (cur ^ 1) * STG;
            #pragma unroll
            for (int i = 0; i < 4; i++) {
                int g = i * 256 + t, row = g >> 3, kq = g & 7;
                float4 v = av[i];
                uint2 hw, lw;
                hw.x = pack_hi(v.x, v.y); hw.y = pack_hi(v.z, v.w);
                lw.x = pack_lo(v.x, v.y); lw.y = pack_lo(v.z, v.w);
                int eo = (row * LDS_ + kq * 4) * 2;
                *(uint2*)(stp + eo)         = hw;
                *(uint2*)(stp + ALOFF + eo) = lw;
            }
            #pragma unroll
            for (int i = 0; i < BN/64; i++) {
                int g = i * 256 + t, row = g >> 2, kq = g & 3;
                int eo = (row * LDS_ + kq * 8) * 2;
                *(uint4*)(stp + BHOFF + eo) = gbh[i];
                *(uint4*)(stp + BLOFF + eo) = gbl[i];
            }
        }
        __syncthreads();
    }

    // epilogue
    #pragma unroll
    for (int mi = 0; mi < 4; mi++) {
        #pragma unroll
        for (int ni = 0; ni < NI; ni++) {
            long long r0 = m0 + wm + mi*16 + (lane >> 2);
            int cc = n0 + wn + ni*8 + (lane & 3) * 2;
            float* cp0 = C + r0 * ldc + cc;
            float* cp1 = cp0 + 8LL * ldc;
            if (acc) {
                float2 o0 = *(float2*)cp0, o1 = *(float2*)cp1;
                o0.x += accr[mi][ni][0]; o0.y += accr[mi][ni][1];
                o1.x += accr[mi][ni][2]; o1.y += accr[mi][ni][3];
                *(float2*)cp0 = o0; *(float2*)cp1 = o1;
            } else {
                float2 o0 = {accr[mi][ni][0], accr[mi][ni][1]};
                float2 o1 = {accr[mi][ni][2], accr[mi][ni][3]};
                *(float2*)cp0 = o0; *(float2*)cp1 = o1;
            }
        }
    }
}

// ---------------- flash attention: O = softmax(causal(Q K^T * 0.125)) V ----------------
// grid (L/128, B*H), 256 threads. Warp w owns q rows [i0 + 16w, i0 + 16w + 16).
// Q/K/V fp32 sources split mem-part (rows < M) / x-part (rows >= M).
#define FLS_ 72   // flash smem row stride (bf16): 144B, 16B-aligned, ldmatrix conflict-free
__global__ void __launch_bounds__(256) flash_k(
    const float* __restrict__ Kmem,   // [B][M][D], rope'd (= mem Q)
    const float* __restrict__ Vmem,   // [B][M][D]
    const float* __restrict__ Qx,     // chunk slice base; row r-M at b*SD + (r-M)*D
    const float* __restrict__ Kx,
    const float* __restrict__ Vx,
    float* __restrict__ O)            // [B][L][D]
{
    __shared__ __nv_bfloat16 sKh[64*FLS_], sKl[64*FLS_], sVh[64*FLS_], sVl[64*FLS_];
    const int t = threadIdx.x, lane = t & 31, w = t >> 5;
    const int bh = blockIdx.y, b = bh >> 4, h = bh & 15;
    const int i0 = blockIdx.x * 128;
    const long long MD = (long long)M_ * D_, SD = (long long)S_ * D_;
    const long long LDmem = (long long)L_ * D_;   // mem buffers have batch stride L*D
    const int hoff = h * HD_;

    const uint32_t kh_b = smem_u32(sKh), kl_b = smem_u32(sKl);
    const uint32_t vh_b = smem_u32(sVh), vl_b = smem_u32(sVl);

    // --- Q fragments (scaled by 0.125, hi/lo), rows r0 = i0+16w+(lane>>2), r1 = r0+8 ---
    uint32_t qh[4][4], ql[4][4];
    {
        const int r0 = i0 + w*16 + (lane >> 2);
        const float* q0 = (r0 < M_) ? (Kmem + b*LDmem + (long long)r0*D_ + hoff)
                                    : (Qx + b*SD + (long long)(r0 - M_)*D_ + hoff);
        const float* q1 = ((r0+8) < M_) ? (Kmem + b*LDmem + (long long)(r0+8)*D_ + hoff)
                                        : (Qx + b*SD + (long long)(r0+8 - M_)*D_ + hoff);
        const int c0 = (lane & 3) * 2;
        #pragma unroll
        for (int ks = 0; ks < 4; ks++) {
            float2 v0 = *(const float2*)(q0 + ks*16 + c0);
            float2 v1 = *(const float2*)(q1 + ks*16 + c0);
            float2 v2 = *(const float2*)(q0 + ks*16 + c0 + 8);
            float2 v3 = *(const float2*)(q1 + ks*16 + c0 + 8);
            v0.x *= 0.125f; v0.y *= 0.125f; v1.x *= 0.125f; v1.y *= 0.125f;
            v2.x *= 0.125f; v2.y *= 0.125f; v3.x *= 0.125f; v3.y *= 0.125f;
            qh[ks][0] = pack_hi(v0.x, v0.y); ql[ks][0] = pack_lo(v0.x, v0.y);
            qh[ks][1] = pack_hi(v1.x, v1.y); ql[ks][1] = pack_lo(v1.x, v1.y);
            qh[ks][2] = pack_hi(v2.x, v2.y); ql[ks][2] = pack_lo(v2.x, v2.y);
            qh[ks][3] = pack_hi(v3.x, v3.y); ql[ks][3] = pack_lo(v3.x, v3.y);
        }
    }

    float oacc[8][4];
    #pragma unroll
    for (int i = 0; i < 8; i++)
        #pragma unroll
        for (int r = 0; r < 4; r++) oacc[i][r] = 0.f;
    float m0 = -1e30f, m1 = -1e30f, l0 = 0.f, l1 = 0.f;

    const int jmax = (i0 >> 6) + 2;
    for (int jt = 0; jt < jmax; jt++) {
        const int j0 = jt * 64;
        if (jt) __syncthreads();
        // cooperative K/V tile load + hi/lo convert (V transposed)
        #pragma unroll
        for (int i = 0; i < 4; i++) {
            int g = i * 256 + t, row = g >> 4, cq = (g & 15) * 4;
            int kr = j0 + row;
            const float* kp = (kr < M_) ? (Kmem + b*LDmem + (long long)kr*D_ + hoff)
                                        : (Kx + b*SD + (long long)(kr - M_)*D_ + hoff);
            float4 kv = *(const float4*)(kp + cq);
            uint2 hw, lw;
            hw.x = pack_hi(kv.x, kv.y); hw.y = pack_hi(kv.z, kv.w);
            lw.x = pack_lo(kv.x, kv.y); lw.y = pack_lo(kv.z, kv.w);
            int eo = (row * FLS_ + cq) * 2;
            *(uint2*)((char*)sKh + eo) = hw;
            *(uint2*)((char*)sKl + eo) = lw;
            const float* vp = (kr < M_) ? (Vmem + b*LDmem + (long long)kr*D_ + hoff)
                                        : (Vx + b*SD + (long long)(kr - M_)*D_ + hoff);
            float4 vv = *(const float4*)(vp + cq);
            float vsv[4] = {vv.x, vv.y, vv.z, vv.w};
            #pragma unroll
            for (int j = 0; j < 4; j++) {
                __nv_bfloat16 hb = __float2bfloat16(vsv[j]);
                __nv_bfloat16 lb = __float2bfloat16(vsv[j] - __bfloat162float(hb));
                sVh[(cq + j) * FLS_ + row] = hb;
                sVl[(cq + j) * FLS_ + row] = lb;
            }
        }
        __syncthreads();

        if (j0 > i0 + w*16 + 15) continue;   // tile fully masked for this warp

        // --- S = Q K^T ---
        float sc[8][4];
        #pragma unroll
        for (int i = 0; i < 8; i++)
            #pragma unroll
            for (int r = 0; r < 4; r++) sc[i][r] = 0.f;
        #pragma unroll
        for (int ks = 0; ks < 4; ks++) {
            const int bcol = ks*16 + (((lane >> 3) & 1) << 3);
            #pragma unroll
            for (int nt = 0; nt < 8; nt++) {
                uint32_t bfh[2], bfl[2];
                uint32_t off = ((nt*8 + (lane & 7)) * FLS_ + bcol) * 2;
                LDM2(bfh, kh_b + off);
                LDM2(bfl, kl_b + off);
                MMA_BF16(sc[nt], qh[ks], bfh);
                MMA_BF16(sc[nt], qh[ks], bfl);
                MMA_BF16(sc[nt], ql[ks], bfh);
            }
        }

        // --- mask + online softmax ---
        const int r0 = i0 + w*16 + (lane >> 2);
        float mt0 = -1e30f, mt1 = -1e30f;
        #pragma unroll
        for (int nt = 0; nt < 8; nt++) {
            int cb = j0 + nt*8 + (lane & 3) * 2;
            if (cb     > r0)     sc[nt][0] = -1e30f;
            if (cb + 1 > r0)     sc[nt][1] = -1e30f;
            if (cb     > r0 + 8) sc[nt][2] = -1e30f;
            if (cb + 1 > r0 + 8) sc[nt][3] = -1e30f;
            mt0 = fmaxf(mt0, fmaxf(sc[nt][0], sc[nt][1]));
            mt1 = fmaxf(mt1, fmaxf(sc[nt][2], sc[nt][3]));
        }
        mt0 = fmaxf(mt0, __shfl_xor_sync(~0u, mt0, 1));
        mt0 = fmaxf(mt0, __shfl_xor_sync(~0u, mt0, 2));
        mt1 = fmaxf(mt1, __shfl_xor_sync(~0u, mt1, 1));
        mt1 = fmaxf(mt1, __shfl_xor_sync(~0u, mt1, 2));
        const float mn0 = fmaxf(m0, mt0), mn1 = fmaxf(m1, mt1);
        const float al0 = __expf(m0 - mn0), al1 = __expf(m1 - mn1);
        m0 = mn0; m1 = mn1;
        float rs0 = 0.f, rs1 = 0.f;
        #pragma unroll
        for (int nt = 0; nt < 8; nt++) {
            sc[nt][0] = __expf(sc[nt][0] - mn0);
            sc[nt][1] = __expf(sc[nt][1] - mn0);
            sc[nt][2] = __expf(sc[nt][2] - mn1);
            sc[nt][3] = __expf(sc[nt][3] - mn1);
            rs0 += sc[nt][0] + sc[nt][1];
            rs1 += sc[nt][2] + sc[nt][3];
        }
        rs0 += __shfl_xor_sync(~0u, rs0, 1); rs0 += __shfl_xor_sync(~0u, rs0, 2);
        rs1 += __shfl_xor_sync(~0u, rs1, 1); rs1 += __shfl_xor_sync(~0u, rs1, 2);
        l0 = l0 * al0 + rs0;
        l1 = l1 * al1 + rs1;
        #pragma unroll
        for (int nt2 = 0; nt2 < 8; nt2++) {
            oacc[nt2][0] *= al0; oacc[nt2][1] *= al0;
            oacc[nt2][2] *= al1; oacc[nt2][3] *= al1;
        }

        // --- P fragments (hi/lo): C-tiles -> A-frag layout ---
        uint32_t ph[4][4], pl[4][4];
        #pragma unroll
        for (int ks2 = 0; ks2 < 4; ks2++) {
            ph[ks2][0] = pack_hi(sc[2*ks2][0],   sc[2*ks2][1]);
            pl[ks2][0] = pack_lo(sc[2*ks2][0],   sc[2*ks2][1]);
            ph[ks2][1] = pack_hi(sc[2*ks2][2],   sc[2*ks2][3]);
            pl[ks2][1] = pack_lo(sc[2*ks2][2],   sc[2*ks2][3]);
            ph[ks2][2] = pack_hi(sc[2*ks2+1][0], sc[2*ks2+1][1]);
            pl[ks2][2] = pack_lo(sc[2*ks2+1][0], sc[2*ks2+1][1]);
            ph[ks2][3] = pack_hi(sc[2*ks2+1][2], sc[2*ks2+1][3]);
            pl[ks2][3] = pack_lo(sc[2*ks2+1][2], sc[2*ks2+1][3]);
        }

        // --- O += P V ---
        #pragma unroll
        for (int ks2 = 0; ks2 < 4; ks2++) {
            const int bcol = ks2*16 + (((lane >> 3) & 1) << 3);
            #pragma unroll
            for (int nt2 = 0; nt2 < 8; nt2++) {
                uint32_t vfh[2], vfl[2];
                uint32_t off = ((nt2*8 + (lane & 7)) * FLS_ + bcol) * 2;
                LDM2(vfh, vh_b + off);
                LDM2(vfl, vl_b + off);
                MMA_BF16(oacc[nt2], ph[ks2], vfh);
                MMA_BF16(oacc[nt2], ph[ks2], vfl);
                MMA_BF16(oacc[nt2], pl[ks2], vfh);
            }
        }
    }

    // --- epilogue: normalize and store ---
    const float inv0 = 1.f / l0, inv1 = 1.f / l1;
    const int r0 = i0 + w*16 + (lane >> 2);
    float* o0 = O + ((long long)b * L_ + r0) * D_ + hoff + (lane & 3) * 2;
    float* o1 = o0 + 8LL * D_;
    #pragma unroll
    for (int nt2 = 0; nt2 < 8; nt2++) {
        float2 v0 = {oacc[nt2][0] * inv0, oacc[nt2][1] * inv0};
        float2 v1 = {oacc[nt2][2] * inv1, oacc[nt2][3] * inv1};
        *(float2*)(o0 + nt2*8) = v0;
        *(float2*)(o1 + nt2*8) = v1;
    }
}

// ---------------- RMSNorm over last dim D_ ----------------
__global__ void rmsnorm_k(const float* __restrict__ X, const float* __restrict__ W,
                          float* __restrict__ Y)
{
    const long long row = blockIdx.x;
    const float* x = X + row * D_;
    float* y = Y + row * D_;
    float ss = 0.f;
    for (int i = threadIdx.x; i < D_; i += 256) { float v = x[i]; ss += v * v; }
    __shared__ float red[8];
    for (int o = 16; o; o >>= 1) ss += __shfl_xor_sync(~0u, ss, o);
    if ((threadIdx.x & 31) == 0) red[threadIdx.x >> 5] = ss;
    __syncthreads();
    float tot = 0.f;
    #pragma unroll
    for (int i = 0; i < 8; i++) tot += red[i];
    const float inv = rsqrtf(tot * (1.f / D_) + EPS_);
    for (int i = threadIdx.x; i < D_; i += 256) y[i] = x[i] * inv * W[i];
}

// ---------------- elementwise ----------------
__global__ void init_om_k(float* __restrict__ om, const float* __restrict__ om0)
{
    int i = blockIdx.x * 256 + threadIdx.x;
    if (i < B_*M_*D_) om[i] = om0[i % (M_*D_)];
}

__global__ void silu_mul_k(float* __restrict__ a, const float* __restrict__ b)
{
    int i = blockIdx.x * 256 + threadIdx.x;
    if (i < B_*M_*HID_) {
        float v = a[i];
        a[i] = (v / (1.f + expf(-v))) * b[i];
    }
}

// rope for mem part: rows B*M (batch stride L*D), position = row index (0..M)
__global__ void rope_mem_k(float* __restrict__ t, const float* __restrict__ cf,
                           const float* __restrict__ sf)
{
    int i = blockIdx.x * 256 + threadIdx.x;
    if (i >= B_*M_*H_*HD2_) return;
    int d2 = i & 31;
    int h  = (i >> 5) & 15;
    int r  = (i >> 9) & (M_ - 1);
    int b  = i >> 18;
    long long base = ((long long)b * L_ + r) * D_ + h * HD_ + 2 * d2;
    float c = cf[r * HD2_ + d2], s = sf[r * HD2_ + d2];
    float tr = t[base], ti = t[base + 1];
    t[base]     = tr * c - ti * s;
    t[base + 1] = tr * s + ti * c;
}

// rope for x part: rows B*S (batch stride S*D), position = M + (row mod M)
__global__ void rope_x_k(float* __restrict__ t, const float* __restrict__ cf,
                         const float* __restrict__ sf)
{
    int i = blockIdx.x * 256 + threadIdx.x;
    if (i >= B_*S_*H_*HD2_) return;
    int d2 = i & 31;
    int h  = (i >> 5) & 15;
    int r  = (i >> 9) & (S_ - 1);
    int b  = i >> 21;
    long long base = ((long long)b * S_ + r) * D_ + h * HD_ + 2 * d2;
    int pos = M_ + (r & (M_ - 1));
    float c = cf[pos * HD2_ + d2], s = sf[pos * HD2_ + d2];
    float tr = t[base], ti = t[base + 1];
    t[base]     = tr * c - ti * s;
    t[base + 1] = tr * s + ti * c;
}

__global__ void extract_k(const float* __restrict__ att, float* __restrict__ om,
                          float* __restrict__ xo, int c)
{
    int i = blockIdx.x * 256 + threadIdx.x;
    if (i < B_*M_*D_) {
        int b = i / (M_*D_), r = i % (M_*D_);
        float v = att[(long long)b * L_ * D_ + (long long)M_ * D_ + r];
        om[i] = v;
        xo[(long long)b * S_ * D_ + (long long)c * M_ * D_ + r] = v;
    }
}

// ---------------- host orchestration ----------------
extern "C" void kernel_launch(void* const* d_in, const int* in_sizes, int n_in,
                              void* d_out, int out_size)
{
    const float* x     = (const float*)d_in[0];
    const float* fcos  = (const float*)d_in[1];
    const float* fsin  = (const float*)d_in[2];
    const float* wq    = (const float*)d_in[3];
    const float* wk    = (const float*)d_in[4];
    const float* wv    = (const float*)d_in[5];
    const float* wo    = (const float*)d_in[6];
    const float* wm    = (const float*)d_in[7];
    const float* wkm   = (const float*)d_in[8];
    const float* wvm   = (const float*)d_in[9];
    const float* w1    = (const float*)d_in[10];
    const float* w3    = (const float*)d_in[11];
    const float* w2    = (const float*)d_in[12];
    const float* ffn_w = (const float*)d_in[13];
    const float* mem_w = (const float*)d_in[14];
    const float* om0   = (const float*)d_in[15];
    float* out = (float*)d_out;

    float *p_om, *p_om2, *p_tmp, *p_h1, *p_h3, *p_k, *p_v, *p_att, *p_xo, *p_xq, *p_xk, *p_xv;
    cudaGetSymbolAddress((void**)&p_om,  g_om);
    cudaGetSymbolAddress((void**)&p_om2, g_om2);
    cudaGetSymbolAddress((void**)&p_tmp, g_tmp);
    cudaGetSymbolAddress((void**)&p_h1,  g_h1);
    cudaGetSymbolAddress((void**)&p_h3,  g_h3);
    cudaGetSymbolAddress((void**)&p_k,   g_k);
    cudaGetSymbolAddress((void**)&p_v,   g_v);
    cudaGetSymbolAddress((void**)&p_att, g_att);
    cudaGetSymbolAddress((void**)&p_xo,  g_xo);
    cudaGetSymbolAddress((void**)&p_xq,  g_xq);
    cudaGetSymbolAddress((void**)&p_xk,  g_xk);
    cudaGetSymbolAddress((void**)&p_xv,  g_xv);

    __nv_bfloat16 *wqh,*wql,*wkh,*wkl,*wvh,*wvl,*woh,*wol,*wmh,*wml,*wkmh,*wkml,*wvmh,*wvml;
    __nv_bfloat16 *w1h,*w1l,*w3h,*w3l,*w2h,*w2l;
    cudaGetSymbolAddress((void**)&wqh,  g_wq_h);  cudaGetSymbolAddress((void**)&wql,  g_wq_l);
    cudaGetSymbolAddress((void**)&wkh,  g_wk_h);  cudaGetSymbolAddress((void**)&wkl,  g_wk_l);
    cudaGetSymbolAddress((void**)&wvh,  g_wv_h);  cudaGetSymbolAddress((void**)&wvl,  g_wv_l);
    cudaGetSymbolAddress((void**)&woh,  g_wo_h);  cudaGetSymbolAddress((void**)&wol,  g_wo_l);
    cudaGetSymbolAddress((void**)&wmh,  g_wm_h);  cudaGetSymbolAddress((void**)&wml,  g_wm_l);
    cudaGetSymbolAddress((void**)&wkmh, g_wkm_h); cudaGetSymbolAddress((void**)&wkml, g_wkm_l);
    cudaGetSymbolAddress((void**)&wvmh, g_wvm_h); cudaGetSymbolAddress((void**)&wvml, g_wvm_l);
    cudaGetSymbolAddress((void**)&w1h,  g_w1_h);  cudaGetSymbolAddress((void**)&w1l,  g_w1_l);
    cudaGetSymbolAddress((void**)&w3h,  g_w3_h);  cudaGetSymbolAddress((void**)&w3l,  g_w3_l);
    cudaGetSymbolAddress((void**)&w2h,  g_w2_h);  cudaGetSymbolAddress((void**)&w2l,  g_w2_l);

    const int GSM128 = 2 * (20480 + 2 * 128 * 80);   // 81920
    const int GSM64  = 2 * (20480 + 2 * 64 * 80);    // 61440
    cudaFuncSetAttribute(gemm_mma<128>, cudaFuncAttributeMaxDynamicSharedMemorySize, GSM128);
    cudaFuncSetAttribute(gemm_mma<64>,  cudaFuncAttributeMaxDynamicSharedMemorySize, GSM64);

    const long long MD = (long long)M_ * D_;
    const long long LD = (long long)L_ * D_;

    // weight prep (transpose + bf16 hi/lo split)
    wprep_k<<<dim3(D_/32,   D_/32),   256>>>(wq,  wqh,  wql,  D_,   D_);
    wprep_k<<<dim3(D_/32,   D_/32),   256>>>(wk,  wkh,  wkl,  D_,   D_);
    wprep_k<<<dim3(D_/32,   D_/32),   256>>>(wv,  wvh,  wvl,  D_,   D_);
    wprep_k<<<dim3(D_/32,   D_/32),   256>>>(wo,  woh,  wol,  D_,   D_);
    wprep_k<<<dim3(D_/32,   D_/32),   256>>>(wm,  wmh,  wml,  D_,   D_);
    wprep_k<<<dim3(D_/32,   D_/32),   256>>>(wkm, wkmh, wkml, D_,   D_);
    wprep_k<<<dim3(D_/32,   D_/32),   256>>>(wvm, wvmh, wvml, D_,   D_);
    wprep_k<<<dim3(HID_/32, D_/32),   256>>>(w1,  w1h,  w1l,  D_,   HID_);
    wprep_k<<<dim3(HID_/32, D_/32),   256>>>(w3,  w3h,  w3l,  D_,   HID_);
    wprep_k<<<dim3(D_/32,   HID_/32), 256>>>(w2,  w2h,  w2l,  HID_, D_);

    init_om_k<<<(B_*M_*D_ + 255) / 256, 256>>>(p_om, om0);

    // hoisted x projections: big full-chip GEMMs over all B*S rows, then rope once
    gemm_mma<128><<<dim3(D_/128, (B_*S_)/128, 1), 256, GSM128>>>(x, wqh, wql, p_xq, D_, D_, D_, 0, 0, 0);
    gemm_mma<128><<<dim3(D_/128, (B_*S_)/128, 1), 256, GSM128>>>(x, wkh, wkl, p_xk, D_, D_, D_, 0, 0, 0);
    gemm_mma<128><<<dim3(D_/128, (B_*S_)/128, 1), 256, GSM128>>>(x, wvh, wvl, p_xv, D_, D_, D_, 0, 0, 0);
    rope_x_k<<<(B_*S_*H_*HD2_ + 255) / 256, 256>>>(p_xq, fcos, fsin);
    rope_x_k<<<(B_*S_*H_*HD2_ + 255) / 256, 256>>>(p_xk, fcos, fsin);

    for (int c = 0; c < NC_; c++) {
        // om2 = om @ wm
        gemm_mma<64><<<dim3(D_/64, 8, 1), 256, GSM64>>>(p_om, wmh, wml, p_om2, D_, D_, D_, 0, 0, 0);
        rmsnorm_k<<<B_*M_, 256>>>(p_om2, ffn_w, p_tmp);
        // h1 = tmp@w1, h3 = tmp@w3
        gemm_mma<64><<<dim3(HID_/64, 8, 1), 256, GSM64>>>(p_tmp, w1h, w1l, p_h1, D_, D_, HID_, 0, 0, 0);
        gemm_mma<64><<<dim3(HID_/64, 8, 1), 256, GSM64>>>(p_tmp, w3h, w3l, p_h3, D_, D_, HID_, 0, 0, 0);
        silu_mul_k<<<(B_*M_*HID_ + 255) / 256, 256>>>(p_h1, p_h3);
        // om2 += h1 @ w2
        gemm_mma<64><<<dim3(D_/64, 8, 1), 256, GSM64>>>(p_h1, w2h, w2l, p_om2, HID_, HID_, D_, 0, 0, 1);
        rmsnorm_k<<<B_*M_, 256>>>(p_om2, mem_w, p_tmp);
        // mk -> g_k[:, :M], mv -> g_v[:, :M]  (batched: A stride MD, C stride LD)
        gemm_mma<64><<<dim3(D_/64, 4, B_), 256, GSM64>>>(p_tmp, wkmh, wkml, p_k, D_, D_, D_, MD, LD, 0);
        gemm_mma<64><<<dim3(D_/64, 4, B_), 256, GSM64>>>(p_tmp, wvmh, wvml, p_v, D_, D_, D_, MD, LD, 0);
        // rope mem K (positions 0..M-1); mem Q = mem K (same buffer)
        rope_mem_k<<<(B_*M_*H_*HD2_ + 255) / 256, 256>>>(p_k, fcos, fsin);
        // fused flash attention
        const long long co = (long long)c * M_ * D_;
        flash_k<<<dim3(L_/128, B_*H_), 256>>>(p_k, p_v, p_xq + co, p_xk + co, p_xv + co, p_att);
        extract_k<<<(B_*M_*D_ + 255) / 256, 256>>>(p_att, p_om, p_xo, c);
    }
    // final: out = xo @ wo
    gemm_mma<128><<<dim3(D_/128, (B_*S_)/128, 1), 256, GSM128>>>(p_xo, woh, wol, out, D_, D_, D_, 0, 0, 0);
}

// round 8
// speedup vs baseline: 5.3167x; 1.0505x over previous
#include <cuda_runtime.h>
#include <cuda_bf16.h>
#include <math.h>
#include <stdint.h>

#define B_   2
#define S_   4096
#define D_   1024
#define H_   16
#define HD_  64
#define HD2_ 32
#define M_   512
#define L_   1024
#define HID_ 2816
#define NC_  8
#define EPS_ 1e-5f

// ---------------- scratch (no cudaMalloc allowed) ----------------
static __device__ float g_om2 [B_*M_*D_];
static __device__ float g_h1  [B_*M_*HID_];
static __device__ float g_h3  [B_*M_*HID_];
static __device__ float g_k   [B_*L_*D_];   // mem-K (= mem-Q), first M rows per batch
static __device__ float g_v   [B_*L_*D_];   // mem-V
static __device__ float g_att [B_*L_*D_];
static __device__ float g_xq  [B_*S_*D_];   // rope'd x-part Q/K + V (fp32, flash inputs)
static __device__ float g_xk  [B_*S_*D_];
static __device__ float g_xv  [B_*S_*D_];

// bf16 hi/lo activations (GEMM A-operands)
static __device__ __nv_bfloat16 g_x_h [B_*S_*D_],  g_x_l [B_*S_*D_];
static __device__ __nv_bfloat16 g_xo_h[B_*S_*D_],  g_xo_l[B_*S_*D_];
static __device__ __nv_bfloat16 g_om_h[B_*M_*D_],  g_om_l[B_*M_*D_];
static __device__ __nv_bfloat16 g_t_h [B_*M_*D_],  g_t_l [B_*M_*D_];
static __device__ __nv_bfloat16 g_h1_h[B_*M_*HID_], g_h1_l[B_*M_*HID_];

// bf16 hi/lo transposed weights [N, K]
static __device__ __nv_bfloat16 g_wq_h[D_*D_],  g_wq_l[D_*D_];
static __device__ __nv_bfloat16 g_wk_h[D_*D_],  g_wk_l[D_*D_];
static __device__ __nv_bfloat16 g_wv_h[D_*D_],  g_wv_l[D_*D_];
static __device__ __nv_bfloat16 g_wo_h[D_*D_],  g_wo_l[D_*D_];
static __device__ __nv_bfloat16 g_wm_h[D_*D_],  g_wm_l[D_*D_];
static __device__ __nv_bfloat16 g_wkm_h[D_*D_], g_wkm_l[D_*D_];
static __device__ __nv_bfloat16 g_wvm_h[D_*D_], g_wvm_l[D_*D_];
static __device__ __nv_bfloat16 g_w1_h[HID_*D_], g_w1_l[HID_*D_];
static __device__ __nv_bfloat16 g_w3_h[HID_*D_], g_w3_l[HID_*D_];
static __device__ __nv_bfloat16 g_w2_h[D_*HID_], g_w2_l[D_*HID_];

// ---------------- PTX helpers (baseline PTX only: works on plain sm_103) ----------------
__device__ __forceinline__ uint32_t smem_u32(const void* p){
    uint32_t a;
    asm("{ .reg .u64 t; cvta.to.shared.u64 t, %1; cvt.u32.u64 %0, t; }":"=r"(a):"l"(p));
    return a;
}

#define LDM4(r, addr) \
    asm volatile("ldmatrix.sync.aligned.m8n8.x4.shared.b16 {%0,%1,%2,%3}, [%4];" \
        : "=r"((r)[0]), "=r"((r)[1]), "=r"((r)[2]), "=r"((r)[3]) : "r"(addr))

#define LDM2(r, addr) \
    asm volatile("ldmatrix.sync.aligned.m8n8.x2.shared.b16 {%0,%1}, [%2];" \
        : "=r"((r)[0]), "=r"((r)[1]) : "r"(addr))

#define MMA_BF16(c, a, b) \
    asm volatile("mma.sync.aligned.m16n8k16.row.col.f32.bf16.bf16.f32 " \
        "{%0,%1,%2,%3}, {%4,%5,%6,%7}, {%8,%9}, {%0,%1,%2,%3};" \
        : "+f"((c)[0]), "+f"((c)[1]), "+f"((c)[2]), "+f"((c)[3]) \
        : "r"((a)[0]), "r"((a)[1]), "r"((a)[2]), "r"((a)[3]), \
          "r"((b)[0]), "r"((b)[1]))

#define CPA16(saddr, gptr) \
    asm volatile("cp.async.ca.shared.global [%0], [%1], 16;" \
        :: "r"(saddr), "l"(gptr))
#define CPCOMMIT() asm volatile("cp.async.commit_group;" ::: "memory")
#define CPWAIT(n)  asm volatile("cp.async.wait_group %0;" :: "n"(n) : "memory")

__device__ __forceinline__ uint32_t pack_hi(float a, float b){
    return (uint32_t)__bfloat16_as_ushort(__float2bfloat16(a))
         | ((uint32_t)__bfloat16_as_ushort(__float2bfloat16(b)) << 16);
}
__device__ __forceinline__ uint32_t pack_lo(float a, float b){
    float ah = __bfloat162float(__float2bfloat16(a));
    float bh = __bfloat162float(__float2bfloat16(b));
    return (uint32_t)__bfloat16_as_ushort(__float2bfloat16(a - ah))
         | ((uint32_t)__bfloat16_as_ushort(__float2bfloat16(b - bh)) << 16);
}
__device__ __forceinline__ void split1(float v, __nv_bfloat16* H, __nv_bfloat16* Lo){
    __nv_bfloat16 h = __float2bfloat16(v);
    *H  = h;
    *Lo = __float2bfloat16(v - __bfloat162float(h));
}

// ---------------- weight prep: W[K,N] -> Thi/Tlo[N,K] bf16 ----------------
__global__ void wprep_k(const float* __restrict__ W,
                        __nv_bfloat16* __restrict__ Thi, __nv_bfloat16* __restrict__ Tlo,
                        int K, int N)
{
    __shared__ float s[32][33];
    const int n0 = blockIdx.x * 32, k0 = blockIdx.y * 32;
    const int tx = threadIdx.x & 31, ty = threadIdx.x >> 5;
    #pragma unroll
    for (int i = 0; i < 4; i++)
        s[ty + 8*i][tx] = W[(long long)(k0 + ty + 8*i) * N + n0 + tx];
    __syncthreads();
    #pragma unroll
    for (int i = 0; i < 4; i++) {
        float x = s[tx][ty + 8*i];
        long long o = (long long)(n0 + ty + 8*i) * K + k0 + tx;
        split1(x, Thi + o, Tlo + o);
    }
}

// ---------------- async HMMA GEMM: C[M,N] (+)= A[M,K] @ Bt[N,K]^T ----------------
// A and B both pre-split bf16 hi/lo in gmem (k-contiguous rows).
// CTA 128 x BN, 8 warps (2 x 4), K-slab 32, 3-stage cp.async pipeline.
template<int BN>
__global__ void __launch_bounds__(256, 1) gemm_a16(
    const __nv_bfloat16* __restrict__ Ahi, const __nv_bfloat16* __restrict__ Alo,
    const __nv_bfloat16* __restrict__ Bhi, const __nv_bfloat16* __restrict__ Blo,
    float* __restrict__ C, int K, int lda, int ldc,
    long long sA, long long sC, int acc)
{
    constexpr int NI    = BN / 32;
    constexpr int ALOFF = 10240;
    constexpr int BHOFF = 20480;
    constexpr int BLOFF = 20480 + BN * 80;
    constexpr int STG   = 20480 + 2 * BN * 80;

    extern __shared__ char sm[];
    const uint32_t sb = smem_u32(sm);
    const int t = threadIdx.x, lane = t & 31, wid = t >> 5;
    const int wm = (wid >> 2) * 64, wn = (wid & 3) * (BN / 4);

    Ahi += (long long)blockIdx.z * sA;
    Alo += (long long)blockIdx.z * sA;
    C   += (long long)blockIdx.z * sC;
    const int m0 = blockIdx.y * 128, n0 = blockIdx.x * BN;

    const int nk = K >> 5;

    // per-thread copy coords: g in [0,512) covers 128 rows x 4 16B-chunks
    const int car = t >> 1;   // unused placeholder to keep regs simple

    // ---- async slab issue ----
    auto issue = [&](int s, int st){
        const uint32_t stg = sb + st * STG;
        const long long ko = (long long)s * 32;
        #pragma unroll
        for (int i = 0; i < 2; i++) {
            int g = i * 256 + t, row = g >> 2, c = g & 3;
            uint32_t sa = stg + row * 80 + c * 16;
            CPA16(sa,         Ahi + (long long)(m0 + row) * lda + ko + c * 8);
            CPA16(sa + ALOFF, Alo + (long long)(m0 + row) * lda + ko + c * 8);
        }
        #pragma unroll
        for (int i = 0; i < BN/64; i++) {
            int g = i * 256 + t, row = g >> 2, c = g & 3;
            uint32_t sa = stg + BHOFF + row * 80 + c * 16;
            CPA16(sa,                   Bhi + (long long)(n0 + row) * K + ko + c * 8);
            CPA16(sa + (BLOFF - BHOFF), Blo + (long long)(n0 + row) * K + ko + c * 8);
        }
        CPCOMMIT();
    };

    float accr[4][NI][4];
    #pragma unroll
    for (int i = 0; i < 4; i++)
        #pragma unroll
        for (int j = 0; j < NI; j++)
            #pragma unroll
            for (int r = 0; r < 4; r++) accr[i][j][r] = 0.f;

    issue(0, 0);
    issue(1, 1);

    for (int kb = 0; kb < nk; kb++) {
        if (kb + 1 < nk) { CPWAIT(1); } else { CPWAIT(0); }
        __syncthreads();
        if (kb + 2 < nk) issue(kb + 2, (kb + 2) % 3);

        const uint32_t stg = sb + (kb % 3) * STG;
        #pragma unroll
        for (int ks = 0; ks < 2; ks++) {
            const int k0 = ks * 16;
            uint32_t ah[4][4], al[4][4];
            const int arw = lane & 15, acl = k0 + ((lane >> 4) << 3);
            #pragma unroll
            for (int mi = 0; mi < 4; mi++) {
                uint32_t ad = stg + ((wm + mi*16 + arw) * 40 + acl) * 2;
                LDM4(ah[mi], ad);
                LDM4(al[mi], ad + ALOFF);
            }
            const int brw = lane & 7, bcl = k0 + (((lane >> 3) & 1) << 3);
            #pragma unroll
            for (int ni = 0; ni < NI; ni++) {
                uint32_t bfh[2], bfl[2];
                uint32_t bd = stg + BHOFF + ((wn + ni*8 + brw) * 40 + bcl) * 2;
                LDM2(bfh, bd);
                LDM2(bfl, bd + (BLOFF - BHOFF));
                #pragma unroll
                for (int mi = 0; mi < 4; mi++) {
                    MMA_BF16(accr[mi][ni], ah[mi], bfh);
                    MMA_BF16(accr[mi][ni], ah[mi], bfl);
                    MMA_BF16(accr[mi][ni], al[mi], bfh);
                }
            }
        }
    }

    // epilogue
    #pragma unroll
    for (int mi = 0; mi < 4; mi++) {
        #pragma unroll
        for (int ni = 0; ni < NI; ni++) {
            long long r0 = m0 + wm + mi*16 + (lane >> 2);
            int cc = n0 + wn + ni*8 + (lane & 3) * 2;
            float* cp0 = C + r0 * ldc + cc;
            float* cp1 = cp0 + 8LL * ldc;
            if (acc) {
                float2 o0 = *(float2*)cp0, o1 = *(float2*)cp1;
                o0.x += accr[mi][ni][0]; o0.y += accr[mi][ni][1];
                o1.x += accr[mi][ni][2]; o1.y += accr[mi][ni][3];
                *(float2*)cp0 = o0; *(float2*)cp1 = o1;
            } else {
                float2 o0 = {accr[mi][ni][0], accr[mi][ni][1]};
                float2 o1 = {accr[mi][ni][2], accr[mi][ni][3]};
                *(float2*)cp0 = o0; *(float2*)cp1 = o1;
            }
        }
    }
}

// ---------------- flash attention (unchanged from R7) ----------------
#define FLS_ 72
__global__ void __launch_bounds__(256) flash_k(
    const float* __restrict__ Kmem, const float* __restrict__ Vmem,
    const float* __restrict__ Qx, const float* __restrict__ Kx,
    const float* __restrict__ Vx, float* __restrict__ O)
{
    __shared__ __nv_bfloat16 sKh[64*FLS_], sKl[64*FLS_], sVh[64*FLS_], sVl[64*FLS_];
    const int t = threadIdx.x, lane = t & 31, w = t >> 5;
    const int bh = blockIdx.y, b = bh >> 4, h = bh & 15;
    const int i0 = blockIdx.x * 128;
    const long long SD = (long long)S_ * D_;
    const long long LDmem = (long long)L_ * D_;
    const int hoff = h * HD_;

    const uint32_t kh_b = smem_u32(sKh), kl_b = smem_u32(sKl);
    const uint32_t vh_b = smem_u32(sVh), vl_b = smem_u32(sVl);

    uint32_t qh[4][4], ql[4][4];
    {
        const int r0 = i0 + w*16 + (lane >> 2);
        const float* q0 = (r0 < M_) ? (Kmem + b*LDmem + (long long)r0*D_ + hoff)
                                    : (Qx + b*SD + (long long)(r0 - M_)*D_ + hoff);
        const float* q1 = ((r0+8) < M_) ? (Kmem + b*LDmem + (long long)(r0+8)*D_ + hoff)
                                        : (Qx + b*SD + (long long)(r0+8 - M_)*D_ + hoff);
        const int c0 = (lane & 3) * 2;
        #pragma unroll
        for (int ks = 0; ks < 4; ks++) {
            float2 v0 = *(const float2*)(q0 + ks*16 + c0);
            float2 v1 = *(const float2*)(q1 + ks*16 + c0);
            float2 v2 = *(const float2*)(q0 + ks*16 + c0 + 8);
            float2 v3 = *(const float2*)(q1 + ks*16 + c0 + 8);
            v0.x *= 0.125f; v0.y *= 0.125f; v1.x *= 0.125f; v1.y *= 0.125f;
            v2.x *= 0.125f; v2.y *= 0.125f; v3.x *= 0.125f; v3.y *= 0.125f;
            qh[ks][0] = pack_hi(v0.x, v0.y); ql[ks][0] = pack_lo(v0.x, v0.y);
            qh[ks][1] = pack_hi(v1.x, v1.y); ql[ks][1] = pack_lo(v1.x, v1.y);
            qh[ks][2] = pack_hi(v2.x, v2.y); ql[ks][2] = pack_lo(v2.x, v2.y);
            qh[ks][3] = pack_hi(v3.x, v3.y); ql[ks][3] = pack_lo(v3.x, v3.y);
        }
    }

    float oacc[8][4];
    #pragma unroll
    for (int i = 0; i < 8; i++)
        #pragma unroll
        for (int r = 0; r < 4; r++) oacc[i][r] = 0.f;
    float m0 = -1e30f, m1 = -1e30f, l0 = 0.f, l1 = 0.f;

    const int jmax = (i0 >> 6) + 2;
    for (int jt = 0; jt < jmax; jt++) {
        const int j0 = jt * 64;
        if (jt) __syncthreads();
        #pragma unroll
        for (int i = 0; i < 4; i++) {
            int g = i * 256 + t, row = g >> 4, cq = (g & 15) * 4;
            int kr = j0 + row;
            const float* kp = (kr < M_) ? (Kmem + b*LDmem + (long long)kr*D_ + hoff)
                                        : (Kx + b*SD + (long long)(kr - M_)*D_ + hoff);
            float4 kv = *(const float4*)(kp + cq);
            uint2 hw, lw;
            hw.x = pack_hi(kv.x, kv.y); hw.y = pack_hi(kv.z, kv.w);
            lw.x = pack_lo(kv.x, kv.y); lw.y = pack_lo(kv.z, kv.w);
            int eo = (row * FLS_ + cq) * 2;
            *(uint2*)((char*)sKh + eo) = hw;
            *(uint2*)((char*)sKl + eo) = lw;
            const float* vp = (kr < M_) ? (Vmem + b*LDmem + (long long)kr*D_ + hoff)
                                        : (Vx + b*SD + (long long)(kr - M_)*D_ + hoff);
            float4 vv = *(const float4*)(vp + cq);
            float vsv[4] = {vv.x, vv.y, vv.z, vv.w};
            #pragma unroll
            for (int j = 0; j < 4; j++) {
                __nv_bfloat16 hb = __float2bfloat16(vsv[j]);
                __nv_bfloat16 lb = __float2bfloat16(vsv[j] - __bfloat162float(hb));
                sVh[(cq + j) * FLS_ + row] = hb;
                sVl[(cq + j) * FLS_ + row] = lb;
            }
        }
        __syncthreads();

        if (j0 > i0 + w*16 + 15) continue;

        float sc[8][4];
        #pragma unroll
        for (int i = 0; i < 8; i++)
            #pragma unroll
            for (int r = 0; r < 4; r++) sc[i][r] = 0.f;
        #pragma unroll
        for (int ks = 0; ks < 4; ks++) {
            const int bcol = ks*16 + (((lane >> 3) & 1) << 3);
            #pragma unroll
            for (int nt = 0; nt < 8; nt++) {
                uint32_t bfh[2], bfl[2];
                uint32_t off = ((nt*8 + (lane & 7)) * FLS_ + bcol) * 2;
                LDM2(bfh, kh_b + off);
                LDM2(bfl, kl_b + off);
                MMA_BF16(sc[nt], qh[ks], bfh);
                MMA_BF16(sc[nt], qh[ks], bfl);
                MMA_BF16(sc[nt], ql[ks], bfh);
            }
        }

        const int r0 = i0 + w*16 + (lane >> 2);
        float mt0 = -1e30f, mt1 = -1e30f;
        #pragma unroll
        for (int nt = 0; nt < 8; nt++) {
            int cb = j0 + nt*8 + (lane & 3) * 2;
            if (cb     > r0)     sc[nt][0] = -1e30f;
            if (cb + 1 > r0)     sc[nt][1] = -1e30f;
            if (cb     > r0 + 8) sc[nt][2] = -1e30f;
            if (cb + 1 > r0 + 8) sc[nt][3] = -1e30f;
            mt0 = fmaxf(mt0, fmaxf(sc[nt][0], sc[nt][1]));
            mt1 = fmaxf(mt1, fmaxf(sc[nt][2], sc[nt][3]));
        }
        mt0 = fmaxf(mt0, __shfl_xor_sync(~0u, mt0, 1));
        mt0 = fmaxf(mt0, __shfl_xor_sync(~0u, mt0, 2));
        mt1 = fmaxf(mt1, __shfl_xor_sync(~0u, mt1, 1));
        mt1 = fmaxf(mt1, __shfl_xor_sync(~0u, mt1, 2));
        const float mn0 = fmaxf(m0, mt0), mn1 = fmaxf(m1, mt1);
        const float al0 = __expf(m0 - mn0), al1 = __expf(m1 - mn1);
        m0 = mn0; m1 = mn1;
        float rs0 = 0.f, rs1 = 0.f;
        #pragma unroll
        for (int nt = 0; nt < 8; nt++) {
            sc[nt][0] = __expf(sc[nt][0] - mn0);
            sc[nt][1] = __expf(sc[nt][1] - mn0);
            sc[nt][2] = __expf(sc[nt][2] - mn1);
            sc[nt][3] = __expf(sc[nt][3] - mn1);
            rs0 += sc[nt][0] + sc[nt][1];
            rs1 += sc[nt][2] + sc[nt][3];
        }
        rs0 += __shfl_xor_sync(~0u, rs0, 1); rs0 += __shfl_xor_sync(~0u, rs0, 2);
        rs1 += __shfl_xor_sync(~0u, rs1, 1); rs1 += __shfl_xor_sync(~0u, rs1, 2);
        l0 = l0 * al0 + rs0;
        l1 = l1 * al1 + rs1;
        #pragma unroll
        for (int nt2 = 0; nt2 < 8; nt2++) {
            oacc[nt2][0] *= al0; oacc[nt2][1] *= al0;
            oacc[nt2][2] *= al1; oacc[nt2][3] *= al1;
        }

        uint32_t ph[4][4], pl[4][4];
        #pragma unroll
        for (int ks2 = 0; ks2 < 4; ks2++) {
            ph[ks2][0] = pack_hi(sc[2*ks2][0],   sc[2*ks2][1]);
            pl[ks2][0] = pack_lo(sc[2*ks2][0],   sc[2*ks2][1]);
            ph[ks2][1] = pack_hi(sc[2*ks2][2],   sc[2*ks2][3]);
            pl[ks2][1] = pack_lo(sc[2*ks2][2],   sc[2*ks2][3]);
            ph[ks2][2] = pack_hi(sc[2*ks2+1][0], sc[2*ks2+1][1]);
            pl[ks2][2] = pack_lo(sc[2*ks2+1][0], sc[2*ks2+1][1]);
            ph[ks2][3] = pack_hi(sc[2*ks2+1][2], sc[2*ks2+1][3]);
            pl[ks2][3] = pack_lo(sc[2*ks2+1][2], sc[2*ks2+1][3]);
        }

        #pragma unroll
        for (int ks2 = 0; ks2 < 4; ks2++) {
            const int bcol = ks2*16 + (((lane >> 3) & 1) << 3);
            #pragma unroll
            for (int nt2 = 0; nt2 < 8; nt2++) {
                uint32_t vfh[2], vfl[2];
                uint32_t off = ((nt2*8 + (lane & 7)) * FLS_ + bcol) * 2;
                LDM2(vfh, vh_b + off);
                LDM2(vfl, vl_b + off);
                MMA_BF16(oacc[nt2], ph[ks2], vfh);
                MMA_BF16(oacc[nt2], ph[ks2], vfl);
                MMA_BF16(oacc[nt2], pl[ks2], vfh);
            }
        }
    }

    const float inv0 = 1.f / l0, inv1 = 1.f / l1;
    const int r0 = i0 + w*16 + (lane >> 2);
    float* o0 = O + ((long long)b * L_ + r0) * D_ + hoff + (lane & 3) * 2;
    float* o1 = o0 + 8LL * D_;
    #pragma unroll
    for (int nt2 = 0; nt2 < 8; nt2++) {
        float2 v0 = {oacc[nt2][0] * inv0, oacc[nt2][1] * inv0};
        float2 v1 = {oacc[nt2][2] * inv1, oacc[nt2][3] * inv1};
        *(float2*)(o0 + nt2*8) = v0;
        *(float2*)(o1 + nt2*8) = v1;
    }
}

// ---------------- RMSNorm -> bf16 hi/lo ----------------
__global__ void rmsnorm_k(const float* __restrict__ X, const float* __restrict__ W,
                          __nv_bfloat16* __restrict__ Yh, __nv_bfloat16* __restrict__ Yl)
{
    const long long row = blockIdx.x;
    const float* x = X + row * D_;
    float ss = 0.f;
    for (int i = threadIdx.x; i < D_; i += 256) { float v = x[i]; ss += v * v; }
    __shared__ float red[8];
    for (int o = 16; o; o >>= 1) ss += __shfl_xor_sync(~0u, ss, o);
    if ((threadIdx.x & 31) == 0) red[threadIdx.x >> 5] = ss;
    __syncthreads();
    float tot = 0.f;
    #pragma unroll
    for (int i = 0; i < 8; i++) tot += red[i];
    const float inv = rsqrtf(tot * (1.f / D_) + EPS_);
    for (int i = threadIdx.x; i < D_; i += 256)
        split1(x[i] * inv * W[i], Yh + row * D_ + i, Yl + row * D_ + i);
}

// ---------------- elementwise ----------------
__global__ void split_x_k(const float* __restrict__ X,
                          __nv_bfloat16* __restrict__ Hh, __nv_bfloat16* __restrict__ Ll,
                          long long n)
{
    long long i = ((long long)blockIdx.x * 256 + threadIdx.x) * 4;
    if (i >= n) return;
    float4 v = *(const float4*)(X + i);
    uint2 hw, lw;
    hw.x = pack_hi(v.x, v.y); hw.y = pack_hi(v.z, v.w);
    lw.x = pack_lo(v.x, v.y); lw.y = pack_lo(v.z, v.w);
    *(uint2*)(Hh + i) = hw;
    *(uint2*)(Ll + i) = lw;
}

__global__ void init_om_k(__nv_bfloat16* __restrict__ omh, __nv_bfloat16* __restrict__ oml,
                          const float* __restrict__ om0)
{
    int i = blockIdx.x * 256 + threadIdx.x;
    if (i < B_*M_*D_) split1(om0[i % (M_*D_)], omh + i, oml + i);
}

__global__ void silu_mul_k(const float* __restrict__ a, const float* __restrict__ b,
                           __nv_bfloat16* __restrict__ Hh, __nv_bfloat16* __restrict__ Ll)
{
    int i = blockIdx.x * 256 + threadIdx.x;
    if (i < B_*M_*HID_) {
        float v = a[i];
        split1((v / (1.f + expf(-v))) * b[i], Hh + i, Ll + i);
    }
}

// rope for mem part: rows B*M (batch stride L*D), position = row index
__global__ void rope_mem_k(float* __restrict__ t, const float* __restrict__ cf,
                           const float* __restrict__ sf)
{
    int i = blockIdx.x * 256 + threadIdx.x;
    if (i >= B_*M_*H_*HD2_) return;
    int d2 = i & 31;
    int h  = (i >> 5) & 15;
    int r  = (i >> 9) & (M_ - 1);
    int b  = i >> 18;
    long long base = ((long long)b * L_ + r) * D_ + h * HD_ + 2 * d2;
    float c = cf[r * HD2_ + d2], s = sf[r * HD2_ + d2];
    float tr = t[base], ti = t[base + 1];
    t[base]     = tr * c - ti * s;
    t[base + 1] = tr * s + ti * c;
}

// rope for x part: rows B*S (batch stride S*D), position = M + (row mod M)
__global__ void rope_x_k(float* __restrict__ t, const float* __restrict__ cf,
                         const float* __restrict__ sf)
{
    int i = blockIdx.x * 256 + threadIdx.x;
    if (i >= B_*S_*H_*HD2_) return;
    int d2 = i & 31;
    int h  = (i >> 5) & 15;
    int r  = (i >> 9) & (S_ - 1);
    int b  = i >> 21;
    long long base = ((long long)b * S_ + r) * D_ + h * HD_ + 2 * d2;
    int pos = M_ + (r & (M_ - 1));
    float c = cf[pos * HD2_ + d2], s = sf[pos * HD2_ + d2];
    float tr = t[base], ti = t[base + 1];
    t[base]     = tr * c - ti * s;
    t[base + 1] = tr * s + ti * c;
}

__global__ void extract_k(const float* __restrict__ att,
                          __nv_bfloat16* __restrict__ omh, __nv_bfloat16* __restrict__ oml,
                          __nv_bfloat16* __restrict__ xoh, __nv_bfloat16* __restrict__ xol,
                          int c)
{
    int i = blockIdx.x * 256 + threadIdx.x;
    if (i < B_*M_*D_) {
        int b = i / (M_*D_), r = i % (M_*D_);
        float v = att[(long long)b * L_ * D_ + (long long)M_ * D_ + r];
        __nv_bfloat16 h = __float2bfloat16(v);
        __nv_bfloat16 lo = __float2bfloat16(v - __bfloat162float(h));
        omh[i] = h; oml[i] = lo;
        long long xi = (long long)b * S_ * D_ + (long long)c * M_ * D_ + r;
        xoh[xi] = h; xol[xi] = lo;
    }
}

// ---------------- host orchestration ----------------
extern "C" void kernel_launch(void* const* d_in, const int* in_sizes, int n_in,
                              void* d_out, int out_size)
{
    const float* x     = (const float*)d_in[0];
    const float* fcos  = (const float*)d_in[1];
    const float* fsin  = (const float*)d_in[2];
    const float* wq    = (const float*)d_in[3];
    const float* wk    = (const float*)d_in[4];
    const float* wv    = (const float*)d_in[5];
    const float* wo    = (const float*)d_in[6];
    const float* wm    = (const float*)d_in[7];
    const float* wkm   = (const float*)d_in[8];
    const float* wvm   = (const float*)d_in[9];
    const float* w1    = (const float*)d_in[10];
    const float* w3    = (const float*)d_in[11];
    const float* w2    = (const float*)d_in[12];
    const float* ffn_w = (const float*)d_in[13];
    const float* mem_w = (const float*)d_in[14];
    const float* om0   = (const float*)d_in[15];
    float* out = (float*)d_out;

    float *p_om2, *p_h1, *p_h3, *p_k, *p_v, *p_att, *p_xq, *p_xk, *p_xv;
    cudaGetSymbolAddress((void**)&p_om2, g_om2);
    cudaGetSymbolAddress((void**)&p_h1,  g_h1);
    cudaGetSymbolAddress((void**)&p_h3,  g_h3);
    cudaGetSymbolAddress((void**)&p_k,   g_k);
    cudaGetSymbolAddress((void**)&p_v,   g_v);
    cudaGetSymbolAddress((void**)&p_att, g_att);
    cudaGetSymbolAddress((void**)&p_xq,  g_xq);
    cudaGetSymbolAddress((void**)&p_xk,  g_xk);
    cudaGetSymbolAddress((void**)&p_xv,  g_xv);

    __nv_bfloat16 *xh,*xl,*xoh,*xol,*omh,*oml,*th,*tl,*h1h,*h1l;
    cudaGetSymbolAddress((void**)&xh,  g_x_h);  cudaGetSymbolAddress((void**)&xl,  g_x_l);
    cudaGetSymbolAddress((void**)&xoh, g_xo_h); cudaGetSymbolAddress((void**)&xol, g_xo_l);
    cudaGetSymbolAddress((void**)&omh, g_om_h); cudaGetSymbolAddress((void**)&oml, g_om_l);
    cudaGetSymbolAddress((void**)&th,  g_t_h);  cudaGetSymbolAddress((void**)&tl,  g_t_l);
    cudaGetSymbolAddress((void**)&h1h, g_h1_h); cudaGetSymbolAddress((void**)&h1l, g_h1_l);

    __nv_bfloat16 *wqh,*wql,*wkh,*wkl,*wvh,*wvl,*woh,*wol,*wmh,*wml,*wkmh,*wkml,*wvmh,*wvml;
    __nv_bfloat16 *w1h,*w1l,*w3h,*w3l,*w2h,*w2l;
    cudaGetSymbolAddress((void**)&wqh,  g_wq_h);  cudaGetSymbolAddress((void**)&wql,  g_wq_l);
    cudaGetSymbolAddress((void**)&wkh,  g_wk_h);  cudaGetSymbolAddress((void**)&wkl,  g_wk_l);
    cudaGetSymbolAddress((void**)&wvh,  g_wv_h);  cudaGetSymbolAddress((void**)&wvl,  g_wv_l);
    cudaGetSymbolAddress((void**)&woh,  g_wo_h);  cudaGetSymbolAddress((void**)&wol,  g_wo_l);
    cudaGetSymbolAddress((void**)&wmh,  g_wm_h);  cudaGetSymbolAddress((void**)&wml,  g_wm_l);
    cudaGetSymbolAddress((void**)&wkmh, g_wkm_h); cudaGetSymbolAddress((void**)&wkml, g_wkm_l);
    cudaGetSymbolAddress((void**)&wvmh, g_wvm_h); cudaGetSymbolAddress((void**)&wvml, g_wvm_l);
    cudaGetSymbolAddress((void**)&w1h,  g_w1_h);  cudaGetSymbolAddress((void**)&w1l,  g_w1_l);
    cudaGetSymbolAddress((void**)&w3h,  g_w3_h);  cudaGetSymbolAddress((void**)&w3l,  g_w3_l);
    cudaGetSymbolAddress((void**)&w2h,  g_w2_h);  cudaGetSymbolAddress((void**)&w2l,  g_w2_l);

    const int GSM128 = 3 * (20480 + 2 * 128 * 80);   // 122880
    const int GSM64  = 3 * (20480 + 2 * 64 * 80);    //  92160
    cudaFuncSetAttribute(gemm_a16<128>, cudaFuncAttributeMaxDynamicSharedMemorySize, GSM128);
    cudaFuncSetAttribute(gemm_a16<64>,  cudaFuncAttributeMaxDynamicSharedMemorySize, GSM64);

    const long long MD = (long long)M_ * D_;
    const long long LD = (long long)L_ * D_;

    // weight prep
    wprep_k<<<dim3(D_/32,   D_/32),   256>>>(wq,  wqh,  wql,  D_,   D_);
    wprep_k<<<dim3(D_/32,   D_/32),   256>>>(wk,  wkh,  wkl,  D_,   D_);
    wprep_k<<<dim3(D_/32,   D_/32),   256>>>(wv,  wvh,  wvl,  D_,   D_);
    wprep_k<<<dim3(D_/32,   D_/32),   256>>>(wo,  woh,  wol,  D_,   D_);
    wprep_k<<<dim3(D_/32,   D_/32),   256>>>(wm,  wmh,  wml,  D_,   D_);
    wprep_k<<<dim3(D_/32,   D_/32),   256>>>(wkm, wkmh, wkml, D_,   D_);
    wprep_k<<<dim3(D_/32,   D_/32),   256>>>(wvm, wvmh, wvml, D_,   D_);
    wprep_k<<<dim3(HID_/32, D_/32),   256>>>(w1,  w1h,  w1l,  D_,   HID_);
    wprep_k<<<dim3(HID_/32, D_/32),   256>>>(w3,  w3h,  w3l,  D_,   HID_);
    wprep_k<<<dim3(D_/32,   HID_/32), 256>>>(w2,  w2h,  w2l,  HID_, D_);

    // activation prep
    split_x_k<<<(B_*S_*D_/4 + 255) / 256, 256>>>(x, xh, xl, (long long)B_*S_*D_);
    init_om_k<<<(B_*M_*D_ + 255) / 256, 256>>>(omh, oml, om0);

    // hoisted x projections + rope
    gemm_a16<128><<<dim3(D_/128, (B_*S_)/128, 1), 256, GSM128>>>(xh, xl, wqh, wql, p_xq, D_, D_, D_, 0, 0, 0);
    gemm_a16<128><<<dim3(D_/128, (B_*S_)/128, 1), 256, GSM128>>>(xh, xl, wkh, wkl, p_xk, D_, D_, D_, 0, 0, 0);
    gemm_a16<128><<<dim3(D_/128, (B_*S_)/128, 1), 256, GSM128>>>(xh, xl, wvh, wvl, p_xv, D_, D_, D_, 0, 0, 0);
    rope_x_k<<<(B_*S_*H_*HD2_ + 255) / 256, 256>>>(p_xq, fcos, fsin);
    rope_x_k<<<(B_*S_*H_*HD2_ + 255) / 256, 256>>>(p_xk, fcos, fsin);

    for (int c = 0; c < NC_; c++) {
        // om2 = om @ wm
        gemm_a16<64><<<dim3(D_/64, 8, 1), 256, GSM64>>>(omh, oml, wmh, wml, p_om2, D_, D_, D_, 0, 0, 0);
        rmsnorm_k<<<B_*M_, 256>>>(p_om2, ffn_w, th, tl);
        // h1 = tmp@w1, h3 = tmp@w3, then silu-mul -> h1 hi/lo
        gemm_a16<64><<<dim3(HID_/64, 8, 1), 256, GSM64>>>(th, tl, w1h, w1l, p_h1, D_, D_, HID_, 0, 0, 0);
        gemm_a16<64><<<dim3(HID_/64, 8, 1), 256, GSM64>>>(th, tl, w3h, w3l, p_h3, D_, D_, HID_, 0, 0, 0);
        silu_mul_k<<<(B_*M_*HID_ + 255) / 256, 256>>>(p_h1, p_h3, h1h, h1l);
        // om2 += h1 @ w2
        gemm_a16<64><<<dim3(D_/64, 8, 1), 256, GSM64>>>(h1h, h1l, w2h, w2l, p_om2, HID_, HID_, D_, 0, 0, 1);
        rmsnorm_k<<<B_*M_, 256>>>(p_om2, mem_w, th, tl);
        // mk/mv -> k/v[:, :M]  (batched)
        gemm_a16<64><<<dim3(D_/64, 4, B_), 256, GSM64>>>(th, tl, wkmh, wkml, p_k, D_, D_, D_, MD, LD, 0);
        gemm_a16<64><<<dim3(D_/64, 4, B_), 256, GSM64>>>(th, tl, wvmh, wvml, p_v, D_, D_, D_, MD, LD, 0);
        rope_mem_k<<<(B_*M_*H_*HD2_ + 255) / 256, 256>>>(p_k, fcos, fsin);
        // fused flash attention
        const long long co = (long long)c * M_ * D_;
        flash_k<<<dim3(L_/128, B_*H_), 256>>>(p_k, p_v, p_xq + co, p_xk + co, p_xv + co, p_att);
        extract_k<<<(B_*M_*D_ + 255) / 256, 256>>>(p_att, omh, oml, xoh, xol, c);
    }
    // final: out = xo @ wo
    gemm_a16<128><<<dim3(D_/128, (B_*S_)/128, 1), 256, GSM128>>>(xoh, xol, woh, wol, out, D_, D_, D_, 0, 0, 0);
}

// round 11
// speedup vs baseline: 5.6208x; 1.0572x over previous
#include <cuda_runtime.h>
#include <cuda_bf16.h>
#include <math.h>
#include <stdint.h>

#define B_   2
#define S_   4096
#define D_   1024
#define H_   16
#define HD_  64
#define HD2_ 32
#define M_   512
#define L_   1024
#define HID_ 2816
#define NC_  8
#define EPS_ 1e-5f
#define KV_  2048      // merged kv row width
#define H13_ 5632      // merged w1|w3 output width

// ---------------- scratch (no cudaMalloc allowed) ----------------
static __device__ float g_om2 [B_*M_*D_];
static __device__ float g_h   [B_*M_*H13_];   // [h1 | h3]
static __device__ float g_kv  [B_*M_*KV_];    // [mem-K | mem-V] (K part rope'd in place)
static __device__ float g_att [B_*L_*D_];
static __device__ float g_xq  [B_*S_*D_];
static __device__ float g_xk  [B_*S_*D_];
static __device__ float g_xv  [B_*S_*D_];

// bf16 hi/lo activations (GEMM A-operands)
static __device__ __nv_bfloat16 g_x_h [B_*S_*D_],  g_x_l [B_*S_*D_];
static __device__ __nv_bfloat16 g_xo_h[B_*S_*D_],  g_xo_l[B_*S_*D_];
static __device__ __nv_bfloat16 g_om_h[B_*M_*D_],  g_om_l[B_*M_*D_];
static __device__ __nv_bfloat16 g_t_h [B_*M_*D_],  g_t_l [B_*M_*D_];
static __device__ __nv_bfloat16 g_h1_h[B_*M_*HID_], g_h1_l[B_*M_*HID_];

// bf16 hi/lo transposed weights [N, K]
static __device__ __nv_bfloat16 g_wq_h[D_*D_],  g_wq_l[D_*D_];
static __device__ __nv_bfloat16 g_wk_h[D_*D_],  g_wk_l[D_*D_];
static __device__ __nv_bfloat16 g_wv_h[D_*D_],  g_wv_l[D_*D_];
static __device__ __nv_bfloat16 g_wo_h[D_*D_],  g_wo_l[D_*D_];
static __device__ __nv_bfloat16 g_wm_h[D_*D_],  g_wm_l[D_*D_];
static __device__ __nv_bfloat16 g_wkvm_h[KV_*D_], g_wkvm_l[KV_*D_];   // [wkm | wvm]
static __device__ __nv_bfloat16 g_w13_h[H13_*D_], g_w13_l[H13_*D_];   // [w1 | w3]
static __device__ __nv_bfloat16 g_w2_h[D_*HID_],  g_w2_l[D_*HID_];

// ---------------- PTX helpers (baseline PTX only: works on plain sm_103) ----------------
__device__ __forceinline__ uint32_t smem_u32(const void* p){
    uint32_t a;
    asm("{ .reg .u64 t; cvta.to.shared.u64 t, %1; cvt.u32.u64 %0, t; }":"=r"(a):"l"(p));
    return a;
}

#define LDM4(r, addr) \
    asm volatile("ldmatrix.sync.aligned.m8n8.x4.shared.b16 {%0,%1,%2,%3}, [%4];" \
        : "=r"((r)[0]), "=r"((r)[1]), "=r"((r)[2]), "=r"((r)[3]) : "r"(addr))

#define LDM2(r, addr) \
    asm volatile("ldmatrix.sync.aligned.m8n8.x2.shared.b16 {%0,%1}, [%2];" \
        : "=r"((r)[0]), "=r"((r)[1]) : "r"(addr))

#define MMA_BF16(c, a, b) \
    asm volatile("mma.sync.aligned.m16n8k16.row.col.f32.bf16.bf16.f32 " \
        "{%0,%1,%2,%3}, {%4,%5,%6,%7}, {%8,%9}, {%0,%1,%2,%3};" \
        : "+f"((c)[0]), "+f"((c)[1]), "+f"((c)[2]), "+f"((c)[3]) \
        : "r"((a)[0]), "r"((a)[1]), "r"((a)[2]), "r"((a)[3]), \
          "r"((b)[0]), "r"((b)[1]))

#define CPA16(saddr, gptr) \
    asm volatile("cp.async.ca.shared.global [%0], [%1], 16;" \
        :: "r"(saddr), "l"(gptr))
#define CPCOMMIT() asm volatile("cp.async.commit_group;" ::: "memory")
#define CPWAIT(n)  asm volatile("cp.async.wait_group %0;" :: "n"(n) : "memory")

__device__ __forceinline__ uint32_t pack_hi(float a, float b){
    return (uint32_t)__bfloat16_as_ushort(__float2bfloat16(a))
         | ((uint32_t)__bfloat16_as_ushort(__float2bfloat16(b)) << 16);
}
__device__ __forceinline__ uint32_t pack_lo(float a, float b){
    float ah = __bfloat162float(__float2bfloat16(a));
    float bh = __bfloat162float(__float2bfloat16(b));
    return (uint32_t)__bfloat16_as_ushort(__float2bfloat16(a - ah))
         | ((uint32_t)__bfloat16_as_ushort(__float2bfloat16(b - bh)) << 16);
}
__device__ __forceinline__ void split1(float v, __nv_bfloat16* H, __nv_bfloat16* Lo){
    __nv_bfloat16 h = __float2bfloat16(v);
    *H  = h;
    *Lo = __float2bfloat16(v - __bfloat162float(h));
}

// ---------------- weight prep: W[K,N] -> Thi/Tlo[N,K] bf16 ----------------
__global__ void wprep_k(const float* __restrict__ W,
                        __nv_bfloat16* __restrict__ Thi, __nv_bfloat16* __restrict__ Tlo,
                        int K, int N)
{
    __shared__ float s[32][33];
    const int n0 = blockIdx.x * 32, k0 = blockIdx.y * 32;
    const int tx = threadIdx.x & 31, ty = threadIdx.x >> 5;
    #pragma unroll
    for (int i = 0; i < 4; i++)
        s[ty + 8*i][tx] = W[(long long)(k0 + ty + 8*i) * N + n0 + tx];
    __syncthreads();
    #pragma unroll
    for (int i = 0; i < 4; i++) {
        float x = s[tx][ty + 8*i];
        long long o = (long long)(n0 + ty + 8*i) * K + k0 + tx;
        split1(x, Thi + o, Tlo + o);
    }
}

// ---------------- async HMMA GEMM: C[M,N] (+)= A[M,K] @ Bt[N,K]^T ----------------
// A/B pre-split bf16 hi/lo. CTA 128x64, 8 warps, K-slab 32, 3-stage cp.async,
// 2 CTAs/SM (184KB smem/SM).
__global__ void __launch_bounds__(256, 2) gemm_a16(
    const __nv_bfloat16* __restrict__ Ahi, const __nv_bfloat16* __restrict__ Alo,
    const __nv_bfloat16* __restrict__ Bhi, const __nv_bfloat16* __restrict__ Blo,
    float* __restrict__ C, int K, int lda, int ldc,
    long long sA, long long sC, int acc)
{
    constexpr int ALOFF = 10240;
    constexpr int BHOFF = 20480;
    constexpr int BLOFF = 20480 + 64 * 80;
    constexpr int STG   = 20480 + 2 * 64 * 80;   // 30720

    extern __shared__ char sm[];
    const uint32_t sb = smem_u32(sm);
    const int t = threadIdx.x, lane = t & 31, wid = t >> 5;
    const int wm = (wid >> 2) * 64, wn = (wid & 3) * 16;

    Ahi += (long long)blockIdx.z * sA;
    Alo += (long long)blockIdx.z * sA;
    C   += (long long)blockIdx.z * sC;
    const int m0 = blockIdx.y * 128, n0 = blockIdx.x * 64;

    const int nk = K >> 5;

    auto issue = [&](int s, int st){
        const uint32_t stg = sb + st * STG;
        const long long ko = (long long)s * 32;
        #pragma unroll
        for (int i = 0; i < 2; i++) {
            int g = i * 256 + t, row = g >> 2, c = g & 3;
            uint32_t sa = stg + row * 80 + c * 16;
            CPA16(sa,         Ahi + (long long)(m0 + row) * lda + ko + c * 8);
            CPA16(sa + ALOFF, Alo + (long long)(m0 + row) * lda + ko + c * 8);
        }
        {
            int row = t >> 2, c = t & 3;
            if (row < 64) {
                uint32_t sa = stg + BHOFF + row * 80 + c * 16;
                CPA16(sa,                   Bhi + (long long)(n0 + row) * K + ko + c * 8);
                CPA16(sa + (BLOFF - BHOFF), Blo + (long long)(n0 + row) * K + ko + c * 8);
            }
        }
        CPCOMMIT();
    };

    float accr[4][2][4];
    #pragma unroll
    for (int i = 0; i < 4; i++)
        #pragma unroll
        for (int j = 0; j < 2; j++)
            #pragma unroll
            for (int r = 0; r < 4; r++) accr[i][j][r] = 0.f;

    issue(0, 0);
    issue(1, 1);

    for (int kb = 0; kb < nk; kb++) {
        if (kb + 1 < nk) { CPWAIT(1); } else { CPWAIT(0); }
        __syncthreads();
        if (kb + 2 < nk) issue(kb + 2, (kb + 2) % 3);

        const uint32_t stg = sb + (kb % 3) * STG;
        #pragma unroll
        for (int ks = 0; ks < 2; ks++) {
            const int k0 = ks * 16;
            uint32_t ah[4][4], al[4][4];
            const int arw = lane & 15, acl = k0 + ((lane >> 4) << 3);
            #pragma unroll
            for (int mi = 0; mi < 4; mi++) {
                uint32_t ad = stg + ((wm + mi*16 + arw) * 40 + acl) * 2;
                LDM4(ah[mi], ad);
                LDM4(al[mi], ad + ALOFF);
            }
            const int brw = lane & 7, bcl = k0 + (((lane >> 3) & 1) << 3);
            #pragma unroll
            for (int ni = 0; ni < 2; ni++) {
                uint32_t bfh[2], bfl[2];
                uint32_t bd = stg + BHOFF + ((wn + ni*8 + brw) * 40 + bcl) * 2;
                LDM2(bfh, bd);
                LDM2(bfl, bd + (BLOFF - BHOFF));
                #pragma unroll
                for (int mi = 0; mi < 4; mi++) {
                    MMA_BF16(accr[mi][ni], ah[mi], bfh);
                    MMA_BF16(accr[mi][ni], ah[mi], bfl);
                    MMA_BF16(accr[mi][ni], al[mi], bfh);
                }
            }
        }
    }

    #pragma unroll
    for (int mi = 0; mi < 4; mi++) {
        #pragma unroll
        for (int ni = 0; ni < 2; ni++) {
            long long r0 = m0 + wm + mi*16 + (lane >> 2);
            int cc = n0 + wn + ni*8 + (lane & 3) * 2;
            float* cp0 = C + r0 * ldc + cc;
            float* cp1 = cp0 + 8LL * ldc;
            if (acc) {
                float2 o0 = *(float2*)cp0, o1 = *(float2*)cp1;
                o0.x += accr[mi][ni][0]; o0.y += accr[mi][ni][1];
                o1.x += accr[mi][ni][2]; o1.y += accr[mi][ni][3];
                *(float2*)cp0 = o0; *(float2*)cp1 = o1;
            } else {
                float2 o0 = {accr[mi][ni][0], accr[mi][ni][1]};
                float2 o1 = {accr[mi][ni][2], accr[mi][ni][3]};
                *(float2*)cp0 = o0; *(float2*)cp1 = o1;
            }
        }
    }
}

// ---------------- flash attention ----------------
// mem K/V live in kv buffer: row stride KV_, batch stride M_*KV_; V = K base + 1024.
#define FLS_ 72
__global__ void __launch_bounds__(256) flash_k(
    const float* __restrict__ Kmem, const float* __restrict__ Vmem,
    const float* __restrict__ Qx, const float* __restrict__ Kx,
    const float* __restrict__ Vx, float* __restrict__ O)
{
    __shared__ __nv_bfloat16 sKh[64*FLS_], sKl[64*FLS_], sVh[64*FLS_], sVl[64*FLS_];
    const int t = threadIdx.x, lane = t & 31, w = t >> 5;
    const int bh = blockIdx.y, b = bh >> 4, h = bh & 15;
    const int i0 = blockIdx.x * 128;
    const long long SD = (long long)S_ * D_;
    const long long MB = (long long)M_ * KV_;   // mem batch stride
    const int hoff = h * HD_;

    const uint32_t kh_b = smem_u32(sKh), kl_b = smem_u32(sKl);
    const uint32_t vh_b = smem_u32(sVh), vl_b = smem_u32(sVl);

    uint32_t qh[4][4], ql[4][4];
    {
        const int r0 = i0 + w*16 + (lane >> 2);
        const float* q0 = (r0 < M_) ? (Kmem + b*MB + (long long)r0*KV_ + hoff)
                                    : (Qx + b*SD + (long long)(r0 - M_)*D_ + hoff);
        const float* q1 = ((r0+8) < M_) ? (Kmem + b*MB + (long long)(r0+8)*KV_ + hoff)
                                        : (Qx + b*SD + (long long)(r0+8 - M_)*D_ + hoff);
        const int c0 = (lane & 3) * 2;
        #pragma unroll
        for (int ks = 0; ks < 4; ks++) {
            float2 v0 = *(const float2*)(q0 + ks*16 + c0);
            float2 v1 = *(const float2*)(q1 + ks*16 + c0);
            float2 v2 = *(const float2*)(q0 + ks*16 + c0 + 8);
            float2 v3 = *(const float2*)(q1 + ks*16 + c0 + 8);
            v0.x *= 0.125f; v0.y *= 0.125f; v1.x *= 0.125f; v1.y *= 0.125f;
            v2.x *= 0.125f; v2.y *= 0.125f; v3.x *= 0.125f; v3.y *= 0.125f;
            qh[ks][0] = pack_hi(v0.x, v0.y); ql[ks][0] = pack_lo(v0.x, v0.y);
            qh[ks][1] = pack_hi(v1.x, v1.y); ql[ks][1] = pack_lo(v1.x, v1.y);
            qh[ks][2] = pack_hi(v2.x, v2.y); ql[ks][2] = pack_lo(v2.x, v2.y);
            qh[ks][3] = pack_hi(v3.x, v3.y); ql[ks][3] = pack_lo(v3.x, v3.y);
        }
    }

    float oacc[8][4];
    #pragma unroll
    for (int i = 0; i < 8; i++)
        #pragma unroll
        for (int r = 0; r < 4; r++) oacc[i][r] = 0.f;
    float m0 = -1e30f, m1 = -1e30f, l0 = 0.f, l1 = 0.f;

    const int jmax = (i0 >> 6) + 2;
    for (int jt = 0; jt < jmax; jt++) {
        const int j0 = jt * 64;
        if (jt) __syncthreads();
        #pragma unroll
        for (int i = 0; i < 4; i++) {
            int g = i * 256 + t, row = g >> 4, cq = (g & 15) * 4;
            int kr = j0 + row;
            const float* kp = (kr < M_) ? (Kmem + b*MB + (long long)kr*KV_ + hoff)
                                        : (Kx + b*SD + (long long)(kr - M_)*D_ + hoff);
            float4 kv = *(const float4*)(kp + cq);
            uint2 hw, lw;
            hw.x = pack_hi(kv.x, kv.y); hw.y = pack_hi(kv.z, kv.w);
            lw.x = pack_lo(kv.x, kv.y); lw.y = pack_lo(kv.z, kv.w);
            int eo = (row * FLS_ + cq) * 2;
            *(uint2*)((char*)sKh + eo) = hw;
            *(uint2*)((char*)sKl + eo) = lw;
            const float* vp = (kr < M_) ? (Vmem + b*MB + (long long)kr*KV_ + hoff)
                                        : (Vx + b*SD + (long long)(kr - M_)*D_ + hoff);
            float4 vv = *(const float4*)(vp + cq);
            float vsv[4] = {vv.x, vv.y, vv.z, vv.w};
            #pragma unroll
            for (int j = 0; j < 4; j++) {
                __nv_bfloat16 hb = __float2bfloat16(vsv[j]);
                __nv_bfloat16 lb = __float2bfloat16(vsv[j] - __bfloat162float(hb));
                sVh[(cq + j) * FLS_ + row] = hb;
                sVl[(cq + j) * FLS_ + row] = lb;
            }
        }
        __syncthreads();

        if (j0 > i0 + w*16 + 15) continue;

        float sc[8][4];
        #pragma unroll
        for (int i = 0; i < 8; i++)
            #pragma unroll
            for (int r = 0; r < 4; r++) sc[i][r] = 0.f;
        #pragma unroll
        for (int ks = 0; ks < 4; ks++) {
            const int bcol = ks*16 + (((lane >> 3) & 1) << 3);
            #pragma unroll
            for (int nt = 0; nt < 8; nt++) {
                uint32_t bfh[2], bfl[2];
                uint32_t off = ((nt*8 + (lane & 7)) * FLS_ + bcol) * 2;
                LDM2(bfh, kh_b + off);
                LDM2(bfl, kl_b + off);
                MMA_BF16(sc[nt], qh[ks], bfh);
                MMA_BF16(sc[nt], qh[ks], bfl);
                MMA_BF16(sc[nt], ql[ks], bfh);
            }
        }

        const int r0 = i0 + w*16 + (lane >> 2);
        float mt0 = -1e30f, mt1 = -1e30f;
        #pragma unroll
        for (int nt = 0; nt < 8; nt++) {
            int cb = j0 + nt*8 + (lane & 3) * 2;
            if (cb     > r0)     sc[nt][0] = -1e30f;
            if (cb + 1 > r0)     sc[nt][1] = -1e30f;
            if (cb     > r0 + 8) sc[nt][2] = -1e30f;
            if (cb + 1 > r0 + 8) sc[nt][3] = -1e30f;
            mt0 = fmaxf(mt0, fmaxf(sc[nt][0], sc[nt][1]));
            mt1 = fmaxf(mt1, fmaxf(sc[nt][2], sc[nt][3]));
        }
        mt0 = fmaxf(mt0, __shfl_xor_sync(~0u, mt0, 1));
        mt0 = fmaxf(mt0, __shfl_xor_sync(~0u, mt0, 2));
        mt1 = fmaxf(mt1, __shfl_xor_sync(~0u, mt1, 1));
        mt1 = fmaxf(mt1, __shfl_xor_sync(~0u, mt1, 2));
        const float mn0 = fmaxf(m0, mt0), mn1 = fmaxf(m1, mt1);
        const float al0 = __expf(m0 - mn0), al1 = __expf(m1 - mn1);
        m0 = mn0; m1 = mn1;
        float rs0 = 0.f, rs1 = 0.f;
        #pragma unroll
        for (int nt = 0; nt < 8; nt++) {
            sc[nt][0] = __expf(sc[nt][0] - mn0);
            sc[nt][1] = __expf(sc[nt][1] - mn0);
            sc[nt][2] = __expf(sc[nt][2] - mn1);
            sc[nt][3] = __expf(sc[nt][3] - mn1);
            rs0 += sc[nt][0] + sc[nt][1];
            rs1 += sc[nt][2] + sc[nt][3];
        }
        rs0 += __shfl_xor_sync(~0u, rs0, 1); rs0 += __shfl_xor_sync(~0u, rs0, 2);
        rs1 += __shfl_xor_sync(~0u, rs1, 1); rs1 += __shfl_xor_sync(~0u, rs1, 2);
        l0 = l0 * al0 + rs0;
        l1 = l1 * al1 + rs1;
        #pragma unroll
        for (int nt2 = 0; nt2 < 8; nt2++) {
            oacc[nt2][0] *= al0; oacc[nt2][1] *= al0;
            oacc[nt2][2] *= al1; oacc[nt2][3] *= al1;
        }

        uint32_t ph[4][4], pl[4][4];
        #pragma unroll
        for (int ks2 = 0; ks2 < 4; ks2++) {
            ph[ks2][0] = pack_hi(sc[2*ks2][0],   sc[2*ks2][1]);
            pl[ks2][0] = pack_lo(sc[2*ks2][0],   sc[2*ks2][1]);
            ph[ks2][1] = pack_hi(sc[2*ks2][2],   sc[2*ks2][3]);
            pl[ks2][1] = pack_lo(sc[2*ks2][2],   sc[2*ks2][3]);
            ph[ks2][2] = pack_hi(sc[2*ks2+1][0], sc[2*ks2+1][1]);
            pl[ks2][2] = pack_lo(sc[2*ks2+1][0], sc[2*ks2+1][1]);
            ph[ks2][3] = pack_hi(sc[2*ks2+1][2], sc[2*ks2+1][3]);
            pl[ks2][3] = pack_lo(sc[2*ks2+1][2], sc[2*ks2+1][3]);
        }

        #pragma unroll
        for (int ks2 = 0; ks2 < 4; ks2++) {
            const int bcol = ks2*16 + (((lane >> 3) & 1) << 3);
            #pragma unroll
            for (int nt2 = 0; nt2 < 8; nt2++) {
                uint32_t vfh[2], vfl[2];
                uint32_t off = ((nt2*8 + (lane & 7)) * FLS_ + bcol) * 2;
                LDM2(vfh, vh_b + off);
                LDM2(vfl, vl_b + off);
                MMA_BF16(oacc[nt2], ph[ks2], vfh);
                MMA_BF16(oacc[nt2], ph[ks2], vfl);
                MMA_BF16(oacc[nt2], pl[ks2], vfh);
            }
        }
    }

    const float inv0 = 1.f / l0, inv1 = 1.f / l1;
    const int r0 = i0 + w*16 + (lane >> 2);
    float* o0 = O + ((long long)b * L_ + r0) * D_ + hoff + (lane & 3) * 2;
    float* o1 = o0 + 8LL * D_;
    #pragma unroll
    for (int nt2 = 0; nt2 < 8; nt2++) {
        float2 v0 = {oacc[nt2][0] * inv0, oacc[nt2][1] * inv0};
        float2 v1 = {oacc[nt2][2] * inv1, oacc[nt2][3] * inv1};
        *(float2*)(o0 + nt2*8) = v0;
        *(float2*)(o1 + nt2*8) = v1;
    }
}

// ---------------- RMSNorm -> bf16 hi/lo ----------------
__global__ void rmsnorm_k(const float* __restrict__ X, const float* __restrict__ W,
                          __nv_bfloat16* __restrict__ Yh, __nv_bfloat16* __restrict__ Yl)
{
    const long long row = blockIdx.x;
    const float* x = X + row * D_;
    float ss = 0.f;
    for (int i = threadIdx.x; i < D_; i += 256) { float v = x[i]; ss += v * v; }
    __shared__ float red[8];
    for (int o = 16; o; o >>= 1) ss += __shfl_xor_sync(~0u, ss, o);
    if ((threadIdx.x & 31) == 0) red[threadIdx.x >> 5] = ss;
    __syncthreads();
    float tot = 0.f;
    #pragma unroll
    for (int i = 0; i < 8; i++) tot += red[i];
    const float inv = rsqrtf(tot * (1.f / D_) + EPS_);
    for (int i = threadIdx.x; i < D_; i += 256)
        split1(x[i] * inv * W[i], Yh + row * D_ + i, Yl + row * D_ + i);
}

// ---------------- elementwise ----------------
__global__ void split_x_k(const float* __restrict__ X,
                          __nv_bfloat16* __restrict__ Hh, __nv_bfloat16* __restrict__ Ll,
                          long long n)
{
    long long i = ((long long)blockIdx.x * 256 + threadIdx.x) * 4;
    if (i >= n) return;
    float4 v = *(const float4*)(X + i);
    uint2 hw, lw;
    hw.x = pack_hi(v.x, v.y); hw.y = pack_hi(v.z, v.w);
    lw.x = pack_lo(v.x, v.y); lw.y = pack_lo(v.z, v.w);
    *(uint2*)(Hh + i) = hw;
    *(uint2*)(Ll + i) = lw;
}

__global__ void init_om_k(__nv_bfloat16* __restrict__ omh, __nv_bfloat16* __restrict__ oml,
                          const float* __restrict__ om0)
{
    int i = blockIdx.x * 256 + threadIdx.x;
    if (i < B_*M_*D_) split1(om0[i % (M_*D_)], omh + i, oml + i);
}

// h = [h1 | h3] merged buffer; out hi/lo of silu(h1)*h3
__global__ void silu_mul_k(const float* __restrict__ hbuf,
                           __nv_bfloat16* __restrict__ Hh, __nv_bfloat16* __restrict__ Ll)
{
    int i = blockIdx.x * 256 + threadIdx.x;
    if (i < B_*M_*HID_) {
        int row = i / HID_, cc = i % HID_;
        float v = hbuf[(long long)row * H13_ + cc];
        float b = hbuf[(long long)row * H13_ + HID_ + cc];
        split1((v / (1.f + expf(-v))) * b, Hh + i, Ll + i);
    }
}

// rope mem-K in kv buffer: rows B*M, row stride KV_, position = row index
__global__ void rope_mem_k(float* __restrict__ t, const float* __restrict__ cf,
                           const float* __restrict__ sf)
{
    int i = blockIdx.x * 256 + threadIdx.x;
    if (i >= B_*M_*H_*HD2_) return;
    int d2 = i & 31;
    int h  = (i >> 5) & 15;
    int r  = (i >> 9) & (M_ - 1);
    int b  = i >> 18;
    long long base = ((long long)b * M_ + r) * KV_ + h * HD_ + 2 * d2;
    float c = cf[r * HD2_ + d2], s = sf[r * HD2_ + d2];
    float tr = t[base], ti = t[base + 1];
    t[base]     = tr * c - ti * s;
    t[base + 1] = tr * s + ti * c;
}

__global__ void rope_x_k(float* __restrict__ t, const float* __restrict__ cf,
                         const float* __restrict__ sf)
{
    int i = blockIdx.x * 256 + threadIdx.x;
    if (i >= B_*S_*H_*HD2_) return;
    int d2 = i & 31;
    int h  = (i >> 5) & 15;
    int r  = (i >> 9) & (S_ - 1);
    int b  = i >> 21;
    long long base = ((long long)b * S_ + r) * D_ + h * HD_ + 2 * d2;
    int pos = M_ + (r & (M_ - 1));
    float c = cf[pos * HD2_ + d2], s = sf[pos * HD2_ + d2];
    float tr = t[base], ti = t[base + 1];
    t[base]     = tr * c - ti * s;
    t[base + 1] = tr * s + ti * c;
}

__global__ void extract_k(const float* __restrict__ att,
                          __nv_bfloat16* __restrict__ omh, __nv_bfloat16* __restrict__ oml,
                          __nv_bfloat16* __restrict__ xoh, __nv_bfloat16* __restrict__ xol,
                          int c)
{
    int i = blockIdx.x * 256 + threadIdx.x;
    if (i < B_*M_*D_) {
        int b = i / (M_*D_), r = i % (M_*D_);
        float v = att[(long long)b * L_ * D_ + (long long)M_ * D_ + r];
        __nv_bfloat16 h = __float2bfloat16(v);
        __nv_bfloat16 lo = __float2bfloat16(v - __bfloat162float(h));
        omh[i] = h; oml[i] = lo;
        long long xi = (long long)b * S_ * D_ + (long long)c * M_ * D_ + r;
        xoh[xi] = h; xol[xi] = lo;
    }
}

// ---------------- host orchestration ----------------
extern "C" void kernel_launch(void* const* d_in, const int* in_sizes, int n_in,
                              void* d_out, int out_size)
{
    const float* x     = (const float*)d_in[0];
    const float* fcos  = (const float*)d_in[1];
    const float* fsin  = (const float*)d_in[2];
    const float* wq    = (const float*)d_in[3];
    const float* wk    = (const float*)d_in[4];
    const float* wv    = (const float*)d_in[5];
    const float* wo    = (const float*)d_in[6];
    const float* wm    = (const float*)d_in[7];
    const float* wkm   = (const float*)d_in[8];
    const float* wvm   = (const float*)d_in[9];
    const float* w1    = (const float*)d_in[10];
    const float* w3    = (const float*)d_in[11];
    const float* w2    = (const float*)d_in[12];
    const float* ffn_w = (const float*)d_in[13];
    const float* mem_w = (const float*)d_in[14];
    const float* om0   = (const float*)d_in[15];
    float* out = (float*)d_out;

    float *p_om2, *p_h, *p_kv, *p_att, *p_xq, *p_xk, *p_xv;
    cudaGetSymbolAddress((void**)&p_om2, g_om2);
    cudaGetSymbolAddress((void**)&p_h,   g_h);
    cudaGetSymbolAddress((void**)&p_kv,  g_kv);
    cudaGetSymbolAddress((void**)&p_att, g_att);
    cudaGetSymbolAddress((void**)&p_xq,  g_xq);
    cudaGetSymbolAddress((void**)&p_xk,  g_xk);
    cudaGetSymbolAddress((void**)&p_xv,  g_xv);

    __nv_bfloat16 *xh,*xl,*xoh,*xol,*omh,*oml,*th,*tl,*h1h,*h1l;
    cudaGetSymbolAddress((void**)&xh,  g_x_h);  cudaGetSymbolAddress((void**)&xl,  g_x_l);
    cudaGetSymbolAddress((void**)&xoh, g_xo_h); cudaGetSymbolAddress((void**)&xol, g_xo_l);
    cudaGetSymbolAddress((void**)&omh, g_om_h); cudaGetSymbolAddress((void**)&oml, g_om_l);
    cudaGetSymbolAddress((void**)&th,  g_t_h);  cudaGetSymbolAddress((void**)&tl,  g_t_l);
    cudaGetSymbolAddress((void**)&h1h, g_h1_h); cudaGetSymbolAddress((void**)&h1l, g_h1_l);

    __nv_bfloat16 *wqh,*wql,*wkh,*wkl,*wvh,*wvl,*woh,*wol,*wmh,*wml;
    __nv_bfloat16 *wkvmh,*wkvml,*w13h,*w13l,*w2h,*w2l;
    cudaGetSymbolAddress((void**)&wqh,  g_wq_h);  cudaGetSymbolAddress((void**)&wql,  g_wq_l);
    cudaGetSymbolAddress((void**)&wkh,  g_wk_h);  cudaGetSymbolAddress((void**)&wkl,  g_wk_l);
    cudaGetSymbolAddress((void**)&wvh,  g_wv_h);  cudaGetSymbolAddress((void**)&wvl,  g_wv_l);
    cudaGetSymbolAddress((void**)&woh,  g_wo_h);  cudaGetSymbolAddress((void**)&wol,  g_wo_l);
    cudaGetSymbolAddress((void**)&wmh,  g_wm_h);  cudaGetSymbolAddress((void**)&wml,  g_wm_l);
    cudaGetSymbolAddress((void**)&wkvmh, g_wkvm_h); cudaGetSymbolAddress((void**)&wkvml, g_wkvm_l);
    cudaGetSymbolAddress((void**)&w13h, g_w13_h); cudaGetSymbolAddress((void**)&w13l, g_w13_l);
    cudaGetSymbolAddress((void**)&w2h,  g_w2_h);  cudaGetSymbolAddress((void**)&w2l,  g_w2_l);

    const int GSM = 3 * (20480 + 2 * 64 * 80);   // 92160
    cudaFuncSetAttribute(gemm_a16, cudaFuncAttributeMaxDynamicSharedMemorySize, GSM);

    const long long MD = (long long)M_ * D_;
    const long long KVB = (long long)M_ * KV_;

    // weight prep (merged layouts: [wkm|wvm] -> [2048,1024]; [w1|w3] -> [5632,1024])
    wprep_k<<<dim3(D_/32,   D_/32),   256>>>(wq,  wqh,  wql,  D_,   D_);
    wprep_k<<<dim3(D_/32,   D_/32),   256>>>(wk,  wkh,  wkl,  D_,   D_);
    wprep_k<<<dim3(D_/32,   D_/32),   256>>>(wv,  wvh,  wvl,  D_,   D_);
    wprep_k<<<dim3(D_/32,   D_/32),   256>>>(wo,  woh,  wol,  D_,   D_);
    wprep_k<<<dim3(D_/32,   D_/32),   256>>>(wm,  wmh,  wml,  D_,   D_);
    wprep_k<<<dim3(D_/32,   D_/32),   256>>>(wkm, wkvmh,            wkvml,            D_, D_);
    wprep_k<<<dim3(D_/32,   D_/32),   256>>>(wvm, wkvmh + D_*D_,    wkvml + D_*D_,    D_, D_);
    wprep_k<<<dim3(HID_/32, D_/32),   256>>>(w1,  w13h,             w13l,             D_, HID_);
    wprep_k<<<dim3(HID_/32, D_/32),   256>>>(w3,  w13h + HID_*D_,   w13l + HID_*D_,   D_, HID_);
    wprep_k<<<dim3(D_/32,   HID_/32), 256>>>(w2,  w2h,  w2l,  HID_, D_);

    // activation prep
    split_x_k<<<(B_*S_*D_/4 + 255) / 256, 256>>>(x, xh, xl, (long long)B_*S_*D_);
    init_om_k<<<(B_*M_*D_ + 255) / 256, 256>>>(omh, oml, om0);

    // hoisted x projections + rope
    gemm_a16<<<dim3(D_/64, (B_*S_)/128, 1), 256, GSM>>>(xh, xl, wqh, wql, p_xq, D_, D_, D_, 0, 0, 0);
    gemm_a16<<<dim3(D_/64, (B_*S_)/128, 1), 256, GSM>>>(xh, xl, wkh, wkl, p_xk, D_, D_, D_, 0, 0, 0);
    gemm_a16<<<dim3(D_/64, (B_*S_)/128, 1), 256, GSM>>>(xh, xl, wvh, wvl, p_xv, D_, D_, D_, 0, 0, 0);
    rope_x_k<<<(B_*S_*H_*HD2_ + 255) / 256, 256>>>(p_xq, fcos, fsin);
    rope_x_k<<<(B_*S_*H_*HD2_ + 255) / 256, 256>>>(p_xk, fcos, fsin);

    for (int c = 0; c < NC_; c++) {
        // om2 = om @ wm
        gemm_a16<<<dim3(D_/64, 8, 1), 256, GSM>>>(omh, oml, wmh, wml, p_om2, D_, D_, D_, 0, 0, 0);
        rmsnorm_k<<<B_*M_, 256>>>(p_om2, ffn_w, th, tl);
        // h = tmp @ [w1|w3]  (N = 5632)
        gemm_a16<<<dim3(H13_/64, 8, 1), 256, GSM>>>(th, tl, w13h, w13l, p_h, D_, D_, H13_, 0, 0, 0);
        silu_mul_k<<<(B_*M_*HID_ + 255) / 256, 256>>>(p_h, h1h, h1l);
        // om2 += h1 @ w2
        gemm_a16<<<dim3(D_/64, 8, 1), 256, GSM>>>(h1h, h1l, w2h, w2l, p_om2, HID_, HID_, D_, 0, 0, 1);
        rmsnorm_k<<<B_*M_, 256>>>(p_om2, mem_w, th, tl);
        // kv = tmp @ [wkm|wvm]  (batched over B, N = 2048)
        gemm_a16<<<dim3(KV_/64, 4, B_), 256, GSM>>>(th, tl, wkvmh, wkvml, p_kv, D_, D_, KV_, MD, KVB, 0);
        rope_mem_k<<<(B_*M_*H_*HD2_ + 255) / 256, 256>>>(p_kv, fcos, fsin);
        // fused flash attention (mem V = kv + 1024)
        const long long co = (long long)c * M_ * D_;
        flash_k<<<dim3(L_/128, B_*H_), 256>>>(p_kv, p_kv + D_, p_xq + co, p_xk + co, p_xv + co, p_att);
        extract_k<<<(B_*M_*D_ + 255) / 256, 256>>>(p_att, omh, oml, xoh, xol, c);
    }
    // final: out = xo @ wo
    gemm_a16<<<dim3(D_/64, (B_*S_)/128, 1), 256, GSM>>>(xoh, xol, woh, wol, out, D_, D_, D_, 0, 0, 0);
}

// round 15
// speedup vs baseline: 6.2082x; 1.1045x over previous
#include <cuda_runtime.h>
#include <cuda_bf16.h>
#include <math.h>
#include <stdint.h>

#define B_   2
#define S_   4096
#define D_   1024
#define H_   16
#define HD_  64
#define HD2_ 32
#define M_   512
#define L_   1024
#define HID_ 2816
#define NC_  8
#define EPS_ 1e-5f
#define KV_  2048      // merged kv row width
#define H13_ 5632      // merged interleaved w1|w3 output width

// ---------------- scratch (no cudaMalloc allowed) ----------------
static __device__ float g_om2 [B_*M_*D_];
static __device__ float g_kv  [B_*M_*KV_];    // [mem-K | mem-V] (K part rope'd in place)
static __device__ float g_xq  [B_*S_*D_];
static __device__ float g_xk  [B_*S_*D_];
static __device__ float g_xv  [B_*S_*D_];

// bf16 hi/lo activations (GEMM A-operands)
static __device__ __nv_bfloat16 g_x_h [B_*S_*D_],  g_x_l [B_*S_*D_];
static __device__ __nv_bfloat16 g_xo_h[B_*S_*D_],  g_xo_l[B_*S_*D_];
static __device__ __nv_bfloat16 g_om_h[B_*M_*D_],  g_om_l[B_*M_*D_];
static __device__ __nv_bfloat16 g_t_h [B_*M_*D_],  g_t_l [B_*M_*D_];
static __device__ __nv_bfloat16 g_h1_h[B_*M_*HID_], g_h1_l[B_*M_*HID_];

// bf16 hi/lo transposed weights [N, K]
static __device__ __nv_bfloat16 g_wq_h[D_*D_],  g_wq_l[D_*D_];
static __device__ __nv_bfloat16 g_wk_h[D_*D_],  g_wk_l[D_*D_];
static __device__ __nv_bfloat16 g_wv_h[D_*D_],  g_wv_l[D_*D_];
static __device__ __nv_bfloat16 g_wo_h[D_*D_],  g_wo_l[D_*D_];
static __device__ __nv_bfloat16 g_wm_h[D_*D_],  g_wm_l[D_*D_];
static __device__ __nv_bfloat16 g_wkvm_h[KV_*D_], g_wkvm_l[KV_*D_];   // [wkm | wvm]
static __device__ __nv_bfloat16 g_w13_h[H13_*D_], g_w13_l[H13_*D_];   // interleaved w1/w3
static __device__ __nv_bfloat16 g_w2_h[D_*HID_],  g_w2_l[D_*HID_];

// ---------------- PTX helpers (baseline PTX only: works on plain sm_103) ----------------
__device__ __forceinline__ uint32_t smem_u32(const void* p){
    uint32_t a;
    asm("{ .reg .u64 t; cvta.to.shared.u64 t, %1; cvt.u32.u64 %0, t; }":"=r"(a):"l"(p));
    return a;
}

#define LDM4(r, addr) \
    asm volatile("ldmatrix.sync.aligned.m8n8.x4.shared.b16 {%0,%1,%2,%3}, [%4];" \
        : "=r"((r)[0]), "=r"((r)[1]), "=r"((r)[2]), "=r"((r)[3]) : "r"(addr))

#define LDM2(r, addr) \
    asm volatile("ldmatrix.sync.aligned.m8n8.x2.shared.b16 {%0,%1}, [%2];" \
        : "=r"((r)[0]), "=r"((r)[1]) : "r"(addr))

#define MMA_BF16(c, a, b) \
    asm volatile("mma.sync.aligned.m16n8k16.row.col.f32.bf16.bf16.f32 " \
        "{%0,%1,%2,%3}, {%4,%5,%6,%7}, {%8,%9}, {%0,%1,%2,%3};" \
        : "+f"((c)[0]), "+f"((c)[1]), "+f"((c)[2]), "+f"((c)[3]) \
        : "r"((a)[0]), "r"((a)[1]), "r"((a)[2]), "r"((a)[3]), \
          "r"((b)[0]), "r"((b)[1]))

#define CPA16(saddr, gptr) \
    asm volatile("cp.async.ca.shared.global [%0], [%1], 16;" \
        :: "r"(saddr), "l"(gptr))
#define CPCOMMIT() asm volatile("cp.async.commit_group;" ::: "memory")
#define CPWAIT(n)  asm volatile("cp.async.wait_group %0;" :: "n"(n) : "memory")

__device__ __forceinline__ uint32_t pack_hi(float a, float b){
    return (uint32_t)__bfloat16_as_ushort(__float2bfloat16(a))
         | ((uint32_t)__bfloat16_as_ushort(__float2bfloat16(b)) << 16);
}
__device__ __forceinline__ uint32_t pack_lo(float a, float b){
    float ah = __bfloat162float(__float2bfloat16(a));
    float bh = __bfloat162float(__float2bfloat16(b));
    return (uint32_t)__bfloat16_as_ushort(__float2bfloat16(a - ah))
         | ((uint32_t)__bfloat16_as_ushort(__float2bfloat16(b - bh)) << 16);
}
__device__ __forceinline__ void split1(float v, __nv_bfloat16* H, __nv_bfloat16* Lo){
    __nv_bfloat16 h = __float2bfloat16(v);
    *H  = h;
    *Lo = __float2bfloat16(v - __bfloat162float(h));
}

// ---------------- weight prep: W[K,N] -> Thi/Tlo[rmul*n+roff, K] bf16 ----------------
__global__ void wprep_k(const float* __restrict__ W,
                        __nv_bfloat16* __restrict__ Thi, __nv_bfloat16* __restrict__ Tlo,
                        int K, int N, int rmul, int roff)
{
    __shared__ float s[32][33];
    const int n0 = blockIdx.x * 32, k0 = blockIdx.y * 32;
    const int tx = threadIdx.x & 31, ty = threadIdx.x >> 5;
    #pragma unroll
    for (int i = 0; i < 4; i++)
        s[ty + 8*i][tx] = W[(long long)(k0 + ty + 8*i) * N + n0 + tx];
    __syncthreads();
    #pragma unroll
    for (int i = 0; i < 4; i++) {
        float x = s[tx][ty + 8*i];
        long long o = (long long)(rmul * (n0 + ty + 8*i) + roff) * K + k0 + tx;
        split1(x, Thi + o, Tlo + o);
    }
}

// ---------------- async HMMA GEMM: C[M,N] (+)= A[M,K] @ Bt[N,K]^T ----------------
// mode 0: C = ...  mode 1: C += ...  mode 2: fused SiLU-mul on interleaved pairs,
// writing bf16 hi/lo at column n/2 (Oh/Ol, row stride HID_).
__global__ void __launch_bounds__(256, 2) gemm_a16(
    const __nv_bfloat16* __restrict__ Ahi, const __nv_bfloat16* __restrict__ Alo,
    const __nv_bfloat16* __restrict__ Bhi, const __nv_bfloat16* __restrict__ Blo,
    float* __restrict__ C,
    __nv_bfloat16* __restrict__ Oh, __nv_bfloat16* __restrict__ Ol,
    int K, int lda, int ldc, long long sA, long long sC, int mode)
{
    constexpr int ALOFF = 10240;
    constexpr int BHOFF = 20480;
    constexpr int BLOFF = 20480 + 64 * 80;
    constexpr int STG   = 20480 + 2 * 64 * 80;   // 30720

    extern __shared__ char sm[];
    const uint32_t sb = smem_u32(sm);
    const int t = threadIdx.x, lane = t & 31, wid = t >> 5;
    const int wm = (wid >> 2) * 64, wn = (wid & 3) * 16;

    Ahi += (long long)blockIdx.z * sA;
    Alo += (long long)blockIdx.z * sA;
    C   += (long long)blockIdx.z * sC;
    const int m0 = blockIdx.y * 128, n0 = blockIdx.x * 64;

    const int nk = K >> 5;

    auto issue = [&](int s, int st){
        const uint32_t stg = sb + st * STG;
        const long long ko = (long long)s * 32;
        #pragma unroll
        for (int i = 0; i < 2; i++) {
            int g = i * 256 + t, row = g >> 2, c = g & 3;
            uint32_t sa = stg + row * 80 + c * 16;
            CPA16(sa,         Ahi + (long long)(m0 + row) * lda + ko + c * 8);
            CPA16(sa + ALOFF, Alo + (long long)(m0 + row) * lda + ko + c * 8);
        }
        {
            int row = t >> 2, c = t & 3;
            if (row < 64) {
                uint32_t sa = stg + BHOFF + row * 80 + c * 16;
                CPA16(sa,                   Bhi + (long long)(n0 + row) * K + ko + c * 8);
                CPA16(sa + (BLOFF - BHOFF), Blo + (long long)(n0 + row) * K + ko + c * 8);
            }
        }
        CPCOMMIT();
    };

    float accr[4][2][4];
    #pragma unroll
    for (int i = 0; i < 4; i++)
        #pragma unroll
        for (int j = 0; j < 2; j++)
            #pragma unroll
            for (int r = 0; r < 4; r++) accr[i][j][r] = 0.f;

    issue(0, 0);
    issue(1, 1);

    for (int kb = 0; kb < nk; kb++) {
        if (kb + 1 < nk) { CPWAIT(1); } else { CPWAIT(0); }
        __syncthreads();
        if (kb + 2 < nk) issue(kb + 2, (kb + 2) % 3);

        const uint32_t stg = sb + (kb % 3) * STG;
        #pragma unroll
        for (int ks = 0; ks < 2; ks++) {
            const int k0 = ks * 16;
            uint32_t ah[4][4], al[4][4];
            const int arw = lane & 15, acl = k0 + ((lane >> 4) << 3);
            #pragma unroll
            for (int mi = 0; mi < 4; mi++) {
                uint32_t ad = stg + ((wm + mi*16 + arw) * 40 + acl) * 2;
                LDM4(ah[mi], ad);
                LDM4(al[mi], ad + ALOFF);
            }
            const int brw = lane & 7, bcl = k0 + (((lane >> 3) & 1) << 3);
            #pragma unroll
            for (int ni = 0; ni < 2; ni++) {
                uint32_t bfh[2], bfl[2];
                uint32_t bd = stg + BHOFF + ((wn + ni*8 + brw) * 40 + bcl) * 2;
                LDM2(bfh, bd);
                LDM2(bfl, bd + (BLOFF - BHOFF));
                #pragma unroll
                for (int mi = 0; mi < 4; mi++) {
                    MMA_BF16(accr[mi][ni], ah[mi], bfh);
                    MMA_BF16(accr[mi][ni], ah[mi], bfl);
                    MMA_BF16(accr[mi][ni], al[mi], bfh);
                }
            }
        }
    }

    if (mode == 2) {
        // interleaved (h1, h3) pairs -> silu(h1)*h3 -> bf16 hi/lo at col n/2
        #pragma unroll
        for (int mi = 0; mi < 4; mi++) {
            #pragma unroll
            for (int ni = 0; ni < 2; ni++) {
                long long r0 = m0 + wm + mi*16 + (lane >> 2);
                int cc = n0 + wn + ni*8 + (lane & 3) * 2;
                int j = cc >> 1;
                float v1 = accr[mi][ni][0], v3 = accr[mi][ni][1];
                float o = (v1 / (1.f + expf(-v1))) * v3;
                split1(o, Oh + r0 * HID_ + j, Ol + r0 * HID_ + j);
                v1 = accr[mi][ni][2]; v3 = accr[mi][ni][3];
                o = (v1 / (1.f + expf(-v1))) * v3;
                split1(o, Oh + (r0 + 8) * HID_ + j, Ol + (r0 + 8) * HID_ + j);
            }
        }
    } else {
        const int acc = (mode == 1);
        #pragma unroll
        for (int mi = 0; mi < 4; mi++) {
            #pragma unroll
            for (int ni = 0; ni < 2; ni++) {
                long long r0 = m0 + wm + mi*16 + (lane >> 2);
                int cc = n0 + wn + ni*8 + (lane & 3) * 2;
                float* cp0 = C + r0 * ldc + cc;
                float* cp1 = cp0 + 8LL * ldc;
                if (acc) {
                    float2 o0 = *(float2*)cp0, o1 = *(float2*)cp1;
                    o0.x += accr[mi][ni][0]; o0.y += accr[mi][ni][1];
                    o1.x += accr[mi][ni][2]; o1.y += accr[mi][ni][3];
                    *(float2*)cp0 = o0; *(float2*)cp1 = o1;
                } else {
                    float2 o0 = {accr[mi][ni][0], accr[mi][ni][1]};
                    float2 o1 = {accr[mi][ni][2], accr[mi][ni][3]};
                    *(float2*)cp0 = o0; *(float2*)cp1 = o1;
                }
            }
        }
    }
}

// ---------------- flash attention: only q-rows [M, L) (rest is discarded by ref) ----
// Output written directly as bf16 hi/lo into om (next-chunk state) and xo (final GEMM A).
#define FLS_ 72
__global__ void __launch_bounds__(256) flash_k(
    const float* __restrict__ Kmem, const float* __restrict__ Vmem,
    const float* __restrict__ Qx, const float* __restrict__ Kx,
    const float* __restrict__ Vx,
    __nv_bfloat16* __restrict__ omh, __nv_bfloat16* __restrict__ oml,
    __nv_bfloat16* __restrict__ xoh, __nv_bfloat16* __restrict__ xol, int c)
{
    __shared__ __nv_bfloat16 sKh[64*FLS_], sKl[64*FLS_], sVh[64*FLS_], sVl[64*FLS_];
    const int t = threadIdx.x, lane = t & 31, w = t >> 5;
    const int bh = blockIdx.y, b = bh >> 4, h = bh & 15;
    const int i0 = M_ + blockIdx.x * 128;   // q rows >= M only
    const long long SD = (long long)S_ * D_;
    const long long MB = (long long)M_ * KV_;
    const int hoff = h * HD_;

    const uint32_t kh_b = smem_u32(sKh), kl_b = smem_u32(sKl);
    const uint32_t vh_b = smem_u32(sVh), vl_b = smem_u32(sVl);

    uint32_t qh[4][4], ql[4][4];
    {
        const int r0 = i0 + w*16 + (lane >> 2);   // >= M always
        const float* q0 = Qx + b*SD + (long long)(r0 - M_)*D_ + hoff;
        const float* q1 = Qx + b*SD + (long long)(r0 + 8 - M_)*D_ + hoff;
        const int c0 = (lane & 3) * 2;
        #pragma unroll
        for (int ks = 0; ks < 4; ks++) {
            float2 v0 = *(const float2*)(q0 + ks*16 + c0);
            float2 v1 = *(const float2*)(q1 + ks*16 + c0);
            float2 v2 = *(const float2*)(q0 + ks*16 + c0 + 8);
            float2 v3 = *(const float2*)(q1 + ks*16 + c0 + 8);
            v0.x *= 0.125f; v0.y *= 0.125f; v1.x *= 0.125f; v1.y *= 0.125f;
            v2.x *= 0.125f; v2.y *= 0.125f; v3.x *= 0.125f; v3.y *= 0.125f;
            qh[ks][0] = pack_hi(v0.x, v0.y); ql[ks][0] = pack_lo(v0.x, v0.y);
            qh[ks][1] = pack_hi(v1.x, v1.y); ql[ks][1] = pack_lo(v1.x, v1.y);
            qh[ks][2] = pack_hi(v2.x, v2.y); ql[ks][2] = pack_lo(v2.x, v2.y);
            qh[ks][3] = pack_hi(v3.x, v3.y); ql[ks][3] = pack_lo(v3.x, v3.y);
        }
    }

    float oacc[8][4];
    #pragma unroll
    for (int i = 0; i < 8; i++)
        #pragma unroll
        for (int r = 0; r < 4; r++) oacc[i][r] = 0.f;
    float m0 = -1e30f, m1 = -1e30f, l0 = 0.f, l1 = 0.f;

    const int jmax = (i0 >> 6) + 2;
    for (int jt = 0; jt < jmax; jt++) {
        const int j0 = jt * 64;
        if (jt) __syncthreads();
        #pragma unroll
        for (int i = 0; i < 4; i++) {
            int g = i * 256 + t, row = g >> 4, cq = (g & 15) * 4;
            int kr = j0 + row;
            const float* kp = (kr < M_) ? (Kmem + b*MB + (long long)kr*KV_ + hoff)
                                        : (Kx + b*SD + (long long)(kr - M_)*D_ + hoff);
            float4 kv = *(const float4*)(kp + cq);
            uint2 hw, lw;
            hw.x = pack_hi(kv.x, kv.y); hw.y = pack_hi(kv.z, kv.w);
            lw.x = pack_lo(kv.x, kv.y); lw.y = pack_lo(kv.z, kv.w);
            int eo = (row * FLS_ + cq) * 2;
            *(uint2*)((char*)sKh + eo) = hw;
            *(uint2*)((char*)sKl + eo) = lw;
            const float* vp = (kr < M_) ? (Vmem + b*MB + (long long)kr*KV_ + hoff)
                                        : (Vx + b*SD + (long long)(kr - M_)*D_ + hoff);
            float4 vv = *(const float4*)(vp + cq);
            float vsv[4] = {vv.x, vv.y, vv.z, vv.w};
            #pragma unroll
            for (int j = 0; j < 4; j++) {
                __nv_bfloat16 hb = __float2bfloat16(vsv[j]);
                __nv_bfloat16 lb = __float2bfloat16(vsv[j] - __bfloat162float(hb));
                sVh[(cq + j) * FLS_ + row] = hb;
                sVl[(cq + j) * FLS_ + row] = lb;
            }
        }
        __syncthreads();

        if (j0 > i0 + w*16 + 15) continue;

        float sc[8][4];
        #pragma unroll
        for (int i = 0; i < 8; i++)
            #pragma unroll
            for (int r = 0; r < 4; r++) sc[i][r] = 0.f;
        #pragma unroll
        for (int ks = 0; ks < 4; ks++) {
            const int bcol = ks*16 + (((lane >> 3) & 1) << 3);
            #pragma unroll
            for (int nt = 0; nt < 8; nt++) {
                uint32_t bfh[2], bfl[2];
                uint32_t off = ((nt*8 + (lane & 7)) * FLS_ + bcol) * 2;
                LDM2(bfh, kh_b + off);
                LDM2(bfl, kl_b + off);
                MMA_BF16(sc[nt], qh[ks], bfh);
                MMA_BF16(sc[nt], qh[ks], bfl);
                MMA_BF16(sc[nt], ql[ks], bfh);
            }
        }

        const int r0 = i0 + w*16 + (lane >> 2);
        float mt0 = -1e30f, mt1 = -1e30f;
        #pragma unroll
        for (int nt = 0; nt < 8; nt++) {
            int cb = j0 + nt*8 + (lane & 3) * 2;
            if (cb     > r0)     sc[nt][0] = -1e30f;
            if (cb + 1 > r0)     sc[nt][1] = -1e30f;
            if (cb     > r0 + 8) sc[nt][2] = -1e30f;
            if (cb + 1 > r0 + 8) sc[nt][3] = -1e30f;
            mt0 = fmaxf(mt0, fmaxf(sc[nt][0], sc[nt][1]));
            mt1 = fmaxf(mt1, fmaxf(sc[nt][2], sc[nt][3]));
        }
        mt0 = fmaxf(mt0, __shfl_xor_sync(~0u, mt0, 1));
        mt0 = fmaxf(mt0, __shfl_xor_sync(~0u, mt0, 2));
        mt1 = fmaxf(mt1, __shfl_xor_sync(~0u, mt1, 1));
        mt1 = fmaxf(mt1, __shfl_xor_sync(~0u, mt1, 2));
        const float mn0 = fmaxf(m0, mt0), mn1 = fmaxf(m1, mt1);
        const float al0 = __expf(m0 - mn0), al1 = __expf(m1 - mn1);
        m0 = mn0; m1 = mn1;
        float rs0 = 0.f, rs1 = 0.f;
        #pragma unroll
        for (int nt = 0; nt < 8; nt++) {
            sc[nt][0] = __expf(sc[nt][0] - mn0);
            sc[nt][1] = __expf(sc[nt][1] - mn0);
            sc[nt][2] = __expf(sc[nt][2] - mn1);
            sc[nt][3] = __expf(sc[nt][3] - mn1);
            rs0 += sc[nt][0] + sc[nt][1];
            rs1 += sc[nt][2] + sc[nt][3];
        }
        rs0 += __shfl_xor_sync(~0u, rs0, 1); rs0 += __shfl_xor_sync(~0u, rs0, 2);
        rs1 += __shfl_xor_sync(~0u, rs1, 1); rs1 += __shfl_xor_sync(~0u, rs1, 2);
        l0 = l0 * al0 + rs0;
        l1 = l1 * al1 + rs1;
        #pragma unroll
        for (int nt2 = 0; nt2 < 8; nt2++) {
            oacc[nt2][0] *= al0; oacc[nt2][1] *= al0;
            oacc[nt2][2] *= al1; oacc[nt2][3] *= al1;
        }

        uint32_t ph[4][4], pl[4][4];
        #pragma unroll
        for (int ks2 = 0; ks2 < 4; ks2++) {
            ph[ks2][0] = pack_hi(sc[2*ks2][0],   sc[2*ks2][1]);
            pl[ks2][0] = pack_lo(sc[2*ks2][0],   sc[2*ks2][1]);
            ph[ks2][1] = pack_hi(sc[2*ks2][2],   sc[2*ks2][3]);
            pl[ks2][1] = pack_lo(sc[2*ks2][2],   sc[2*ks2][3]);
            ph[ks2][2] = pack_hi(sc[2*ks2+1][0], sc[2*ks2+1][1]);
            pl[ks2][2] = pack_lo(sc[2*ks2+1][0], sc[2*ks2+1][1]);
            ph[ks2][3] = pack_hi(sc[2*ks2+1][2], sc[2*ks2+1][3]);
            pl[ks2][3] = pack_lo(sc[2*ks2+1][2], sc[2*ks2+1][3]);
        }

        #pragma unroll
        for (int ks2 = 0; ks2 < 4; ks2++) {
            const int bcol = ks2*16 + (((lane >> 3) & 1) << 3);
            #pragma unroll
            for (int nt2 = 0; nt2 < 8; nt2++) {
                uint32_t vfh[2], vfl[2];
                uint32_t off = ((nt2*8 + (lane & 7)) * FLS_ + bcol) * 2;
                LDM2(vfh, vh_b + off);
                LDM2(vfl, vl_b + off);
                MMA_BF16(oacc[nt2], ph[ks2], vfh);
                MMA_BF16(oacc[nt2], ph[ks2], vfl);
                MMA_BF16(oacc[nt2], pl[ks2], vfh);
            }
        }
    }

    // epilogue: normalize, split hi/lo, write om + xo directly
    const float inv0 = 1.f / l0, inv1 = 1.f / l1;
    const int r0 = i0 + w*16 + (lane >> 2);
    const int rr0 = r0 - M_;
    const long long om0 = ((long long)b * M_ + rr0) * D_ + hoff;
    const long long om1 = om0 + 8LL * D_;
    const long long xo0 = ((long long)b * S_ + (long long)c * M_ + rr0) * D_ + hoff;
    const long long xo1 = xo0 + 8LL * D_;
    #pragma unroll
    for (int nt2 = 0; nt2 < 8; nt2++) {
        const int col = nt2*8 + (lane & 3) * 2;
        float a0 = oacc[nt2][0] * inv0, a1 = oacc[nt2][1] * inv0;
        float b0 = oacc[nt2][2] * inv1, b1 = oacc[nt2][3] * inv1;
        uint32_t h0 = pack_hi(a0, a1), lo0 = pack_lo(a0, a1);
        uint32_t h1 = pack_hi(b0, b1), lo1 = pack_lo(b0, b1);
        *(uint32_t*)(omh + om0 + col) = h0;  *(uint32_t*)(oml + om0 + col) = lo0;
        *(uint32_t*)(omh + om1 + col) = h1;  *(uint32_t*)(oml + om1 + col) = lo1;
        *(uint32_t*)(xoh + xo0 + col) = h0;  *(uint32_t*)(xol + xo0 + col) = lo0;
        *(uint32_t*)(xoh + xo1 + col) = h1;  *(uint32_t*)(xol + xo1 + col) = lo1;
    }
}

// ---------------- RMSNorm -> bf16 hi/lo ----------------
__global__ void rmsnorm_k(const float* __restrict__ X, const float* __restrict__ W,
                          __nv_bfloat16* __restrict__ Yh, __nv_bfloat16* __restrict__ Yl)
{
    const long long row = blockIdx.x;
    const float* x = X + row * D_;
    float ss = 0.f;
    for (int i = threadIdx.x; i < D_; i += 256) { float v = x[i]; ss += v * v; }
    __shared__ float red[8];
    for (int o = 16; o; o >>= 1) ss += __shfl_xor_sync(~0u, ss, o);
    if ((threadIdx.x & 31) == 0) red[threadIdx.x >> 5] = ss;
    __syncthreads();
    float tot = 0.f;
    #pragma unroll
    for (int i = 0; i < 8; i++) tot += red[i];
    const float inv = rsqrtf(tot * (1.f / D_) + EPS_);
    for (int i = threadIdx.x; i < D_; i += 256)
        split1(x[i] * inv * W[i], Yh + row * D_ + i, Yl + row * D_ + i);
}

// ---------------- elementwise ----------------
__global__ void split_x_k(const float* __restrict__ X,
                          __nv_bfloat16* __restrict__ Hh, __nv_bfloat16* __restrict__ Ll,
                          long long n)
{
    long long i = ((long long)blockIdx.x * 256 + threadIdx.x) * 4;
    if (i >= n) return;
    float4 v = *(const float4*)(X + i);
    uint2 hw, lw;
    hw.x = pack_hi(v.x, v.y); hw.y = pack_hi(v.z, v.w);
    lw.x = pack_lo(v.x, v.y); lw.y = pack_lo(v.z, v.w);
    *(uint2*)(Hh + i) = hw;
    *(uint2*)(Ll + i) = lw;
}

__global__ void init_om_k(__nv_bfloat16* __restrict__ omh, __nv_bfloat16* __restrict__ oml,
                          const float* __restrict__ om0)
{
    int i = blockIdx.x * 256 + threadIdx.x;
    if (i < B_*M_*D_) split1(om0[i % (M_*D_)], omh + i, oml + i);
}

// rope mem-K in kv buffer: rows B*M, row stride KV_, position = row index
__global__ void rope_mem_k(float* __restrict__ t, const float* __restrict__ cf,
                           const float* __restrict__ sf)
{
    int i = blockIdx.x * 256 + threadIdx.x;
    if (i >= B_*M_*H_*HD2_) return;
    int d2 = i & 31;
    int h  = (i >> 5) & 15;
    int r  = (i >> 9) & (M_ - 1);
    int b  = i >> 18;
    long long base = ((long long)b * M_ + r) * KV_ + h * HD_ + 2 * d2;
    float c = cf[r * HD2_ + d2], s = sf[r * HD2_ + d2];
    float tr = t[base], ti = t[base + 1];
    t[base]     = tr * c - ti * s;
    t[base + 1] = tr * s + ti * c;
}

__global__ void rope_x_k(float* __restrict__ t, const float* __restrict__ cf,
                         const float* __restrict__ sf)
{
    int i = blockIdx.x * 256 + threadIdx.x;
    if (i >= B_*S_*H_*HD2_) return;
    int d2 = i & 31;
    int h  = (i >> 5) & 15;
    int r  = (i >> 9) & (S_ - 1);
    int b  = i >> 21;
    long long base = ((long long)b * S_ + r) * D_ + h * HD_ + 2 * d2;
    int pos = M_ + (r & (M_ - 1));
    float c = cf[pos * HD2_ + d2], s = sf[pos * HD2_ + d2];
    float tr = t[base], ti = t[base + 1];
    t[base]     = tr * c - ti * s;
    t[base + 1] = tr * s + ti * c;
}

// ---------------- host orchestration ----------------
extern "C" void kernel_launch(void* const* d_in, const int* in_sizes, int n_in,
                              void* d_out, int out_size)
{
    const float* x     = (const float*)d_in[0];
    const float* fcos  = (const float*)d_in[1];
    const float* fsin  = (const float*)d_in[2];
    const float* wq    = (const float*)d_in[3];
    const float* wk    = (const float*)d_in[4];
    const float* wv    = (const float*)d_in[5];
    const float* wo    = (const float*)d_in[6];
    const float* wm    = (const float*)d_in[7];
    const float* wkm   = (const float*)d_in[8];
    const float* wvm   = (const float*)d_in[9];
    const float* w1    = (const float*)d_in[10];
    const float* w3    = (const float*)d_in[11];
    const float* w2    = (const float*)d_in[12];
    const float* ffn_w = (const float*)d_in[13];
    const float* mem_w = (const float*)d_in[14];
    const float* om0   = (const float*)d_in[15];
    float* out = (float*)d_out;

    float *p_om2, *p_kv, *p_xq, *p_xk, *p_xv;
    cudaGetSymbolAddress((void**)&p_om2, g_om2);
    cudaGetSymbolAddress((void**)&p_kv,  g_kv);
    cudaGetSymbolAddress((void**)&p_xq,  g_xq);
    cudaGetSymbolAddress((void**)&p_xk,  g_xk);
    cudaGetSymbolAddress((void**)&p_xv,  g_xv);

    __nv_bfloat16 *xh,*xl,*xoh,*xol,*omh,*oml,*th,*tl,*h1h,*h1l;
    cudaGetSymbolAddress((void**)&xh,  g_x_h);  cudaGetSymbolAddress((void**)&xl,  g_x_l);
    cudaGetSymbolAddress((void**)&xoh, g_xo_h); cudaGetSymbolAddress((void**)&xol, g_xo_l);
    cudaGetSymbolAddress((void**)&omh, g_om_h); cudaGetSymbolAddress((void**)&oml, g_om_l);
    cudaGetSymbolAddress((void**)&th,  g_t_h);  cudaGetSymbolAddress((void**)&tl,  g_t_l);
    cudaGetSymbolAddress((void**)&h1h, g_h1_h); cudaGetSymbolAddress((void**)&h1l, g_h1_l);

    __nv_bfloat16 *wqh,*wql,*wkh,*wkl,*wvh,*wvl,*woh,*wol,*wmh,*wml;
    __nv_bfloat16 *wkvmh,*wkvml,*w13h,*w13l,*w2h,*w2l;
    cudaGetSymbolAddress((void**)&wqh,  g_wq_h);  cudaGetSymbolAddress((void**)&wql,  g_wq_l);
    cudaGetSymbolAddress((void**)&wkh,  g_wk_h);  cudaGetSymbolAddress((void**)&wkl,  g_wk_l);
    cudaGetSymbolAddress((void**)&wvh,  g_wv_h);  cudaGetSymbolAddress((void**)&wvl,  g_wv_l);
    cudaGetSymbolAddress((void**)&woh,  g_wo_h);  cudaGetSymbolAddress((void**)&wol,  g_wo_l);
    cudaGetSymbolAddress((void**)&wmh,  g_wm_h);  cudaGetSymbolAddress((void**)&wml,  g_wm_l);
    cudaGetSymbolAddress((void**)&wkvmh, g_wkvm_h); cudaGetSymbolAddress((void**)&wkvml, g_wkvm_l);
    cudaGetSymbolAddress((void**)&w13h, g_w13_h); cudaGetSymbolAddress((void**)&w13l, g_w13_l);
    cudaGetSymbolAddress((void**)&w2h,  g_w2_h);  cudaGetSymbolAddress((void**)&w2l,  g_w2_l);

    const int GSM = 3 * (20480 + 2 * 64 * 80);   // 92160
    cudaFuncSetAttribute(gemm_a16, cudaFuncAttributeMaxDynamicSharedMemorySize, GSM);

    const long long MD = (long long)M_ * D_;
    const long long KVB = (long long)M_ * KV_;

    // weight prep (merged: [wkm|wvm] rows 0..2047; w1/w3 interleaved even/odd rows)
    wprep_k<<<dim3(D_/32,   D_/32),   256>>>(wq,  wqh,  wql,  D_,   D_,   1, 0);
    wprep_k<<<dim3(D_/32,   D_/32),   256>>>(wk,  wkh,  wkl,  D_,   D_,   1, 0);
    wprep_k<<<dim3(D_/32,   D_/32),   256>>>(wv,  wvh,  wvl,  D_,   D_,   1, 0);
    wprep_k<<<dim3(D_/32,   D_/32),   256>>>(wo,  woh,  wol,  D_,   D_,   1, 0);
    wprep_k<<<dim3(D_/32,   D_/32),   256>>>(wm,  wmh,  wml,  D_,   D_,   1, 0);
    wprep_k<<<dim3(D_/32,   D_/32),   256>>>(wkm, wkvmh,         wkvml,         D_, D_, 1, 0);
    wprep_k<<<dim3(D_/32,   D_/32),   256>>>(wvm, wkvmh + D_*D_, wkvml + D_*D_, D_, D_, 1, 0);
    wprep_k<<<dim3(HID_/32, D_/32),   256>>>(w1,  w13h, w13l, D_,   HID_, 2, 0);
    wprep_k<<<dim3(HID_/32, D_/32),   256>>>(w3,  w13h, w13l, D_,   HID_, 2, 1);
    wprep_k<<<dim3(D_/32,   HID_/32), 256>>>(w2,  w2h,  w2l,  HID_, D_,   1, 0);

    // activation prep
    split_x_k<<<(B_*S_*D_/4 + 255) / 256, 256>>>(x, xh, xl, (long long)B_*S_*D_);
    init_om_k<<<(B_*M_*D_ + 255) / 256, 256>>>(omh, oml, om0);

    // hoisted x projections + rope
    gemm_a16<<<dim3(D_/64, (B_*S_)/128, 1), 256, GSM>>>(xh, xl, wqh, wql, p_xq, 0, 0, D_, D_, D_, 0, 0, 0);
    gemm_a16<<<dim3(D_/64, (B_*S_)/128, 1), 256, GSM>>>(xh, xl, wkh, wkl, p_xk, 0, 0, D_, D_, D_, 0, 0, 0);
    gemm_a16<<<dim3(D_/64, (B_*S_)/128, 1), 256, GSM>>>(xh, xl, wvh, wvl, p_xv, 0, 0, D_, D_, D_, 0, 0, 0);
    rope_x_k<<<(B_*S_*H_*HD2_ + 255) / 256, 256>>>(p_xq, fcos, fsin);
    rope_x_k<<<(B_*S_*H_*HD2_ + 255) / 256, 256>>>(p_xk, fcos, fsin);

    for (int c = 0; c < NC_; c++) {
        // om2 = om @ wm
        gemm_a16<<<dim3(D_/64, 8, 1), 256, GSM>>>(omh, oml, wmh, wml, p_om2, 0, 0, D_, D_, D_, 0, 0, 0);
        rmsnorm_k<<<B_*M_, 256>>>(p_om2, ffn_w, th, tl);
        // h1 = silu(tmp@w1) * (tmp@w3)  -- fused, interleaved w13, bf16 hi/lo out
        gemm_a16<<<dim3(H13_/64, 8, 1), 256, GSM>>>(th, tl, w13h, w13l, p_om2 /*unused*/, h1h, h1l, D_, D_, 0, 0, 0, 2);
        // om2 += h1 @ w2
        gemm_a16<<<dim3(D_/64, 8, 1), 256, GSM>>>(h1h, h1l, w2h, w2l, p_om2, 0, 0, HID_, HID_, D_, 0, 0, 1);
        rmsnorm_k<<<B_*M_, 256>>>(p_om2, mem_w, th, tl);
        // kv = tmp @ [wkm|wvm]  (batched over B)
        gemm_a16<<<dim3(KV_/64, 4, B_), 256, GSM>>>(th, tl, wkvmh, wkvml, p_kv, 0, 0, D_, D_, KV_, MD, KVB, 0);
        rope_mem_k<<<(B_*M_*H_*HD2_ + 255) / 256, 256>>>(p_kv, fcos, fsin);
        // fused flash attention on q-rows [M,L) only; writes om/xo hi/lo directly
        const long long co = (long long)c * M_ * D_;
        flash_k<<<dim3((L_-M_)/128, B_*H_), 256>>>(p_kv, p_kv + D_, p_xq + co, p_xk + co, p_xv + co,
                                                   omh, oml, xoh, xol, c);
    }
    // final: out = xo @ wo
    gemm_a16<<<dim3(D_/64, (B_*S_)/128, 1), 256, GSM>>>(xoh, xol, woh, wol, out, 0, 0, D_, D_, D_, 0, 0, 0);
}